// round 1
// baseline (speedup 1.0000x reference)
#include <cuda_runtime.h>
#include <cuda_bf16.h>
#include <math.h>

#define V_  10000
#define C_  8192
#define NC_ 64
#define SPW_ 128
#define H_  256
#define B_  16
#define T_  33
#define MAXW_ 1024

// ---------------- scratch (device globals; no allocation allowed) ----------------
__device__ __align__(16) float g_tmp[C_ * H_];
__device__ __align__(16) float g_r_start[C_ * H_];
__device__ __align__(16) float g_r_state[C_ * H_];
__device__ __align__(16) float g_r_pre[C_ * H_];
__device__ __align__(16) float g_trans[(size_t)C_ * C_];   // 256 MB trans_logits
__device__ float g_row_lse[C_];
__device__ float g_start_s[C_];
__device__ float g_start_lse_v;
__device__ float g_else[C_];
__device__ float g_obs[B_ * T_ * SPW_];
__device__ int   g_cl_words[NC_ * MAXW_];
__device__ int   g_cl_cnt[NC_];

// ---------------- generic NT SGEMM: C[m,n] = act(A[m,:]·B[n,:] + bias[n]) + res[m,n] ----
// A: M x K row-major, B: N x K row-major. M,N multiples of 128, K multiple of 16.
template <int ACT>   // 0 = none, 1 = relu
__global__ void gemm_nt(const float* __restrict__ A, const float* __restrict__ Bm,
                        const float* __restrict__ bias, const float* __restrict__ res,
                        float* __restrict__ Cm, int M, int N, int K) {
    const int BM = 128, BN = 128, BK = 16;
    __shared__ float As[BK][BM];
    __shared__ float Bs[BK][BN];

    int t  = threadIdx.x;          // 0..255
    int m0 = blockIdx.y * BM;
    int n0 = blockIdx.x * BN;
    int tx = t & 15, ty = t >> 4;

    float acc[8][8];
#pragma unroll
    for (int a = 0; a < 8; a++)
#pragma unroll
        for (int b = 0; b < 8; b++) acc[a][b] = 0.f;

    for (int k0 = 0; k0 < K; k0 += BK) {
#pragma unroll
        for (int r = 0; r < 2; r++) {
            int idx  = r * 256 + t;         // 0..511
            int row  = idx >> 2;            // 0..127
            int quad = idx & 3;             // 0..3
            float4 va = *reinterpret_cast<const float4*>(A + (size_t)(m0 + row) * K + k0 + quad * 4);
            As[quad * 4 + 0][row] = va.x;
            As[quad * 4 + 1][row] = va.y;
            As[quad * 4 + 2][row] = va.z;
            As[quad * 4 + 3][row] = va.w;
            float4 vb = *reinterpret_cast<const float4*>(Bm + (size_t)(n0 + row) * K + k0 + quad * 4);
            Bs[quad * 4 + 0][row] = vb.x;
            Bs[quad * 4 + 1][row] = vb.y;
            Bs[quad * 4 + 2][row] = vb.z;
            Bs[quad * 4 + 3][row] = vb.w;
        }
        __syncthreads();
#pragma unroll
        for (int k = 0; k < BK; k++) {
            float ra[8], rb[8];
            *reinterpret_cast<float4*>(ra)     = *reinterpret_cast<float4*>(&As[k][ty * 8]);
            *reinterpret_cast<float4*>(ra + 4) = *reinterpret_cast<float4*>(&As[k][ty * 8 + 4]);
            *reinterpret_cast<float4*>(rb)     = *reinterpret_cast<float4*>(&Bs[k][tx * 8]);
            *reinterpret_cast<float4*>(rb + 4) = *reinterpret_cast<float4*>(&Bs[k][tx * 8 + 4]);
#pragma unroll
            for (int a = 0; a < 8; a++)
#pragma unroll
                for (int b = 0; b < 8; b++) acc[a][b] = fmaf(ra[a], rb[b], acc[a][b]);
        }
        __syncthreads();
    }

#pragma unroll
    for (int a = 0; a < 8; a++) {
        int m = m0 + ty * 8 + a;
#pragma unroll
        for (int b = 0; b < 8; b++) {
            int n = n0 + tx * 8 + b;
            float v = acc[a][b];
            if (bias) v += bias[n];
            if (ACT == 1) v = fmaxf(v, 0.f);
            if (res) v += res[(size_t)m * N + n];
            Cm[(size_t)m * N + n] = v;
        }
    }
}

// ---------------- start head: s[c] = r_start[c]·sow + sob --------------------------
__global__ void start_head(const float* __restrict__ sow, const float* __restrict__ sob) {
    int gw   = (blockIdx.x * blockDim.x + threadIdx.x) >> 5;  // one warp per row
    int lane = threadIdx.x & 31;
    if (gw >= C_) return;
    float acc = 0.f;
#pragma unroll
    for (int q = 0; q < 8; q++)
        acc += g_r_start[(size_t)gw * H_ + lane + 32 * q] * sow[lane + 32 * q];
#pragma unroll
    for (int o = 16; o > 0; o >>= 1) acc += __shfl_xor_sync(0xffffffffu, acc, o);
    if (lane == 0) g_start_s[gw] = acc + sob[0];
}

// ---------------- single-block LSE over g_start_s -----------------------------------
__global__ void start_lse_kernel() {
    int tid = threadIdx.x;
    float m = -INFINITY, s = 0.f;
    for (int c = tid; c < C_; c += 256) {
        float x  = g_start_s[c];
        float nm = fmaxf(m, x);
        s = s * __expf(m - nm) + __expf(x - nm);
        m = nm;
    }
    __shared__ float sm[256], ss[256];
    sm[tid] = m; ss[tid] = s;
    __syncthreads();
    for (int o = 128; o > 0; o >>= 1) {
        if (tid < o) {
            float m2 = sm[tid + o], s2 = ss[tid + o];
            float nm = fmaxf(sm[tid], m2);
            ss[tid] = ss[tid] * __expf(sm[tid] - nm) + s2 * __expf(m2 - nm);
            sm[tid] = nm;
        }
        __syncthreads();
    }
    if (tid == 0) g_start_lse_v = sm[0] + logf(ss[0]);
}

// ---------------- per-row LSE over g_trans ------------------------------------------
__global__ void row_lse_kernel() {
    int row = blockIdx.x;
    int tid = threadIdx.x;
    const float* p = g_trans + (size_t)row * C_;
    float m = -INFINITY, s = 0.f;
    for (int j = tid; j < C_; j += 256) {
        float x  = p[j];
        float nm = fmaxf(m, x);
        s = s * __expf(m - nm) + __expf(x - nm);
        m = nm;
    }
    __shared__ float sm[256], ss[256];
    sm[tid] = m; ss[tid] = s;
    __syncthreads();
    for (int o = 128; o > 0; o >>= 1) {
        if (tid < o) {
            float m2 = sm[tid + o], s2 = ss[tid + o];
            float nm = fmaxf(sm[tid], m2);
            ss[tid] = ss[tid] * __expf(sm[tid] - nm) + s2 * __expf(m2 - nm);
            sm[tid] = nm;
        }
        __syncthreads();
    }
    if (tid == 0) g_row_lse[row] = sm[0] + logf(ss[0]);
}

// ---------------- cluster membership lists ------------------------------------------
__global__ void zero_counts() {
    if (threadIdx.x < NC_) g_cl_cnt[threadIdx.x] = 0;
}
__global__ void build_lists(const int* __restrict__ word2state) {
    int w = blockIdx.x * blockDim.x + threadIdx.x;
    if (w >= V_) return;
    int k   = word2state[(size_t)w * SPW_] >> 7;   // cluster id
    int pos = atomicAdd(&g_cl_cnt[k], 1);
    if (pos < MAXW_) g_cl_words[k * MAXW_ + pos] = w;
}

// ---------------- emission denominator: LSE over words of row's cluster --------------
__global__ void emis_lse_kernel(const float* __restrict__ proj_w, const float* __restrict__ proj_b) {
    int c   = blockIdx.x;
    int tid = threadIdx.x;
    __shared__ float xr[H_];
    xr[tid] = g_r_pre[(size_t)c * H_ + tid];
    __syncthreads();
    int k    = c >> 7;
    int cnt  = g_cl_cnt[k];
    const int* words = &g_cl_words[k * MAXW_];
    int lane = tid & 31, wrp = tid >> 5;

    float m = -INFINITY, s = 0.f;
    for (int idx = wrp; idx < cnt; idx += 8) {
        int v = words[idx];
        float acc = 0.f;
#pragma unroll
        for (int q = 0; q < 8; q++)
            acc += xr[lane + 32 * q] * proj_w[(size_t)v * H_ + lane + 32 * q];
#pragma unroll
        for (int o = 16; o > 0; o >>= 1) acc += __shfl_xor_sync(0xffffffffu, acc, o);
        float x  = acc + proj_b[v];
        float nm = fmaxf(m, x);
        s = s * __expf(m - nm) + __expf(x - nm);
        m = nm;
    }
    __shared__ float sm[8], ss[8];
    if (lane == 0) { sm[wrp] = m; ss[wrp] = s; }
    __syncthreads();
    if (tid == 0) {
        float M = -INFINITY, S = 0.f;
        for (int i = 0; i < 8; i++) {
            if (sm[i] == -INFINITY) continue;
            float nm = fmaxf(M, sm[i]);
            S = S * __expf(M - nm) + ss[i] * __expf(sm[i] - nm);
            M = nm;
        }
        g_else[c] = M + logf(S);
    }
}

// ---------------- obs[b,t,s] = r_pre[cb+s]·proj_w[v] + proj_b[v] - else[cb+s] --------
__global__ void obs_kernel(const int* __restrict__ text, const int* __restrict__ word2state,
                           const float* __restrict__ proj_w, const float* __restrict__ proj_b) {
    int bt  = blockIdx.x;
    int tid = threadIdx.x;
    int v     = text[bt];
    int cbase = word2state[(size_t)v * SPW_];
    __shared__ float pw[H_];
    pw[tid] = proj_w[(size_t)v * H_ + tid];
    __syncthreads();
    int lane = tid & 31, wrp = tid >> 5;
    float pb = proj_b[v];
    for (int s = wrp; s < SPW_; s += 8) {
        int c = cbase + s;
        float acc = 0.f;
#pragma unroll
        for (int q = 0; q < 8; q++)
            acc += pw[lane + 32 * q] * g_r_pre[(size_t)c * H_ + lane + 32 * q];
#pragma unroll
        for (int o = 16; o > 0; o >>= 1) acc += __shfl_xor_sync(0xffffffffu, acc, o);
        if (lane == 0) g_obs[bt * SPW_ + s] = acc + pb - g_else[c];
    }
}

// ---------------- forward recursion (one block per batch element) --------------------
__device__ __forceinline__ float block_max128(float v, float* red) {
    int j = threadIdx.x;
    red[j] = v;
    __syncthreads();
#pragma unroll
    for (int o = 64; o > 0; o >>= 1) {
        if (j < o) red[j] = fmaxf(red[j], red[j + o]);
        __syncthreads();
    }
    float r = red[0];
    __syncthreads();
    return r;
}

__global__ void forward_kernel(const int* __restrict__ text, const int* __restrict__ word2state,
                               float* __restrict__ out) {
    int b = blockIdx.x;
    int j = threadIdx.x;       // 0..127
    __shared__ float add[SPW_];
    __shared__ float red[SPW_];

    float slse = g_start_lse_v;

    int v0  = text[b * T_ + 0];
    int cb0 = word2state[(size_t)v0 * SPW_];
    int v1  = text[b * T_ + 1];
    int cb1 = word2state[(size_t)v1 * SPW_];

    // t = 0 : add_i = start_lp[i] + obs0[i] - row_lse[i]
    add[j] = g_start_s[cb0 + j] - slse + g_obs[(b * T_ + 0) * SPW_ + j] - g_row_lse[cb0 + j];
    __syncthreads();
    float mx = block_max128(add[j], red);

    const float* base = g_trans + (size_t)cb0 * C_ + cb1;
    float s = 0.f;
#pragma unroll 4
    for (int i = 0; i < SPW_; i++)
        s += __expf(base[(size_t)i * C_ + j] + add[i] - mx);
    float aj = mx + logf(s) + g_obs[(b * T_ + 1) * SPW_ + j];

    int cprev = cb1;
    for (int t = 1; t < T_ - 1; t++) {
        int vn  = text[b * T_ + t + 1];
        int cbn = word2state[(size_t)vn * SPW_];
        __syncthreads();                 // protect add[] from previous readers
        add[j] = aj - g_row_lse[cprev + j];
        __syncthreads();
        mx = block_max128(add[j], red);

        const float* bs2 = g_trans + (size_t)cprev * C_ + cbn;
        float s2 = 0.f;
#pragma unroll 4
        for (int i = 0; i < SPW_; i++)
            s2 += __expf(bs2[(size_t)i * C_ + j] + add[i] - mx);
        aj = mx + logf(s2) + g_obs[(b * T_ + (t + 1)) * SPW_ + j];
        cprev = cbn;
    }

    // final LSE over aj
    float m = block_max128(aj, red);
    red[j] = __expf(aj - m);
    __syncthreads();
#pragma unroll
    for (int o = 64; o > 0; o >>= 1) {
        if (j < o) red[j] += red[j + o];
        __syncthreads();
    }
    if (j == 0) out[b] = m + logf(red[0]);
}

// ---------------- launch ----------------------------------------------------------------
extern "C" void kernel_launch(void* const* d_in, const int* in_sizes, int n_in,
                              void* d_out, int out_size) {
    const int*   text       = (const int*)d_in[0];
    const int*   word2state = (const int*)d_in[1];
    const float* start_emb  = (const float*)d_in[2];
    const float* sw1 = (const float*)d_in[3];
    const float* sb1 = (const float*)d_in[4];
    const float* sw2 = (const float*)d_in[5];
    const float* sb2 = (const float*)d_in[6];
    const float* sow = (const float*)d_in[7];
    const float* sob = (const float*)d_in[8];
    const float* state_emb = (const float*)d_in[9];
    const float* tw1 = (const float*)d_in[10];
    const float* tb1 = (const float*)d_in[11];
    const float* tw2 = (const float*)d_in[12];
    const float* tb2 = (const float*)d_in[13];
    const float* next_state_emb  = (const float*)d_in[14];
    const float* preterminal_emb = (const float*)d_in[15];
    const float* ew1 = (const float*)d_in[16];
    const float* eb1 = (const float*)d_in[17];
    const float* ew2 = (const float*)d_in[18];
    const float* eb2 = (const float*)d_in[19];
    const float* proj_w = (const float*)d_in[20];
    const float* proj_b = (const float*)d_in[21];
    float* out = (float*)d_out;

    float *p_tmp, *p_rstart, *p_rstate, *p_rpre, *p_trans;
    cudaGetSymbolAddress((void**)&p_tmp,    g_tmp);
    cudaGetSymbolAddress((void**)&p_rstart, g_r_start);
    cudaGetSymbolAddress((void**)&p_rstate, g_r_state);
    cudaGetSymbolAddress((void**)&p_rpre,   g_r_pre);
    cudaGetSymbolAddress((void**)&p_trans,  g_trans);

    dim3 gs(H_ / 128, C_ / 128);   // (2, 64) for the MLP gemms
    // residual MLPs
    gemm_nt<1><<<gs, 256>>>(start_emb, sw1, sb1, nullptr, p_tmp, C_, H_, H_);
    gemm_nt<1><<<gs, 256>>>(p_tmp, sw2, sb2, start_emb, p_rstart, C_, H_, H_);
    gemm_nt<1><<<gs, 256>>>(state_emb, tw1, tb1, nullptr, p_tmp, C_, H_, H_);
    gemm_nt<1><<<gs, 256>>>(p_tmp, tw2, tb2, state_emb, p_rstate, C_, H_, H_);
    gemm_nt<1><<<gs, 256>>>(preterminal_emb, ew1, eb1, nullptr, p_tmp, C_, H_, H_);
    gemm_nt<1><<<gs, 256>>>(p_tmp, ew2, eb2, preterminal_emb, p_rpre, C_, H_, H_);

    // start distribution
    start_head<<<C_ / 8, 256>>>(sow, sob);
    start_lse_kernel<<<1, 256>>>();

    // transition logits (the big one) + row LSE
    dim3 gt(C_ / 128, C_ / 128);   // (64, 64)
    gemm_nt<0><<<gt, 256>>>(p_rstate, next_state_emb, nullptr, nullptr, p_trans, C_, C_, H_);
    row_lse_kernel<<<C_, 256>>>();

    // emission (sparse path — only cluster-restricted columns)
    zero_counts<<<1, 64>>>();
    build_lists<<<(V_ + 255) / 256, 256>>>(word2state);
    emis_lse_kernel<<<C_, 256>>>(proj_w, proj_b);
    obs_kernel<<<B_ * T_, 256>>>(text, word2state, proj_w, proj_b);

    // forward algorithm
    forward_kernel<<<B_, 128>>>(text, word2state, out);
}

// round 3
// speedup vs baseline: 1.3861x; 1.3861x over previous
#include <cuda_runtime.h>
#include <cuda_bf16.h>
#include <math.h>
#include <stdint.h>

#define V_  10000
#define C_  8192
#define NC_ 64
#define SPW_ 128
#define H_  256
#define B_  16
#define T_  33
#define MAXW_ 1024

// ---------------- scratch (device globals; no allocation allowed) ----------------
__device__ __align__(16) float g_tmp[C_ * H_];
__device__ __align__(16) float g_r_start[C_ * H_];
__device__ __align__(16) float g_r_state[C_ * H_];
__device__ __align__(16) float g_r_pre[C_ * H_];
__device__ __align__(16) float g_trans[(size_t)C_ * C_];   // 256 MB trans_logits
__device__ __align__(16) __nv_bfloat16 g_state_bf[C_ * H_];
__device__ __align__(16) __nv_bfloat16 g_next_bf[C_ * H_];
__device__ __align__(16) float g_rowsum_part[64 * C_];     // per col-block partial exp sums
__device__ float g_row_lse[C_];
__device__ float g_start_s[C_];
__device__ float g_start_lse_v;
__device__ float g_else[C_];
__device__ float g_obs[B_ * T_ * SPW_];
__device__ int   g_cl_words[NC_ * MAXW_];
__device__ int   g_cl_cnt[NC_];

__device__ __forceinline__ uint32_t smem_u32(const void* p) {
    uint32_t a;
    asm("{ .reg .u64 t; cvta.to.shared.u64 t, %1; cvt.u32.u64 %0, t; }" : "=r"(a) : "l"(p));
    return a;
}

// ---------------- trans GEMM via mma.sync (HMMA bf16) ---------------------------------
// 128x128 tile per CTA, K=256 fully SMEM-resident. 8 warps: 2 (M) x 4 (N), warp = 64x32.
// Also computes per-tile row sums of exp(x) into g_rowsum_part (deterministic).
#define LDA_ 264                         // 256 + 8 pad (conflict-free ldmatrix)
#define TG_A_BYTES (128 * LDA_ * 2)      // 67584
#define TG_SMEM_TOT (2 * TG_A_BYTES + 4 * 128 * 4)  // A + B + rowsum partials

__global__ void __launch_bounds__(256, 1) trans_gemm_kernel() {
    extern __shared__ char smem[];
    __nv_bfloat16* As = reinterpret_cast<__nv_bfloat16*>(smem);
    __nv_bfloat16* Bs = reinterpret_cast<__nv_bfloat16*>(smem + TG_A_BYTES);
    float* rs_sm = reinterpret_cast<float*>(smem + 2 * TG_A_BYTES);  // [4][128]

    int tid  = threadIdx.x;
    int warp = tid >> 5;
    int lane = tid & 31;
    int wm = warp >> 2;        // 0..1
    int wn = warp & 3;         // 0..3
    int m0 = blockIdx.y * 128;
    int n0 = blockIdx.x * 128;

    // ---- load tiles: thread = (row = tid>>1, half = tid&1), 16 x uint4 each ----
    {
        int row  = tid >> 1;
        int half = tid & 1;
        const uint4* ga = reinterpret_cast<const uint4*>(g_state_bf + (size_t)(m0 + row) * H_ + half * 128);
        const uint4* gb = reinterpret_cast<const uint4*>(g_next_bf  + (size_t)(n0 + row) * H_ + half * 128);
        uint4* sa = reinterpret_cast<uint4*>(As + row * LDA_ + half * 128);
        uint4* sb = reinterpret_cast<uint4*>(Bs + row * LDA_ + half * 128);
#pragma unroll
        for (int i = 0; i < 16; i++) { sa[i] = ga[i]; sb[i] = gb[i]; }
    }
    __syncthreads();

    // ---- fragment base addresses ----
    uint32_t a_base = smem_u32(As) + (((wm * 64 + (lane & 15)) * LDA_ + (lane >> 4) * 8) << 1);
    uint32_t b_base = smem_u32(Bs) + (((wn * 32 + (lane & 7)) * LDA_ + ((lane >> 3) & 1) * 8) << 1);

    float acc[4][4][4];
#pragma unroll
    for (int mi = 0; mi < 4; mi++)
#pragma unroll
        for (int nf = 0; nf < 4; nf++)
#pragma unroll
            for (int r = 0; r < 4; r++) acc[mi][nf][r] = 0.f;

#pragma unroll
    for (int k = 0; k < 16; k++) {
        uint32_t a[4][4], b[4][2];
#pragma unroll
        for (int mi = 0; mi < 4; mi++) {
            uint32_t addr = a_base + ((mi * 16 * LDA_ + k * 16) << 1);
            asm volatile("ldmatrix.sync.aligned.m8n8.x4.shared.b16 {%0,%1,%2,%3}, [%4];"
                         : "=r"(a[mi][0]), "=r"(a[mi][1]), "=r"(a[mi][2]), "=r"(a[mi][3])
                         : "r"(addr));
        }
#pragma unroll
        for (int nf = 0; nf < 4; nf++) {
            uint32_t addr = b_base + ((nf * 8 * LDA_ + k * 16) << 1);
            asm volatile("ldmatrix.sync.aligned.m8n8.x2.shared.b16 {%0,%1}, [%2];"
                         : "=r"(b[nf][0]), "=r"(b[nf][1])
                         : "r"(addr));
        }
#pragma unroll
        for (int mi = 0; mi < 4; mi++)
#pragma unroll
            for (int nf = 0; nf < 4; nf++) {
                asm volatile(
                    "mma.sync.aligned.m16n8k16.row.col.f32.bf16.bf16.f32 "
                    "{%0,%1,%2,%3}, {%4,%5,%6,%7}, {%8,%9}, {%0,%1,%2,%3};"
                    : "+f"(acc[mi][nf][0]), "+f"(acc[mi][nf][1]),
                      "+f"(acc[mi][nf][2]), "+f"(acc[mi][nf][3])
                    : "r"(a[mi][0]), "r"(a[mi][1]), "r"(a[mi][2]), "r"(a[mi][3]),
                      "r"(b[nf][0]), "r"(b[nf][1]));
            }
    }

    // ---- epilogue: store + fused row exp-sums -----------------------------------------
    // Thread owns rows r0 = wm*64 + mi*16 + lane/4, r1 = r0 + 8; cols wn*32 + nf*8 + (lane%4)*2.
    int qr = lane >> 2;            // 0..7
    int qc = lane & 3;             // 0..3
#pragma unroll
    for (int mi = 0; mi < 4; mi++) {
        int rloc0 = wm * 64 + mi * 16 + qr;
        float* row0 = g_trans + (size_t)(m0 + rloc0) * C_ + n0 + wn * 32 + qc * 2;
        float* row1 = row0 + (size_t)8 * C_;
        float s0 = 0.f, s1 = 0.f;
#pragma unroll
        for (int nf = 0; nf < 4; nf++) {
            float2 v0 = make_float2(acc[mi][nf][0], acc[mi][nf][1]);
            float2 v1 = make_float2(acc[mi][nf][2], acc[mi][nf][3]);
            s0 += __expf(v0.x) + __expf(v0.y);
            s1 += __expf(v1.x) + __expf(v1.y);
            *reinterpret_cast<float2*>(row0 + nf * 8) = v0;
            *reinterpret_cast<float2*>(row1 + nf * 8) = v1;
        }
        // reduce across the 4 lanes sharing a row
        s0 += __shfl_xor_sync(0xffffffffu, s0, 1);
        s0 += __shfl_xor_sync(0xffffffffu, s0, 2);
        s1 += __shfl_xor_sync(0xffffffffu, s1, 1);
        s1 += __shfl_xor_sync(0xffffffffu, s1, 2);
        if (qc == 0) {
            rs_sm[wn * 128 + rloc0]     = s0;
            rs_sm[wn * 128 + rloc0 + 8] = s1;
        }
    }
    __syncthreads();
    if (tid < 128) {
        float s = rs_sm[tid] + rs_sm[128 + tid] + rs_sm[256 + tid] + rs_sm[384 + tid];
        g_rowsum_part[(size_t)blockIdx.x * C_ + m0 + tid] = s;
    }
}

// ---------------- bf16 conversions ---------------------------------------------------
__global__ void conv_bf16_kernel(const float* __restrict__ next_state_emb) {
    int i = blockIdx.x * blockDim.x + threadIdx.x;
    if (i < C_ * H_) {
        g_state_bf[i] = __float2bfloat16_rn(g_r_state[i]);
        g_next_bf[i]  = __float2bfloat16_rn(next_state_emb[i]);
    }
}

// ---------------- row lse from partial sums ------------------------------------------
__global__ void row_lse_final_kernel() {
    int c = blockIdx.x * blockDim.x + threadIdx.x;
    if (c >= C_) return;
    float s = 0.f;
#pragma unroll
    for (int p = 0; p < 64; p++) s += g_rowsum_part[(size_t)p * C_ + c];
    g_row_lse[c] = logf(s);
}

// ---------------- generic NT SGEMM (fp32 MLPs) ---------------------------------------
template <int ACT>   // 0 = none, 1 = relu
__global__ void gemm_nt(const float* __restrict__ A, const float* __restrict__ Bm,
                        const float* __restrict__ bias, const float* __restrict__ res,
                        float* __restrict__ Cm, int M, int N, int K) {
    const int BM = 128, BN = 128, BK = 16;
    __shared__ float As[BK][BM];
    __shared__ float Bs[BK][BN];

    int t  = threadIdx.x;
    int m0 = blockIdx.y * BM;
    int n0 = blockIdx.x * BN;
    int tx = t & 15, ty = t >> 4;

    float acc[8][8];
#pragma unroll
    for (int a = 0; a < 8; a++)
#pragma unroll
        for (int b = 0; b < 8; b++) acc[a][b] = 0.f;

    for (int k0 = 0; k0 < K; k0 += BK) {
#pragma unroll
        for (int r = 0; r < 2; r++) {
            int idx  = r * 256 + t;
            int row  = idx >> 2;
            int quad = idx & 3;
            float4 va = *reinterpret_cast<const float4*>(A + (size_t)(m0 + row) * K + k0 + quad * 4);
            As[quad * 4 + 0][row] = va.x;
            As[quad * 4 + 1][row] = va.y;
            As[quad * 4 + 2][row] = va.z;
            As[quad * 4 + 3][row] = va.w;
            float4 vb = *reinterpret_cast<const float4*>(Bm + (size_t)(n0 + row) * K + k0 + quad * 4);
            Bs[quad * 4 + 0][row] = vb.x;
            Bs[quad * 4 + 1][row] = vb.y;
            Bs[quad * 4 + 2][row] = vb.z;
            Bs[quad * 4 + 3][row] = vb.w;
        }
        __syncthreads();
#pragma unroll
        for (int k = 0; k < BK; k++) {
            float ra[8], rb[8];
            *reinterpret_cast<float4*>(ra)     = *reinterpret_cast<float4*>(&As[k][ty * 8]);
            *reinterpret_cast<float4*>(ra + 4) = *reinterpret_cast<float4*>(&As[k][ty * 8 + 4]);
            *reinterpret_cast<float4*>(rb)     = *reinterpret_cast<float4*>(&Bs[k][tx * 8]);
            *reinterpret_cast<float4*>(rb + 4) = *reinterpret_cast<float4*>(&Bs[k][tx * 8 + 4]);
#pragma unroll
            for (int a = 0; a < 8; a++)
#pragma unroll
                for (int b = 0; b < 8; b++) acc[a][b] = fmaf(ra[a], rb[b], acc[a][b]);
        }
        __syncthreads();
    }

#pragma unroll
    for (int a = 0; a < 8; a++) {
        int m = m0 + ty * 8 + a;
#pragma unroll
        for (int b = 0; b < 8; b++) {
            int n = n0 + tx * 8 + b;
            float v = acc[a][b];
            if (bias) v += bias[n];
            if (ACT == 1) v = fmaxf(v, 0.f);
            if (res) v += res[(size_t)m * N + n];
            Cm[(size_t)m * N + n] = v;
        }
    }
}

// ---------------- start head ----------------------------------------------------------
__global__ void start_head(const float* __restrict__ sow, const float* __restrict__ sob) {
    int gw   = (blockIdx.x * blockDim.x + threadIdx.x) >> 5;
    int lane = threadIdx.x & 31;
    if (gw >= C_) return;
    float acc = 0.f;
#pragma unroll
    for (int q = 0; q < 8; q++)
        acc += g_r_start[(size_t)gw * H_ + lane + 32 * q] * sow[lane + 32 * q];
#pragma unroll
    for (int o = 16; o > 0; o >>= 1) acc += __shfl_xor_sync(0xffffffffu, acc, o);
    if (lane == 0) g_start_s[gw] = acc + sob[0];
}

__global__ void start_lse_kernel() {
    int tid = threadIdx.x;
    float m = -INFINITY, s = 0.f;
    for (int c = tid; c < C_; c += 256) {
        float x  = g_start_s[c];
        float nm = fmaxf(m, x);
        s = s * __expf(m - nm) + __expf(x - nm);
        m = nm;
    }
    __shared__ float sm[256], ss[256];
    sm[tid] = m; ss[tid] = s;
    __syncthreads();
    for (int o = 128; o > 0; o >>= 1) {
        if (tid < o) {
            float m2 = sm[tid + o], s2 = ss[tid + o];
            float nm = fmaxf(sm[tid], m2);
            ss[tid] = ss[tid] * __expf(sm[tid] - nm) + s2 * __expf(m2 - nm);
            sm[tid] = nm;
        }
        __syncthreads();
    }
    if (tid == 0) g_start_lse_v = sm[0] + logf(ss[0]);
}

// ---------------- cluster membership lists ------------------------------------------
__global__ void zero_counts() {
    if (threadIdx.x < NC_) g_cl_cnt[threadIdx.x] = 0;
}
__global__ void build_lists(const int* __restrict__ word2state) {
    int w = blockIdx.x * blockDim.x + threadIdx.x;
    if (w >= V_) return;
    int k   = word2state[(size_t)w * SPW_] >> 7;
    int pos = atomicAdd(&g_cl_cnt[k], 1);
    if (pos < MAXW_) g_cl_words[k * MAXW_ + pos] = w;
}

// ---------------- emission denominator ------------------------------------------------
__global__ void emis_lse_kernel(const float* __restrict__ proj_w, const float* __restrict__ proj_b) {
    int c   = blockIdx.x;
    int tid = threadIdx.x;
    __shared__ float xr[H_];
    xr[tid] = g_r_pre[(size_t)c * H_ + tid];
    __syncthreads();
    int k    = c >> 7;
    int cnt  = g_cl_cnt[k];
    const int* words = &g_cl_words[k * MAXW_];
    int lane = tid & 31, wrp = tid >> 5;

    float m = -INFINITY, s = 0.f;
    for (int idx = wrp; idx < cnt; idx += 8) {
        int v = words[idx];
        float acc = 0.f;
#pragma unroll
        for (int q = 0; q < 8; q++)
            acc += xr[lane + 32 * q] * proj_w[(size_t)v * H_ + lane + 32 * q];
#pragma unroll
        for (int o = 16; o > 0; o >>= 1) acc += __shfl_xor_sync(0xffffffffu, acc, o);
        float x  = acc + proj_b[v];
        float nm = fmaxf(m, x);
        s = s * __expf(m - nm) + __expf(x - nm);
        m = nm;
    }
    __shared__ float sm[8], ss[8];
    if (lane == 0) { sm[wrp] = m; ss[wrp] = s; }
    __syncthreads();
    if (tid == 0) {
        float M = -INFINITY, S = 0.f;
        for (int i = 0; i < 8; i++) {
            if (sm[i] == -INFINITY) continue;
            float nm = fmaxf(M, sm[i]);
            S = S * __expf(M - nm) + ss[i] * __expf(sm[i] - nm);
            M = nm;
        }
        g_else[c] = M + logf(S);
    }
}

// ---------------- obs ------------------------------------------------------------------
__global__ void obs_kernel(const int* __restrict__ text, const int* __restrict__ word2state,
                           const float* __restrict__ proj_w, const float* __restrict__ proj_b) {
    int bt  = blockIdx.x;
    int tid = threadIdx.x;
    int v     = text[bt];
    int cbase = word2state[(size_t)v * SPW_];
    __shared__ float pw[H_];
    pw[tid] = proj_w[(size_t)v * H_ + tid];
    __syncthreads();
    int lane = tid & 31, wrp = tid >> 5;
    float pb = proj_b[v];
    for (int s = wrp; s < SPW_; s += 8) {
        int c = cbase + s;
        float acc = 0.f;
#pragma unroll
        for (int q = 0; q < 8; q++)
            acc += pw[lane + 32 * q] * g_r_pre[(size_t)c * H_ + lane + 32 * q];
#pragma unroll
        for (int o = 16; o > 0; o >>= 1) acc += __shfl_xor_sync(0xffffffffu, acc, o);
        if (lane == 0) g_obs[bt * SPW_ + s] = acc + pb - g_else[c];
    }
}

// ---------------- forward recursion ---------------------------------------------------
__device__ __forceinline__ float block_max128(float v, float* red) {
    int j = threadIdx.x;
    red[j] = v;
    __syncthreads();
#pragma unroll
    for (int o = 64; o > 0; o >>= 1) {
        if (j < o) red[j] = fmaxf(red[j], red[j + o]);
        __syncthreads();
    }
    float r = red[0];
    __syncthreads();
    return r;
}

__global__ void forward_kernel(const int* __restrict__ text, const int* __restrict__ word2state,
                               float* __restrict__ out) {
    int b = blockIdx.x;
    int j = threadIdx.x;
    __shared__ float add[SPW_];
    __shared__ float red[SPW_];

    float slse = g_start_lse_v;

    int v0  = text[b * T_ + 0];
    int cb0 = word2state[(size_t)v0 * SPW_];
    int v1  = text[b * T_ + 1];
    int cb1 = word2state[(size_t)v1 * SPW_];

    add[j] = g_start_s[cb0 + j] - slse + g_obs[(b * T_ + 0) * SPW_ + j] - g_row_lse[cb0 + j];
    __syncthreads();
    float mx = block_max128(add[j], red);

    const float* base = g_trans + (size_t)cb0 * C_ + cb1;
    float s = 0.f;
#pragma unroll 4
    for (int i = 0; i < SPW_; i++)
        s += __expf(base[(size_t)i * C_ + j] + add[i] - mx);
    float aj = mx + logf(s) + g_obs[(b * T_ + 1) * SPW_ + j];

    int cprev = cb1;
    for (int t = 1; t < T_ - 1; t++) {
        int vn  = text[b * T_ + t + 1];
        int cbn = word2state[(size_t)vn * SPW_];
        __syncthreads();
        add[j] = aj - g_row_lse[cprev + j];
        __syncthreads();
        mx = block_max128(add[j], red);

        const float* bs2 = g_trans + (size_t)cprev * C_ + cbn;
        float s2 = 0.f;
#pragma unroll 4
        for (int i = 0; i < SPW_; i++)
            s2 += __expf(bs2[(size_t)i * C_ + j] + add[i] - mx);
        aj = mx + logf(s2) + g_obs[(b * T_ + (t + 1)) * SPW_ + j];
        cprev = cbn;
    }

    float m = block_max128(aj, red);
    red[j] = __expf(aj - m);
    __syncthreads();
#pragma unroll
    for (int o = 64; o > 0; o >>= 1) {
        if (j < o) red[j] += red[j + o];
        __syncthreads();
    }
    if (j == 0) out[b] = m + logf(red[0]);
}

// ---------------- launch ----------------------------------------------------------------
extern "C" void kernel_launch(void* const* d_in, const int* in_sizes, int n_in,
                              void* d_out, int out_size) {
    const int*   text       = (const int*)d_in[0];
    const int*   word2state = (const int*)d_in[1];
    const float* start_emb  = (const float*)d_in[2];
    const float* sw1 = (const float*)d_in[3];
    const float* sb1 = (const float*)d_in[4];
    const float* sw2 = (const float*)d_in[5];
    const float* sb2 = (const float*)d_in[6];
    const float* sow = (const float*)d_in[7];
    const float* sob = (const float*)d_in[8];
    const float* state_emb = (const float*)d_in[9];
    const float* tw1 = (const float*)d_in[10];
    const float* tb1 = (const float*)d_in[11];
    const float* tw2 = (const float*)d_in[12];
    const float* tb2 = (const float*)d_in[13];
    const float* next_state_emb  = (const float*)d_in[14];
    const float* preterminal_emb = (const float*)d_in[15];
    const float* ew1 = (const float*)d_in[16];
    const float* eb1 = (const float*)d_in[17];
    const float* ew2 = (const float*)d_in[18];
    const float* eb2 = (const float*)d_in[19];
    const float* proj_w = (const float*)d_in[20];
    const float* proj_b = (const float*)d_in[21];
    float* out = (float*)d_out;

    float *p_tmp, *p_rstart, *p_rstate, *p_rpre;
    cudaGetSymbolAddress((void**)&p_tmp,    g_tmp);
    cudaGetSymbolAddress((void**)&p_rstart, g_r_start);
    cudaGetSymbolAddress((void**)&p_rstate, g_r_state);
    cudaGetSymbolAddress((void**)&p_rpre,   g_r_pre);

    cudaFuncSetAttribute(trans_gemm_kernel, cudaFuncAttributeMaxDynamicSharedMemorySize, TG_SMEM_TOT);

    dim3 gs(H_ / 128, C_ / 128);   // (2, 64) for the MLP gemms
    // residual MLPs (fp32)
    gemm_nt<1><<<gs, 256>>>(start_emb, sw1, sb1, nullptr, p_tmp, C_, H_, H_);
    gemm_nt<1><<<gs, 256>>>(p_tmp, sw2, sb2, start_emb, p_rstart, C_, H_, H_);
    gemm_nt<1><<<gs, 256>>>(state_emb, tw1, tb1, nullptr, p_tmp, C_, H_, H_);
    gemm_nt<1><<<gs, 256>>>(p_tmp, tw2, tb2, state_emb, p_rstate, C_, H_, H_);
    gemm_nt<1><<<gs, 256>>>(preterminal_emb, ew1, eb1, nullptr, p_tmp, C_, H_, H_);
    gemm_nt<1><<<gs, 256>>>(p_tmp, ew2, eb2, preterminal_emb, p_rpre, C_, H_, H_);

    // start distribution
    start_head<<<C_ / 8, 256>>>(sow, sob);
    start_lse_kernel<<<1, 256>>>();

    // transition logits: bf16 HMMA GEMM with fused row exp-sum
    conv_bf16_kernel<<<(C_ * H_ + 255) / 256, 256>>>(next_state_emb);
    dim3 gt(C_ / 128, C_ / 128);   // (64, 64)
    trans_gemm_kernel<<<gt, 256, TG_SMEM_TOT>>>();
    row_lse_final_kernel<<<C_ / 256, 256>>>();

    // emission (sparse path)
    zero_counts<<<1, 64>>>();
    build_lists<<<(V_ + 255) / 256, 256>>>(word2state);
    emis_lse_kernel<<<C_, 256>>>(proj_w, proj_b);
    obs_kernel<<<B_ * T_, 256>>>(text, word2state, proj_w, proj_b);

    // forward algorithm
    forward_kernel<<<B_, 128>>>(text, word2state, out);
}

// round 4
// speedup vs baseline: 3.2422x; 2.3390x over previous
#include <cuda_runtime.h>
#include <cuda_bf16.h>
#include <math.h>
#include <stdint.h>

#define V_  10000
#define C_  8192
#define NC_ 64
#define SPW_ 128
#define H_  256
#define B_  16
#define T_  33
#define MAXW_ 1024
#define NP_  (B_ * (T_ - 1))     // 512 transition blocks

// ---------------- scratch (device globals; no allocation allowed) ----------------
__device__ __align__(16) float g_r_start[C_ * H_];
__device__ __align__(16) float g_r_pre[C_ * H_];
__device__ __align__(16) __nv_bfloat16 g_h_bf[C_ * H_];       // hidden (layer1 out)
__device__ __align__(16) __nv_bfloat16 g_semb_bf[C_ * H_];
__device__ __align__(16) __nv_bfloat16 g_stemb_bf[C_ * H_];
__device__ __align__(16) __nv_bfloat16 g_ptemb_bf[C_ * H_];
__device__ __align__(16) __nv_bfloat16 g_next_bf[C_ * H_];
__device__ __align__(16) __nv_bfloat16 g_state_bf[C_ * H_];
__device__ __align__(16) __nv_bfloat16 g_wbf[6 * H_ * H_];    // sw1,sw2,tw1,tw2,ew1,ew2
__device__ __align__(16) float g_blk[(size_t)NP_ * SPW_ * SPW_];  // 32 MB
__device__ __align__(16) float g_rowsum_part[64 * C_];
__device__ float g_row_lse[C_];
__device__ float g_start_s[C_];
__device__ float g_start_lse_v;
__device__ float g_else[C_];
__device__ float g_obs[B_ * T_ * SPW_];
__device__ int   g_cl_words[NC_ * MAXW_];
__device__ int   g_cl_cnt[NC_];

__device__ __forceinline__ uint32_t smem_u32(const void* p) {
    uint32_t a;
    asm("{ .reg .u64 t; cvta.to.shared.u64 t, %1; cvt.u32.u64 %0, t; }" : "=r"(a) : "l"(p));
    return a;
}

// ======================================================================================
// Shared HMMA tile machinery: 128x128 output, K=256 SMEM-resident, 8 warps (2M x 4N)
// ======================================================================================
#define LDA_ 264
#define TILE_BYTES_ (128 * LDA_ * 2)            // 67584 per tile
#define HG_SMEM_ (2 * TILE_BYTES_)              // 135168

// loads 128 rows x 256 bf16 from src (pitch H_) into tile
__device__ __forceinline__ void load_tile(__nv_bfloat16* dst, const __nv_bfloat16* src, int tid) {
    int row  = tid >> 1;
    int half = tid & 1;
    const uint4* g = reinterpret_cast<const uint4*>(src + (size_t)row * H_ + half * 128);
    uint4* s = reinterpret_cast<uint4*>(dst + row * LDA_ + half * 128);
#pragma unroll
    for (int i = 0; i < 16; i++) s[i] = g[i];
}

// mainloop: fills acc[4][4][4] from As/Bs
__device__ __forceinline__ void mma_mainloop(const __nv_bfloat16* As, const __nv_bfloat16* Bs,
                                             int wm, int wn, int lane, float acc[4][4][4]) {
    uint32_t a_base = smem_u32(As) + (((wm * 64 + (lane & 15)) * LDA_ + (lane >> 4) * 8) << 1);
    uint32_t b_base = smem_u32(Bs) + (((wn * 32 + (lane & 7)) * LDA_ + ((lane >> 3) & 1) * 8) << 1);
#pragma unroll
    for (int k = 0; k < 16; k++) {
        uint32_t a[4][4], b[4][2];
#pragma unroll
        for (int mi = 0; mi < 4; mi++) {
            uint32_t addr = a_base + ((mi * 16 * LDA_ + k * 16) << 1);
            asm volatile("ldmatrix.sync.aligned.m8n8.x4.shared.b16 {%0,%1,%2,%3}, [%4];"
                         : "=r"(a[mi][0]), "=r"(a[mi][1]), "=r"(a[mi][2]), "=r"(a[mi][3])
                         : "r"(addr));
        }
#pragma unroll
        for (int nf = 0; nf < 4; nf++) {
            uint32_t addr = b_base + ((nf * 8 * LDA_ + k * 16) << 1);
            asm volatile("ldmatrix.sync.aligned.m8n8.x2.shared.b16 {%0,%1}, [%2];"
                         : "=r"(b[nf][0]), "=r"(b[nf][1])
                         : "r"(addr));
        }
#pragma unroll
        for (int mi = 0; mi < 4; mi++)
#pragma unroll
            for (int nf = 0; nf < 4; nf++) {
                asm volatile(
                    "mma.sync.aligned.m16n8k16.row.col.f32.bf16.bf16.f32 "
                    "{%0,%1,%2,%3}, {%4,%5,%6,%7}, {%8,%9}, {%0,%1,%2,%3};"
                    : "+f"(acc[mi][nf][0]), "+f"(acc[mi][nf][1]),
                      "+f"(acc[mi][nf][2]), "+f"(acc[mi][nf][3])
                    : "r"(a[mi][0]), "r"(a[mi][1]), "r"(a[mi][2]), "r"(a[mi][3]),
                      "r"(b[nf][0]), "r"(b[nf][1]));
            }
    }
}

// ---------------- rowsum kernel: full C x C, exp-sum only, no store ---------------------
__global__ void __launch_bounds__(256, 1) rowsum_kernel() {
    extern __shared__ char smem[];
    __nv_bfloat16* As = reinterpret_cast<__nv_bfloat16*>(smem);
    __nv_bfloat16* Bs = reinterpret_cast<__nv_bfloat16*>(smem + TILE_BYTES_);
    __shared__ float rs_sm[4 * 128];

    int tid = threadIdx.x, warp = tid >> 5, lane = tid & 31;
    int wm = warp >> 2, wn = warp & 3;
    int m0 = blockIdx.y * 128, n0 = blockIdx.x * 128;

    load_tile(As, g_state_bf + (size_t)m0 * H_, tid);
    load_tile(Bs, g_next_bf  + (size_t)n0 * H_, tid);
    __syncthreads();

    float acc[4][4][4];
#pragma unroll
    for (int mi = 0; mi < 4; mi++)
#pragma unroll
        for (int nf = 0; nf < 4; nf++)
#pragma unroll
            for (int r = 0; r < 4; r++) acc[mi][nf][r] = 0.f;
    mma_mainloop(As, Bs, wm, wn, lane, acc);

    int qr = lane >> 2, qc = lane & 3;
#pragma unroll
    for (int mi = 0; mi < 4; mi++) {
        int rloc0 = wm * 64 + mi * 16 + qr;
        float s0 = 0.f, s1 = 0.f;
#pragma unroll
        for (int nf = 0; nf < 4; nf++) {
            s0 += __expf(acc[mi][nf][0]) + __expf(acc[mi][nf][1]);
            s1 += __expf(acc[mi][nf][2]) + __expf(acc[mi][nf][3]);
        }
        s0 += __shfl_xor_sync(0xffffffffu, s0, 1);
        s0 += __shfl_xor_sync(0xffffffffu, s0, 2);
        s1 += __shfl_xor_sync(0xffffffffu, s1, 1);
        s1 += __shfl_xor_sync(0xffffffffu, s1, 2);
        if (qc == 0) {
            rs_sm[wn * 128 + rloc0]     = s0;
            rs_sm[wn * 128 + rloc0 + 8] = s1;
        }
    }
    __syncthreads();
    if (tid < 128) {
        float s = rs_sm[tid] + rs_sm[128 + tid] + rs_sm[256 + tid] + rs_sm[384 + tid];
        g_rowsum_part[(size_t)blockIdx.x * C_ + m0 + tid] = s;
    }
}

// ---------------- blk kernel: one 128x128 logits block per (b,t) pair -------------------
__global__ void __launch_bounds__(256, 1) blk_kernel(const int* __restrict__ text,
                                                     const int* __restrict__ w2s) {
    extern __shared__ char smem[];
    __nv_bfloat16* As = reinterpret_cast<__nv_bfloat16*>(smem);
    __nv_bfloat16* Bs = reinterpret_cast<__nv_bfloat16*>(smem + TILE_BYTES_);

    int tid = threadIdx.x, warp = tid >> 5, lane = tid & 31;
    int wm = warp >> 2, wn = warp & 3;
    int p = blockIdx.x;
    int b = p >> 5, s = p & 31;               // T_-1 = 32
    int cp = w2s[(size_t)text[b * T_ + s]     * SPW_];
    int cn = w2s[(size_t)text[b * T_ + s + 1] * SPW_];

    load_tile(As, g_state_bf + (size_t)cp * H_, tid);
    load_tile(Bs, g_next_bf  + (size_t)cn * H_, tid);
    __syncthreads();

    float acc[4][4][4];
#pragma unroll
    for (int mi = 0; mi < 4; mi++)
#pragma unroll
        for (int nf = 0; nf < 4; nf++)
#pragma unroll
            for (int r = 0; r < 4; r++) acc[mi][nf][r] = 0.f;
    mma_mainloop(As, Bs, wm, wn, lane, acc);

    int qr = lane >> 2, qc = lane & 3;
    float* out = g_blk + (size_t)p * (SPW_ * SPW_);
#pragma unroll
    for (int mi = 0; mi < 4; mi++) {
        int rloc0 = wm * 64 + mi * 16 + qr;
        float* row0 = out + rloc0 * SPW_ + wn * 32 + qc * 2;
        float* row1 = row0 + 8 * SPW_;
#pragma unroll
        for (int nf = 0; nf < 4; nf++) {
            *reinterpret_cast<float2*>(row0 + nf * 8) = make_float2(acc[mi][nf][0], acc[mi][nf][1]);
            *reinterpret_cast<float2*>(row1 + nf * 8) = make_float2(acc[mi][nf][2], acc[mi][nf][3]);
        }
    }
}

// ---------------- MLP GEMM: out = relu(A @ W^T + bias) [+ res], bf16 in, fp32 acc -------
// MODE 0: store bf16 relu(acc+bias) to outB (hidden layer)
// MODE 1: v = relu(acc+bias) + res ; store fp32 to outF (if nonnull), bf16 to outB (if nonnull)
template <int MODE>
__global__ void __launch_bounds__(256, 1) hgemm_kernel(
    const __nv_bfloat16* __restrict__ A, const __nv_bfloat16* __restrict__ W,
    const float* __restrict__ bias, const float* __restrict__ res,
    float* __restrict__ outF, __nv_bfloat16* __restrict__ outB) {
    extern __shared__ char smem[];
    __nv_bfloat16* As = reinterpret_cast<__nv_bfloat16*>(smem);
    __nv_bfloat16* Bs = reinterpret_cast<__nv_bfloat16*>(smem + TILE_BYTES_);

    int tid = threadIdx.x, warp = tid >> 5, lane = tid & 31;
    int wm = warp >> 2, wn = warp & 3;
    int m0 = blockIdx.y * 128, n0 = blockIdx.x * 128;

    load_tile(As, A + (size_t)m0 * H_, tid);
    load_tile(Bs, W + (size_t)n0 * H_, tid);
    __syncthreads();

    float acc[4][4][4];
#pragma unroll
    for (int mi = 0; mi < 4; mi++)
#pragma unroll
        for (int nf = 0; nf < 4; nf++)
#pragma unroll
            for (int r = 0; r < 4; r++) acc[mi][nf][r] = 0.f;
    mma_mainloop(As, Bs, wm, wn, lane, acc);

    int qr = lane >> 2, qc = lane & 3;
#pragma unroll
    for (int mi = 0; mi < 4; mi++) {
        int r0 = m0 + wm * 64 + mi * 16 + qr;
        int r1 = r0 + 8;
#pragma unroll
        for (int nf = 0; nf < 4; nf++) {
            int c = n0 + wn * 32 + nf * 8 + qc * 2;
            float b0 = bias[c], b1 = bias[c + 1];
            float v00 = fmaxf(acc[mi][nf][0] + b0, 0.f);
            float v01 = fmaxf(acc[mi][nf][1] + b1, 0.f);
            float v10 = fmaxf(acc[mi][nf][2] + b0, 0.f);
            float v11 = fmaxf(acc[mi][nf][3] + b1, 0.f);
            if (MODE == 1) {
                float2 x0 = *reinterpret_cast<const float2*>(res + (size_t)r0 * H_ + c);
                float2 x1 = *reinterpret_cast<const float2*>(res + (size_t)r1 * H_ + c);
                v00 += x0.x; v01 += x0.y; v10 += x1.x; v11 += x1.y;
                if (outF) {
                    *reinterpret_cast<float2*>(outF + (size_t)r0 * H_ + c) = make_float2(v00, v01);
                    *reinterpret_cast<float2*>(outF + (size_t)r1 * H_ + c) = make_float2(v10, v11);
                }
            }
            if (outB) {
                __nv_bfloat162 h0 = __floats2bfloat162_rn(v00, v01);
                __nv_bfloat162 h1 = __floats2bfloat162_rn(v10, v11);
                *reinterpret_cast<__nv_bfloat162*>(outB + (size_t)r0 * H_ + c) = h0;
                *reinterpret_cast<__nv_bfloat162*>(outB + (size_t)r1 * H_ + c) = h1;
            }
        }
    }
}

// ---------------- conversions ---------------------------------------------------------
__global__ void conv_embs(const float* __restrict__ a, const float* __restrict__ b,
                          const float* __restrict__ c, const float* __restrict__ d) {
    int i = blockIdx.x * blockDim.x + threadIdx.x;
    if (i < C_ * H_) {
        g_semb_bf[i]  = __float2bfloat16_rn(a[i]);
        g_stemb_bf[i] = __float2bfloat16_rn(b[i]);
        g_ptemb_bf[i] = __float2bfloat16_rn(c[i]);
        g_next_bf[i]  = __float2bfloat16_rn(d[i]);
    }
}
__global__ void conv_ws(const float* __restrict__ w0, const float* __restrict__ w1,
                        const float* __restrict__ w2, const float* __restrict__ w3,
                        const float* __restrict__ w4, const float* __restrict__ w5) {
    int i = blockIdx.x * blockDim.x + threadIdx.x;
    if (i < H_ * H_) {
        g_wbf[0 * H_ * H_ + i] = __float2bfloat16_rn(w0[i]);
        g_wbf[1 * H_ * H_ + i] = __float2bfloat16_rn(w1[i]);
        g_wbf[2 * H_ * H_ + i] = __float2bfloat16_rn(w2[i]);
        g_wbf[3 * H_ * H_ + i] = __float2bfloat16_rn(w3[i]);
        g_wbf[4 * H_ * H_ + i] = __float2bfloat16_rn(w4[i]);
        g_wbf[5 * H_ * H_ + i] = __float2bfloat16_rn(w5[i]);
    }
}

// ---------------- row lse from partial sums ------------------------------------------
__global__ void row_lse_final_kernel() {
    int c = blockIdx.x * blockDim.x + threadIdx.x;
    if (c >= C_) return;
    float s = 0.f;
#pragma unroll
    for (int p = 0; p < 64; p++) s += g_rowsum_part[(size_t)p * C_ + c];
    g_row_lse[c] = logf(s);
}

// ---------------- start head ----------------------------------------------------------
__global__ void start_head(const float* __restrict__ sow, const float* __restrict__ sob) {
    int gw   = (blockIdx.x * blockDim.x + threadIdx.x) >> 5;
    int lane = threadIdx.x & 31;
    if (gw >= C_) return;
    float acc = 0.f;
#pragma unroll
    for (int q = 0; q < 8; q++)
        acc += g_r_start[(size_t)gw * H_ + lane + 32 * q] * sow[lane + 32 * q];
#pragma unroll
    for (int o = 16; o > 0; o >>= 1) acc += __shfl_xor_sync(0xffffffffu, acc, o);
    if (lane == 0) g_start_s[gw] = acc + sob[0];
}

__global__ void start_lse_kernel() {
    int tid = threadIdx.x;
    float m = -INFINITY, s = 0.f;
    for (int c = tid; c < C_; c += 256) {
        float x  = g_start_s[c];
        float nm = fmaxf(m, x);
        s = s * __expf(m - nm) + __expf(x - nm);
        m = nm;
    }
    __shared__ float sm[256], ss[256];
    sm[tid] = m; ss[tid] = s;
    __syncthreads();
    for (int o = 128; o > 0; o >>= 1) {
        if (tid < o) {
            float m2 = sm[tid + o], s2 = ss[tid + o];
            float nm = fmaxf(sm[tid], m2);
            ss[tid] = ss[tid] * __expf(sm[tid] - nm) + s2 * __expf(m2 - nm);
            sm[tid] = nm;
        }
        __syncthreads();
    }
    if (tid == 0) g_start_lse_v = sm[0] + logf(ss[0]);
}

// ---------------- cluster membership lists ------------------------------------------
__global__ void zero_counts() {
    if (threadIdx.x < NC_) g_cl_cnt[threadIdx.x] = 0;
}
__global__ void build_lists(const int* __restrict__ word2state) {
    int w = blockIdx.x * blockDim.x + threadIdx.x;
    if (w >= V_) return;
    int k   = word2state[(size_t)w * SPW_] >> 7;
    int pos = atomicAdd(&g_cl_cnt[k], 1);
    if (pos < MAXW_) g_cl_words[k * MAXW_ + pos] = w;
}

// ---------------- emission denominator ------------------------------------------------
__global__ void emis_lse_kernel(const float* __restrict__ proj_w, const float* __restrict__ proj_b) {
    int c   = blockIdx.x;
    int tid = threadIdx.x;
    __shared__ float xr[H_];
    xr[tid] = g_r_pre[(size_t)c * H_ + tid];
    __syncthreads();
    int k    = c >> 7;
    int cnt  = g_cl_cnt[k];
    const int* words = &g_cl_words[k * MAXW_];
    int lane = tid & 31, wrp = tid >> 5;

    float m = -INFINITY, s = 0.f;
    for (int idx = wrp; idx < cnt; idx += 8) {
        int v = words[idx];
        float acc = 0.f;
#pragma unroll
        for (int q = 0; q < 8; q++)
            acc += xr[lane + 32 * q] * proj_w[(size_t)v * H_ + lane + 32 * q];
#pragma unroll
        for (int o = 16; o > 0; o >>= 1) acc += __shfl_xor_sync(0xffffffffu, acc, o);
        float x  = acc + proj_b[v];
        float nm = fmaxf(m, x);
        s = s * __expf(m - nm) + __expf(x - nm);
        m = nm;
    }
    __shared__ float sm[8], ss[8];
    if (lane == 0) { sm[wrp] = m; ss[wrp] = s; }
    __syncthreads();
    if (tid == 0) {
        float M = -INFINITY, S = 0.f;
        for (int i = 0; i < 8; i++) {
            if (sm[i] == -INFINITY) continue;
            float nm = fmaxf(M, sm[i]);
            S = S * __expf(M - nm) + ss[i] * __expf(sm[i] - nm);
            M = nm;
        }
        g_else[c] = M + logf(S);
    }
}

// ---------------- obs ------------------------------------------------------------------
__global__ void obs_kernel(const int* __restrict__ text, const int* __restrict__ word2state,
                           const float* __restrict__ proj_w, const float* __restrict__ proj_b) {
    int bt  = blockIdx.x;
    int tid = threadIdx.x;
    int v     = text[bt];
    int cbase = word2state[(size_t)v * SPW_];
    __shared__ float pw[H_];
    pw[tid] = proj_w[(size_t)v * H_ + tid];
    __syncthreads();
    int lane = tid & 31, wrp = tid >> 5;
    float pb = proj_b[v];
    for (int s = wrp; s < SPW_; s += 8) {
        int c = cbase + s;
        float acc = 0.f;
#pragma unroll
        for (int q = 0; q < 8; q++)
            acc += pw[lane + 32 * q] * g_r_pre[(size_t)c * H_ + lane + 32 * q];
#pragma unroll
        for (int o = 16; o > 0; o >>= 1) acc += __shfl_xor_sync(0xffffffffu, acc, o);
        if (lane == 0) g_obs[bt * SPW_ + s] = acc + pb - g_else[c];
    }
}

// ---------------- forward recursion (smem-staged blocks, cp.async double buffer) -------
#define FW_PITCH_ 132
#define FW_BUF_   (128 * FW_PITCH_)             // floats
#define FW_SMEM_  (2 * FW_BUF_ * 4)             // bytes

__device__ __forceinline__ void fwd_load(float* buf, const float* __restrict__ src, int tid) {
    uint32_t sb = smem_u32(buf);
#pragma unroll
    for (int k = 0; k < 32; k++) {
        int f = k * 128 + tid;          // float4 index 0..4095
        int e = f << 2;
        int i = e >> 7, col = e & 127;
        uint32_t dst = sb + ((i * FW_PITCH_ + col) << 2);
        asm volatile("cp.async.cg.shared.global [%0], [%1], 16;" :: "r"(dst), "l"(src + e) : "memory");
    }
    asm volatile("cp.async.commit_group;" ::: "memory");
}

__device__ __forceinline__ float block_max128(float v, float* red) {
    int j = threadIdx.x;
    red[j] = v;
    __syncthreads();
#pragma unroll
    for (int o = 64; o > 0; o >>= 1) {
        if (j < o) red[j] = fmaxf(red[j], red[j + o]);
        __syncthreads();
    }
    float r = red[0];
    __syncthreads();
    return r;
}

__global__ void __launch_bounds__(128, 1) forward_kernel(const int* __restrict__ text,
                                                         const int* __restrict__ w2s,
                                                         float* __restrict__ out) {
    extern __shared__ float fsm[];              // 2 buffers
    __shared__ float add[128], red[128];
    int b = blockIdx.x, j = threadIdx.x;
    float* buf0 = fsm;
    float* buf1 = fsm + FW_BUF_;
    const float* blkbase = g_blk + (size_t)b * (T_ - 1) * (SPW_ * SPW_);

    fwd_load(buf0, blkbase, j);

    int cbs = w2s[(size_t)text[b * T_] * SPW_];
    float aj = g_start_s[cbs + j] - g_start_lse_v + g_obs[(b * T_) * SPW_ + j];

    for (int s = 0; s < T_ - 1; s++) {
        __syncthreads();                        // all threads done with previous add[]
        add[j] = aj - g_row_lse[cbs + j];
        asm volatile("cp.async.wait_group 0;" ::: "memory");
        __syncthreads();                        // block s in smem, add[] visible
        if (s + 1 < T_ - 1)
            fwd_load((s & 1) ? buf0 : buf1, blkbase + (size_t)(s + 1) * (SPW_ * SPW_), j);
        float mx = block_max128(add[j], red);
        const float* bc = (s & 1) ? buf1 : buf0;
        float sum = 0.f;
#pragma unroll 4
        for (int i = 0; i < 128; i++)
            sum += __expf(bc[i * FW_PITCH_ + j] + add[i] - mx);
        aj = mx + logf(sum) + g_obs[(b * T_ + s + 1) * SPW_ + j];
        cbs = w2s[(size_t)text[b * T_ + s + 1] * SPW_];
    }

    float m = block_max128(aj, red);
    red[j] = __expf(aj - m);
    __syncthreads();
#pragma unroll
    for (int o = 64; o > 0; o >>= 1) {
        if (j < o) red[j] += red[j + o];
        __syncthreads();
    }
    if (j == 0) out[b] = m + logf(red[0]);
}

// ---------------- launch ----------------------------------------------------------------
extern "C" void kernel_launch(void* const* d_in, const int* in_sizes, int n_in,
                              void* d_out, int out_size) {
    const int*   text       = (const int*)d_in[0];
    const int*   word2state = (const int*)d_in[1];
    const float* start_emb  = (const float*)d_in[2];
    const float* sw1 = (const float*)d_in[3];
    const float* sb1 = (const float*)d_in[4];
    const float* sw2 = (const float*)d_in[5];
    const float* sb2 = (const float*)d_in[6];
    const float* sow = (const float*)d_in[7];
    const float* sob = (const float*)d_in[8];
    const float* state_emb = (const float*)d_in[9];
    const float* tw1 = (const float*)d_in[10];
    const float* tb1 = (const float*)d_in[11];
    const float* tw2 = (const float*)d_in[12];
    const float* tb2 = (const float*)d_in[13];
    const float* next_state_emb  = (const float*)d_in[14];
    const float* preterminal_emb = (const float*)d_in[15];
    const float* ew1 = (const float*)d_in[16];
    const float* eb1 = (const float*)d_in[17];
    const float* ew2 = (const float*)d_in[18];
    const float* eb2 = (const float*)d_in[19];
    const float* proj_w = (const float*)d_in[20];
    const float* proj_b = (const float*)d_in[21];
    float* out = (float*)d_out;

    __nv_bfloat16 *p_semb, *p_stemb, *p_ptemb, *p_h, *p_state, *p_w;
    float *p_rstart, *p_rpre;
    cudaGetSymbolAddress((void**)&p_semb,   g_semb_bf);
    cudaGetSymbolAddress((void**)&p_stemb,  g_stemb_bf);
    cudaGetSymbolAddress((void**)&p_ptemb,  g_ptemb_bf);
    cudaGetSymbolAddress((void**)&p_h,      g_h_bf);
    cudaGetSymbolAddress((void**)&p_state,  g_state_bf);
    cudaGetSymbolAddress((void**)&p_w,      g_wbf);
    cudaGetSymbolAddress((void**)&p_rstart, g_r_start);
    cudaGetSymbolAddress((void**)&p_rpre,   g_r_pre);

    cudaFuncSetAttribute(hgemm_kernel<0>, cudaFuncAttributeMaxDynamicSharedMemorySize, HG_SMEM_);
    cudaFuncSetAttribute(hgemm_kernel<1>, cudaFuncAttributeMaxDynamicSharedMemorySize, HG_SMEM_);
    cudaFuncSetAttribute(rowsum_kernel,   cudaFuncAttributeMaxDynamicSharedMemorySize, HG_SMEM_);
    cudaFuncSetAttribute(blk_kernel,      cudaFuncAttributeMaxDynamicSharedMemorySize, HG_SMEM_);
    cudaFuncSetAttribute(forward_kernel,  cudaFuncAttributeMaxDynamicSharedMemorySize, FW_SMEM_);

    // conversions
    conv_embs<<<(C_ * H_ + 255) / 256, 256>>>(start_emb, state_emb, preterminal_emb, next_state_emb);
    conv_ws<<<(H_ * H_ + 255) / 256, 256>>>(sw1, sw2, tw1, tw2, ew1, ew2);

    // residual MLPs in bf16 HMMA
    dim3 gs(H_ / 128, C_ / 128);
    hgemm_kernel<0><<<gs, 256, HG_SMEM_>>>(p_semb,  p_w + 0 * H_ * H_, sb1, nullptr, nullptr, p_h);
    hgemm_kernel<1><<<gs, 256, HG_SMEM_>>>(p_h,     p_w + 1 * H_ * H_, sb2, start_emb, p_rstart, nullptr);
    hgemm_kernel<0><<<gs, 256, HG_SMEM_>>>(p_stemb, p_w + 2 * H_ * H_, tb1, nullptr, nullptr, p_h);
    hgemm_kernel<1><<<gs, 256, HG_SMEM_>>>(p_h,     p_w + 3 * H_ * H_, tb2, state_emb, nullptr, p_state);
    hgemm_kernel<0><<<gs, 256, HG_SMEM_>>>(p_ptemb, p_w + 4 * H_ * H_, eb1, nullptr, nullptr, p_h);
    hgemm_kernel<1><<<gs, 256, HG_SMEM_>>>(p_h,     p_w + 5 * H_ * H_, eb2, preterminal_emb, p_rpre, nullptr);

    // start distribution
    start_head<<<C_ / 8, 256>>>(sow, sob);
    start_lse_kernel<<<1, 256>>>();

    // transition row-softmax denominators (no logits materialization)
    dim3 gt(C_ / 128, C_ / 128);
    rowsum_kernel<<<gt, 256, HG_SMEM_>>>();
    row_lse_final_kernel<<<C_ / 256, 256>>>();

    // per-(b,t) transition blocks (32 MB, L2-resident)
    blk_kernel<<<NP_, 256, HG_SMEM_>>>(text, word2state);

    // emission (sparse path)
    zero_counts<<<1, 64>>>();
    build_lists<<<(V_ + 255) / 256, 256>>>(word2state);
    emis_lse_kernel<<<C_, 256>>>(proj_w, proj_b);
    obs_kernel<<<B_ * T_, 256>>>(text, word2state, proj_w, proj_b);

    // forward algorithm
    forward_kernel<<<B_, 128, FW_SMEM_>>>(text, word2state, out);
}

// round 5
// speedup vs baseline: 5.1675x; 1.5939x over previous
#include <cuda_runtime.h>
#include <cuda_bf16.h>
#include <math.h>
#include <stdint.h>

#define V_  10000
#define C_  8192
#define NC_ 64
#define SPW_ 128
#define H_  256
#define B_  16
#define T_  33
#define MAXW_ 1024
#define NP_  (B_ * (T_ - 1))     // 512 transition blocks

// ---------------- scratch (device globals; no allocation allowed) ----------------
__device__ __align__(16) float g_r_start[C_ * H_];
__device__ __align__(16) __nv_bfloat16 g_h_unused[16];
__device__ __align__(16) __nv_bfloat16 g_semb_bf[C_ * H_];
__device__ __align__(16) __nv_bfloat16 g_stemb_bf[C_ * H_];
__device__ __align__(16) __nv_bfloat16 g_ptemb_bf[C_ * H_];
__device__ __align__(16) __nv_bfloat16 g_next_bf[C_ * H_];
__device__ __align__(16) __nv_bfloat16 g_state_bf[C_ * H_];
__device__ __align__(16) __nv_bfloat16 g_rpre_bf[C_ * H_];
__device__ __align__(16) __nv_bfloat16 g_projw_bf[V_ * H_];
__device__ __align__(16) __nv_bfloat16 g_wbf[6 * H_ * H_];      // sw1,sw2,tw1,tw2,ew1,ew2
__device__ __align__(16) float g_blk[(size_t)NP_ * SPW_ * SPW_];   // 32 MB
__device__ __align__(16) float g_elog[(size_t)NC_ * SPW_ * MAXW_]; // 33.5 MB
__device__ __align__(16) float g_rowsum_part[8 * C_];
__device__ float g_row_lse[C_];
__device__ float g_start_s[C_];
__device__ float g_start_lse_v;
__device__ float g_else[C_];
__device__ float g_obs[B_ * T_ * SPW_];
__device__ int   g_cl_words[NC_ * MAXW_];
__device__ int   g_cl_cnt[NC_];
__device__ int   g_word_pos[V_];

__device__ __forceinline__ uint32_t smem_u32(const void* p) {
    uint32_t a;
    asm("{ .reg .u64 t; cvta.to.shared.u64 t, %1; cvt.u32.u64 %0, t; }" : "=r"(a) : "l"(p));
    return a;
}

// ======================================================================================
// HMMA tile machinery: 128x128 output, K=256 SMEM-resident, 8 warps (2M x 4N)
// ======================================================================================
#define LDA_ 264
#define TILE_BYTES_ (128 * LDA_ * 2)            // 67584 per tile
#define HG2_SMEM_ (2 * TILE_BYTES_)             // 135168
#define HG3_SMEM_ (3 * TILE_BYTES_)             // 202752

__device__ __forceinline__ void load_tile(__nv_bfloat16* dst, const __nv_bfloat16* src, int tid) {
    int row  = tid >> 1;
    int half = tid & 1;
    const uint4* g = reinterpret_cast<const uint4*>(src + (size_t)row * H_ + half * 128);
    uint4* s = reinterpret_cast<uint4*>(dst + row * LDA_ + half * 128);
#pragma unroll
    for (int i = 0; i < 16; i++) s[i] = g[i];
}

// async tile load (caller commits group)
__device__ __forceinline__ void cp_tile(__nv_bfloat16* dst, const __nv_bfloat16* src, int tid) {
    int row  = tid >> 1;
    int half = tid & 1;
    const char* g = reinterpret_cast<const char*>(src + (size_t)row * H_ + half * 128);
    uint32_t s = smem_u32(dst + row * LDA_ + half * 128);
#pragma unroll
    for (int i = 0; i < 16; i++)
        asm volatile("cp.async.cg.shared.global [%0], [%1], 16;" :: "r"(s + i * 16), "l"(g + i * 16) : "memory");
}

__device__ __forceinline__ void mma_mainloop(const __nv_bfloat16* As, const __nv_bfloat16* Bs,
                                             int wm, int wn, int lane, float acc[4][4][4]) {
    uint32_t a_base = smem_u32(As) + (((wm * 64 + (lane & 15)) * LDA_ + (lane >> 4) * 8) << 1);
    uint32_t b_base = smem_u32(Bs) + (((wn * 32 + (lane & 7)) * LDA_ + ((lane >> 3) & 1) * 8) << 1);
#pragma unroll
    for (int k = 0; k < 16; k++) {
        uint32_t a[4][4], b[4][2];
#pragma unroll
        for (int mi = 0; mi < 4; mi++) {
            uint32_t addr = a_base + ((mi * 16 * LDA_ + k * 16) << 1);
            asm volatile("ldmatrix.sync.aligned.m8n8.x4.shared.b16 {%0,%1,%2,%3}, [%4];"
                         : "=r"(a[mi][0]), "=r"(a[mi][1]), "=r"(a[mi][2]), "=r"(a[mi][3])
                         : "r"(addr));
        }
#pragma unroll
        for (int nf = 0; nf < 4; nf++) {
            uint32_t addr = b_base + ((nf * 8 * LDA_ + k * 16) << 1);
            asm volatile("ldmatrix.sync.aligned.m8n8.x2.shared.b16 {%0,%1}, [%2];"
                         : "=r"(b[nf][0]), "=r"(b[nf][1])
                         : "r"(addr));
        }
#pragma unroll
        for (int mi = 0; mi < 4; mi++)
#pragma unroll
            for (int nf = 0; nf < 4; nf++) {
                asm volatile(
                    "mma.sync.aligned.m16n8k16.row.col.f32.bf16.bf16.f32 "
                    "{%0,%1,%2,%3}, {%4,%5,%6,%7}, {%8,%9}, {%0,%1,%2,%3};"
                    : "+f"(acc[mi][nf][0]), "+f"(acc[mi][nf][1]),
                      "+f"(acc[mi][nf][2]), "+f"(acc[mi][nf][3])
                    : "r"(a[mi][0]), "r"(a[mi][1]), "r"(a[mi][2]), "r"(a[mi][3]),
                      "r"(b[nf][0]), "r"(b[nf][1]));
            }
    }
}

#define ZERO_ACC(acc) do { \
    _Pragma("unroll") for (int mi = 0; mi < 4; mi++) \
    _Pragma("unroll") for (int nf = 0; nf < 4; nf++) \
    _Pragma("unroll") for (int r = 0; r < 4; r++) acc[mi][nf][r] = 0.f; } while (0)

// ---------------- rowsum strip kernel: 128 x 1024 per CTA, 8 B-tiles pipelined ----------
__global__ void __launch_bounds__(256, 1) rowsum_kernel() {
    extern __shared__ char smem[];
    __nv_bfloat16* As = reinterpret_cast<__nv_bfloat16*>(smem);
    __nv_bfloat16* B0 = reinterpret_cast<__nv_bfloat16*>(smem + TILE_BYTES_);
    __nv_bfloat16* B1 = reinterpret_cast<__nv_bfloat16*>(smem + 2 * TILE_BYTES_);
    __shared__ float rs_sm[4 * 128];

    int tid = threadIdx.x, warp = tid >> 5, lane = tid & 31;
    int wm = warp >> 2, wn = warp & 3;
    int m0 = blockIdx.y * 128;
    int n_base = blockIdx.x * 1024;

    load_tile(As, g_state_bf + (size_t)m0 * H_, tid);
    cp_tile(B0, g_next_bf + (size_t)n_base * H_, tid);
    asm volatile("cp.async.commit_group;" ::: "memory");
    cp_tile(B1, g_next_bf + (size_t)(n_base + 128) * H_, tid);
    asm volatile("cp.async.commit_group;" ::: "memory");

    int qr = lane >> 2, qc = lane & 3;
    float rsum[4][2];
#pragma unroll
    for (int mi = 0; mi < 4; mi++) { rsum[mi][0] = 0.f; rsum[mi][1] = 0.f; }

#pragma unroll
    for (int t = 0; t < 8; t++) {
        if (t < 7) asm volatile("cp.async.wait_group 1;" ::: "memory");
        else       asm volatile("cp.async.wait_group 0;" ::: "memory");
        __syncthreads();
        __nv_bfloat16* Bc = (t & 1) ? B1 : B0;
        float acc[4][4][4];
        ZERO_ACC(acc);
        mma_mainloop(As, Bc, wm, wn, lane, acc);
#pragma unroll
        for (int mi = 0; mi < 4; mi++) {
            float s0 = 0.f, s1 = 0.f;
#pragma unroll
            for (int nf = 0; nf < 4; nf++) {
                s0 += __expf(acc[mi][nf][0]) + __expf(acc[mi][nf][1]);
                s1 += __expf(acc[mi][nf][2]) + __expf(acc[mi][nf][3]);
            }
            rsum[mi][0] += s0;
            rsum[mi][1] += s1;
        }
        __syncthreads();
        if (t + 2 < 8) {
            cp_tile((t & 1) ? B1 : B0, g_next_bf + (size_t)(n_base + (t + 2) * 128) * H_, tid);
            asm volatile("cp.async.commit_group;" ::: "memory");
        }
    }

#pragma unroll
    for (int mi = 0; mi < 4; mi++) {
        float s0 = rsum[mi][0], s1 = rsum[mi][1];
        s0 += __shfl_xor_sync(0xffffffffu, s0, 1);
        s0 += __shfl_xor_sync(0xffffffffu, s0, 2);
        s1 += __shfl_xor_sync(0xffffffffu, s1, 1);
        s1 += __shfl_xor_sync(0xffffffffu, s1, 2);
        if (qc == 0) {
            int rloc = wm * 64 + mi * 16 + qr;
            rs_sm[wn * 128 + rloc]     = s0;
            rs_sm[wn * 128 + rloc + 8] = s1;
        }
    }
    __syncthreads();
    if (tid < 128) {
        float s = rs_sm[tid] + rs_sm[128 + tid] + rs_sm[256 + tid] + rs_sm[384 + tid];
        g_rowsum_part[(size_t)blockIdx.x * C_ + m0 + tid] = s;
    }
}

// ---------------- blk kernel: one 128x128 logits block per (b,t) pair -------------------
__global__ void __launch_bounds__(256, 1) blk_kernel(const int* __restrict__ text,
                                                     const int* __restrict__ w2s) {
    extern __shared__ char smem[];
    __nv_bfloat16* As = reinterpret_cast<__nv_bfloat16*>(smem);
    __nv_bfloat16* Bs = reinterpret_cast<__nv_bfloat16*>(smem + TILE_BYTES_);

    int tid = threadIdx.x, warp = tid >> 5, lane = tid & 31;
    int wm = warp >> 2, wn = warp & 3;
    int p = blockIdx.x;
    int b = p >> 5, s = p & 31;
    int cp = w2s[(size_t)text[b * T_ + s]     * SPW_];
    int cn = w2s[(size_t)text[b * T_ + s + 1] * SPW_];

    load_tile(As, g_state_bf + (size_t)cp * H_, tid);
    load_tile(Bs, g_next_bf  + (size_t)cn * H_, tid);
    __syncthreads();

    float acc[4][4][4];
    ZERO_ACC(acc);
    mma_mainloop(As, Bs, wm, wn, lane, acc);

    int qr = lane >> 2, qc = lane & 3;
    float* out = g_blk + (size_t)p * (SPW_ * SPW_);
#pragma unroll
    for (int mi = 0; mi < 4; mi++) {
        int rloc0 = wm * 64 + mi * 16 + qr;
        float* row0 = out + rloc0 * SPW_ + wn * 32 + qc * 2;
        float* row1 = row0 + 8 * SPW_;
#pragma unroll
        for (int nf = 0; nf < 4; nf++) {
            *reinterpret_cast<float2*>(row0 + nf * 8) = make_float2(acc[mi][nf][0], acc[mi][nf][1]);
            *reinterpret_cast<float2*>(row1 + nf * 8) = make_float2(acc[mi][nf][2], acc[mi][nf][3]);
        }
    }
}

// ---------------- fused residual MLP: one CTA = 128 rows, both layers -------------------
// out = relu( relu(A@W1^T+b1) @ W2^T + b2 ) + res ; write fp32 (outF) and/or bf16 (outB)
__global__ void __launch_bounds__(256, 1) mlp_kernel(
    const __nv_bfloat16* __restrict__ A, const __nv_bfloat16* __restrict__ W1,
    const float* __restrict__ b1, const __nv_bfloat16* __restrict__ W2,
    const float* __restrict__ b2, const float* __restrict__ res,
    float* __restrict__ outF, __nv_bfloat16* __restrict__ outB) {
    extern __shared__ char smem[];
    __nv_bfloat16* bufA = reinterpret_cast<__nv_bfloat16*>(smem);
    __nv_bfloat16* bufB = reinterpret_cast<__nv_bfloat16*>(smem + TILE_BYTES_);
    __nv_bfloat16* bufH = reinterpret_cast<__nv_bfloat16*>(smem + 2 * TILE_BYTES_);

    int tid = threadIdx.x, warp = tid >> 5, lane = tid & 31;
    int wm = warp >> 2, wn = warp & 3;
    int m0 = blockIdx.x * 128;
    int qr = lane >> 2, qc = lane & 3;

    load_tile(bufA, A + (size_t)m0 * H_, tid);

    // ---- layer 1: hidden = relu(A @ W1^T + b1), kept bf16 in bufH ----
#pragma unroll
    for (int h = 0; h < 2; h++) {
        __syncthreads();
        load_tile(bufB, W1 + (size_t)(h * 128) * H_, tid);
        __syncthreads();
        float acc[4][4][4];
        ZERO_ACC(acc);
        mma_mainloop(bufA, bufB, wm, wn, lane, acc);
#pragma unroll
        for (int mi = 0; mi < 4; mi++) {
            int r0 = wm * 64 + mi * 16 + qr;
#pragma unroll
            for (int nf = 0; nf < 4; nf++) {
                int c = wn * 32 + nf * 8 + qc * 2;
                float bb0 = b1[h * 128 + c], bb1 = b1[h * 128 + c + 1];
                __nv_bfloat162 h0 = __floats2bfloat162_rn(fmaxf(acc[mi][nf][0] + bb0, 0.f),
                                                          fmaxf(acc[mi][nf][1] + bb1, 0.f));
                __nv_bfloat162 h1 = __floats2bfloat162_rn(fmaxf(acc[mi][nf][2] + bb0, 0.f),
                                                          fmaxf(acc[mi][nf][3] + bb1, 0.f));
                *reinterpret_cast<__nv_bfloat162*>(bufH + (size_t)r0 * LDA_ + h * 128 + c) = h0;
                *reinterpret_cast<__nv_bfloat162*>(bufH + (size_t)(r0 + 8) * LDA_ + h * 128 + c) = h1;
            }
        }
    }

    // ---- layer 2: out = relu(H @ W2^T + b2) + res ----
#pragma unroll
    for (int h = 0; h < 2; h++) {
        __syncthreads();
        load_tile(bufB, W2 + (size_t)(h * 128) * H_, tid);
        __syncthreads();
        float acc[4][4][4];
        ZERO_ACC(acc);
        mma_mainloop(bufH, bufB, wm, wn, lane, acc);
#pragma unroll
        for (int mi = 0; mi < 4; mi++) {
            int r0 = m0 + wm * 64 + mi * 16 + qr;
            int r1 = r0 + 8;
#pragma unroll
            for (int nf = 0; nf < 4; nf++) {
                int c = h * 128 + wn * 32 + nf * 8 + qc * 2;
                float bb0 = b2[c], bb1 = b2[c + 1];
                float v00 = fmaxf(acc[mi][nf][0] + bb0, 0.f);
                float v01 = fmaxf(acc[mi][nf][1] + bb1, 0.f);
                float v10 = fmaxf(acc[mi][nf][2] + bb0, 0.f);
                float v11 = fmaxf(acc[mi][nf][3] + bb1, 0.f);
                float2 x0 = *reinterpret_cast<const float2*>(res + (size_t)r0 * H_ + c);
                float2 x1 = *reinterpret_cast<const float2*>(res + (size_t)r1 * H_ + c);
                v00 += x0.x; v01 += x0.y; v10 += x1.x; v11 += x1.y;
                if (outF) {
                    *reinterpret_cast<float2*>(outF + (size_t)r0 * H_ + c) = make_float2(v00, v01);
                    *reinterpret_cast<float2*>(outF + (size_t)r1 * H_ + c) = make_float2(v10, v11);
                }
                if (outB) {
                    *reinterpret_cast<__nv_bfloat162*>(outB + (size_t)r0 * H_ + c) = __floats2bfloat162_rn(v00, v01);
                    *reinterpret_cast<__nv_bfloat162*>(outB + (size_t)r1 * H_ + c) = __floats2bfloat162_rn(v10, v11);
                }
            }
        }
    }
}

// ---------------- conversions ---------------------------------------------------------
__global__ void conv_embs(const float* __restrict__ a, const float* __restrict__ b,
                          const float* __restrict__ c, const float* __restrict__ d) {
    int i = blockIdx.x * blockDim.x + threadIdx.x;
    if (i < C_ * H_) {
        g_semb_bf[i]  = __float2bfloat16_rn(a[i]);
        g_stemb_bf[i] = __float2bfloat16_rn(b[i]);
        g_ptemb_bf[i] = __float2bfloat16_rn(c[i]);
        g_next_bf[i]  = __float2bfloat16_rn(d[i]);
    }
}
__global__ void conv_ws(const float* __restrict__ w0, const float* __restrict__ w1,
                        const float* __restrict__ w2, const float* __restrict__ w3,
                        const float* __restrict__ w4, const float* __restrict__ w5) {
    int i = blockIdx.x * blockDim.x + threadIdx.x;
    if (i < H_ * H_) {
        g_wbf[0 * H_ * H_ + i] = __float2bfloat16_rn(w0[i]);
        g_wbf[1 * H_ * H_ + i] = __float2bfloat16_rn(w1[i]);
        g_wbf[2 * H_ * H_ + i] = __float2bfloat16_rn(w2[i]);
        g_wbf[3 * H_ * H_ + i] = __float2bfloat16_rn(w3[i]);
        g_wbf[4 * H_ * H_ + i] = __float2bfloat16_rn(w4[i]);
        g_wbf[5 * H_ * H_ + i] = __float2bfloat16_rn(w5[i]);
    }
}
__global__ void conv_projw(const float* __restrict__ pw) {
    int i = blockIdx.x * blockDim.x + threadIdx.x;
    if (i < V_ * H_) g_projw_bf[i] = __float2bfloat16_rn(pw[i]);
}

// ---------------- row lse from partial sums ------------------------------------------
__global__ void row_lse_final_kernel() {
    int c = blockIdx.x * blockDim.x + threadIdx.x;
    if (c >= C_) return;
    float s = 0.f;
#pragma unroll
    for (int p = 0; p < 8; p++) s += g_rowsum_part[(size_t)p * C_ + c];
    g_row_lse[c] = logf(s);
}

// ---------------- start head ----------------------------------------------------------
__global__ void start_head(const float* __restrict__ sow, const float* __restrict__ sob) {
    int gw   = (blockIdx.x * blockDim.x + threadIdx.x) >> 5;
    int lane = threadIdx.x & 31;
    if (gw >= C_) return;
    float acc = 0.f;
#pragma unroll
    for (int q = 0; q < 8; q++)
        acc += g_r_start[(size_t)gw * H_ + lane + 32 * q] * sow[lane + 32 * q];
#pragma unroll
    for (int o = 16; o > 0; o >>= 1) acc += __shfl_xor_sync(0xffffffffu, acc, o);
    if (lane == 0) g_start_s[gw] = acc + sob[0];
}

__global__ void start_lse_kernel() {
    int tid = threadIdx.x;
    float m = -INFINITY, s = 0.f;
    for (int c = tid; c < C_; c += 256) {
        float x  = g_start_s[c];
        float nm = fmaxf(m, x);
        s = s * __expf(m - nm) + __expf(x - nm);
        m = nm;
    }
    __shared__ float sm[256], ss[256];
    sm[tid] = m; ss[tid] = s;
    __syncthreads();
    for (int o = 128; o > 0; o >>= 1) {
        if (tid < o) {
            float m2 = sm[tid + o], s2 = ss[tid + o];
            float nm = fmaxf(sm[tid], m2);
            ss[tid] = ss[tid] * __expf(sm[tid] - nm) + s2 * __expf(m2 - nm);
            sm[tid] = nm;
        }
        __syncthreads();
    }
    if (tid == 0) g_start_lse_v = sm[0] + logf(ss[0]);
}

// ---------------- deterministic cluster lists (block-wide scan per cluster) ------------
__global__ void build_lists2(const int* __restrict__ w2s) {
    int k = blockIdx.x;
    int tid = threadIdx.x, lane = tid & 31, wp = tid >> 5;
    __shared__ int warpcnt[8];
    __shared__ int base;
    if (tid == 0) base = 0;
    __syncthreads();
    for (int w0 = 0; w0 < V_; w0 += 256) {
        int w = w0 + tid;
        bool m = (w < V_) && ((w2s[(size_t)w * SPW_] >> 7) == k);
        unsigned bal = __ballot_sync(0xffffffffu, m);
        if (lane == 0) warpcnt[wp] = __popc(bal);
        __syncthreads();
        int wbase = 0;
#pragma unroll
        for (int i = 0; i < 8; i++) wbase += (i < wp) ? warpcnt[i] : 0;
        int pre = __popc(bal & ((1u << lane) - 1u));
        if (m) {
            int p = base + wbase + pre;
            if (p < MAXW_) { g_cl_words[k * MAXW_ + p] = w; g_word_pos[w] = p; }
        }
        __syncthreads();
        if (tid == 0) {
            int tot = 0;
#pragma unroll
            for (int i = 0; i < 8; i++) tot += warpcnt[i];
            base += tot;
        }
        __syncthreads();
    }
    if (tid == 0) g_cl_cnt[k] = base;
}

// ---------------- emission: per-cluster HMMA logits + row exp-sums ---------------------
__device__ __forceinline__ void gather_tile(__nv_bfloat16* dst, const int* __restrict__ words,
                                            int basei, int cnt, int tid) {
    int row  = tid >> 1;
    int half = tid & 1;
    uint4* s = reinterpret_cast<uint4*>(dst + row * LDA_ + half * 128);
    int idx = basei + row;
    if (idx < cnt) {
        const uint4* g = reinterpret_cast<const uint4*>(g_projw_bf + (size_t)words[idx] * H_ + half * 128);
#pragma unroll
        for (int i = 0; i < 16; i++) s[i] = g[i];
    } else {
        uint4 z = make_uint4(0, 0, 0, 0);
#pragma unroll
        for (int i = 0; i < 16; i++) s[i] = z;
    }
}

__global__ void __launch_bounds__(256, 1) emis_kernel(const float* __restrict__ proj_b) {
    extern __shared__ char smem[];
    __nv_bfloat16* As = reinterpret_cast<__nv_bfloat16*>(smem);
    __nv_bfloat16* Bs = reinterpret_cast<__nv_bfloat16*>(smem + TILE_BYTES_);
    __shared__ float rs_sm[4 * 128];

    int tid = threadIdx.x, warp = tid >> 5, lane = tid & 31;
    int wm = warp >> 2, wn = warp & 3;
    int k = blockIdx.x;
    int cnt = g_cl_cnt[k];
    const int* words = &g_cl_words[k * MAXW_];
    int qr = lane >> 2, qc = lane & 3;

    load_tile(As, g_rpre_bf + (size_t)(k * 128) * H_, tid);

    float rsum[4][2];
#pragma unroll
    for (int mi = 0; mi < 4; mi++) { rsum[mi][0] = 0.f; rsum[mi][1] = 0.f; }

    int nch = (cnt + 127) >> 7;
    for (int ch = 0; ch < nch; ch++) {
        __syncthreads();
        gather_tile(Bs, words, ch * 128, cnt, tid);
        __syncthreads();
        float acc[4][4][4];
        ZERO_ACC(acc);
        mma_mainloop(As, Bs, wm, wn, lane, acc);
#pragma unroll
        for (int mi = 0; mi < 4; mi++) {
            int r0 = wm * 64 + mi * 16 + qr;
            float* er0 = g_elog + ((size_t)(k * 128 + r0) * MAXW_);
            float* er1 = g_elog + ((size_t)(k * 128 + r0 + 8) * MAXW_);
#pragma unroll
            for (int nf = 0; nf < 4; nf++) {
                int n = ch * 128 + wn * 32 + nf * 8 + qc * 2;
                if (n < cnt) {
                    float bb = proj_b[words[n]];
                    float v0 = acc[mi][nf][0] + bb;
                    float v2 = acc[mi][nf][2] + bb;
                    er0[n] = v0; er1[n] = v2;
                    rsum[mi][0] += __expf(v0);
                    rsum[mi][1] += __expf(v2);
                }
                if (n + 1 < cnt) {
                    float bb = proj_b[words[n + 1]];
                    float v1 = acc[mi][nf][1] + bb;
                    float v3 = acc[mi][nf][3] + bb;
                    er0[n + 1] = v1; er1[n + 1] = v3;
                    rsum[mi][0] += __expf(v1);
                    rsum[mi][1] += __expf(v3);
                }
            }
        }
    }

#pragma unroll
    for (int mi = 0; mi < 4; mi++) {
        float s0 = rsum[mi][0], s1 = rsum[mi][1];
        s0 += __shfl_xor_sync(0xffffffffu, s0, 1);
        s0 += __shfl_xor_sync(0xffffffffu, s0, 2);
        s1 += __shfl_xor_sync(0xffffffffu, s1, 1);
        s1 += __shfl_xor_sync(0xffffffffu, s1, 2);
        if (qc == 0) {
            int rloc = wm * 64 + mi * 16 + qr;
            rs_sm[wn * 128 + rloc]     = s0;
            rs_sm[wn * 128 + rloc + 8] = s1;
        }
    }
    __syncthreads();
    if (tid < 128) {
        float s = rs_sm[tid] + rs_sm[128 + tid] + rs_sm[256 + tid] + rs_sm[384 + tid];
        g_else[k * 128 + tid] = logf(s);
    }
}

// ---------------- obs lookup ------------------------------------------------------------
__global__ void obs_kernel(const int* __restrict__ text, const int* __restrict__ w2s) {
    int bt = blockIdx.x;
    int s  = threadIdx.x;
    int v  = text[bt];
    int cb = w2s[(size_t)v * SPW_];
    int k  = cb >> 7;
    float lg = g_elog[((size_t)(k * 128 + s)) * MAXW_ + g_word_pos[v]];
    g_obs[bt * SPW_ + s] = lg - g_else[cb + s];
}

// ---------------- forward recursion (512 threads, smem-staged blocks) --------------------
#define FW_PITCH_ 132
#define FW_BUF_   (128 * FW_PITCH_)
#define FW_SMEM_  (2 * FW_BUF_ * 4)

__device__ __forceinline__ void fwd_load512(float* buf, const float* __restrict__ src, int t) {
    uint32_t sb = smem_u32(buf);
#pragma unroll
    for (int k = 0; k < 8; k++) {
        int f = k * 512 + t;
        int e = f << 2;
        int i = e >> 7, col = e & 127;
        asm volatile("cp.async.cg.shared.global [%0], [%1], 16;"
                     :: "r"(sb + ((i * FW_PITCH_ + col) << 2)), "l"(src + e) : "memory");
    }
    asm volatile("cp.async.commit_group;" ::: "memory");
}

__global__ void __launch_bounds__(512, 1) forward_kernel(const int* __restrict__ text,
                                                         const int* __restrict__ w2s,
                                                         float* __restrict__ out) {
    extern __shared__ float fsm[];
    __shared__ float add[128], red[128], psum[512];
    int b = blockIdx.x, t = threadIdx.x;
    int j = t & 127, g = t >> 7;
    float* buf0 = fsm;
    float* buf1 = fsm + FW_BUF_;
    const float* blkbase = g_blk + (size_t)b * (T_ - 1) * (SPW_ * SPW_);

    fwd_load512(buf0, blkbase, t);

    int cbs = w2s[(size_t)text[b * T_] * SPW_];
    float aj = g_start_s[cbs + j] - g_start_lse_v + g_obs[(b * T_) * SPW_ + j];

    for (int s = 0; s < T_ - 1; s++) {
        __syncthreads();
        if (g == 0) add[j] = aj - g_row_lse[cbs + j];
        asm volatile("cp.async.wait_group 0;" ::: "memory");
        __syncthreads();
        if (s + 1 < T_ - 1)
            fwd_load512((s & 1) ? buf0 : buf1, blkbase + (size_t)(s + 1) * (SPW_ * SPW_), t);

        // max over add[0..127]
        if (t < 64) red[t] = fmaxf(add[t], add[t + 64]);
        __syncthreads();
        if (t < 32) {
            float v = fmaxf(red[t], red[t + 32]);
#pragma unroll
            for (int o = 16; o > 0; o >>= 1) v = fmaxf(v, __shfl_xor_sync(0xffffffffu, v, o));
            if (t == 0) red[0] = v;
        }
        __syncthreads();
        float mx = red[0];

        const float* bc = (s & 1) ? buf1 : buf0;
        float sum = 0.f;
        int i0 = g * 32;
#pragma unroll 8
        for (int i = 0; i < 32; i++)
            sum += __expf(bc[(i0 + i) * FW_PITCH_ + j] + add[i0 + i] - mx);
        psum[t] = sum;
        __syncthreads();
        float tot = psum[j] + psum[j + 128] + psum[j + 256] + psum[j + 384];
        aj = mx + logf(tot) + g_obs[(b * T_ + s + 1) * SPW_ + j];
        cbs = w2s[(size_t)text[b * T_ + s + 1] * SPW_];
    }

    // final LSE over aj (use g==0 copies)
    __syncthreads();
    if (g == 0) add[j] = aj;
    __syncthreads();
    if (t < 64) red[t] = fmaxf(add[t], add[t + 64]);
    __syncthreads();
    if (t < 32) {
        float v = fmaxf(red[t], red[t + 32]);
#pragma unroll
        for (int o = 16; o > 0; o >>= 1) v = fmaxf(v, __shfl_xor_sync(0xffffffffu, v, o));
        if (t == 0) red[0] = v;
    }
    __syncthreads();
    float m = red[0];
    if (t < 64) psum[t] = __expf(add[t] - m) + __expf(add[t + 64] - m);
    __syncthreads();
    if (t < 32) {
        float v = psum[t] + psum[t + 32];
#pragma unroll
        for (int o = 16; o > 0; o >>= 1) v += __shfl_xor_sync(0xffffffffu, v, o);
        if (t == 0) out[b] = m + logf(v);
    }
}

// ---------------- launch ----------------------------------------------------------------
extern "C" void kernel_launch(void* const* d_in, const int* in_sizes, int n_in,
                              void* d_out, int out_size) {
    const int*   text       = (const int*)d_in[0];
    const int*   word2state = (const int*)d_in[1];
    const float* start_emb  = (const float*)d_in[2];
    const float* sw1 = (const float*)d_in[3];
    const float* sb1 = (const float*)d_in[4];
    const float* sw2 = (const float*)d_in[5];
    const float* sb2 = (const float*)d_in[6];
    const float* sow = (const float*)d_in[7];
    const float* sob = (const float*)d_in[8];
    const float* state_emb = (const float*)d_in[9];
    const float* tw1 = (const float*)d_in[10];
    const float* tb1 = (const float*)d_in[11];
    const float* tw2 = (const float*)d_in[12];
    const float* tb2 = (const float*)d_in[13];
    const float* next_state_emb  = (const float*)d_in[14];
    const float* preterminal_emb = (const float*)d_in[15];
    const float* ew1 = (const float*)d_in[16];
    const float* eb1 = (const float*)d_in[17];
    const float* ew2 = (const float*)d_in[18];
    const float* eb2 = (const float*)d_in[19];
    const float* proj_w = (const float*)d_in[20];
    const float* proj_b = (const float*)d_in[21];
    float* out = (float*)d_out;

    __nv_bfloat16 *p_semb, *p_stemb, *p_ptemb, *p_state, *p_rpre, *p_w;
    float *p_rstart;
    cudaGetSymbolAddress((void**)&p_semb,   g_semb_bf);
    cudaGetSymbolAddress((void**)&p_stemb,  g_stemb_bf);
    cudaGetSymbolAddress((void**)&p_ptemb,  g_ptemb_bf);
    cudaGetSymbolAddress((void**)&p_state,  g_state_bf);
    cudaGetSymbolAddress((void**)&p_rpre,   g_rpre_bf);
    cudaGetSymbolAddress((void**)&p_w,      g_wbf);
    cudaGetSymbolAddress((void**)&p_rstart, g_r_start);

    cudaFuncSetAttribute(mlp_kernel,     cudaFuncAttributeMaxDynamicSharedMemorySize, HG3_SMEM_);
    cudaFuncSetAttribute(rowsum_kernel,  cudaFuncAttributeMaxDynamicSharedMemorySize, HG3_SMEM_);
    cudaFuncSetAttribute(blk_kernel,     cudaFuncAttributeMaxDynamicSharedMemorySize, HG2_SMEM_);
    cudaFuncSetAttribute(emis_kernel,    cudaFuncAttributeMaxDynamicSharedMemorySize, HG2_SMEM_);
    cudaFuncSetAttribute(forward_kernel, cudaFuncAttributeMaxDynamicSharedMemorySize, FW_SMEM_);

    // conversions
    conv_embs<<<(C_ * H_ + 255) / 256, 256>>>(start_emb, state_emb, preterminal_emb, next_state_emb);
    conv_ws<<<(H_ * H_ + 255) / 256, 256>>>(sw1, sw2, tw1, tw2, ew1, ew2);
    conv_projw<<<(V_ * H_ + 255) / 256, 256>>>(proj_w);
    build_lists2<<<NC_, 256>>>(word2state);

    // fused residual MLPs
    mlp_kernel<<<C_ / 128, 256, HG3_SMEM_>>>(p_semb,  p_w + 0 * H_ * H_, sb1, p_w + 1 * H_ * H_, sb2,
                                             start_emb, p_rstart, nullptr);
    mlp_kernel<<<C_ / 128, 256, HG3_SMEM_>>>(p_stemb, p_w + 2 * H_ * H_, tb1, p_w + 3 * H_ * H_, tb2,
                                             state_emb, nullptr, p_state);
    mlp_kernel<<<C_ / 128, 256, HG3_SMEM_>>>(p_ptemb, p_w + 4 * H_ * H_, eb1, p_w + 5 * H_ * H_, eb2,
                                             preterminal_emb, nullptr, p_rpre);

    // start distribution
    start_head<<<C_ / 8, 256>>>(sow, sob);
    start_lse_kernel<<<1, 256>>>();

    // transition row-softmax denominators (strips, pipelined, no logits store)
    dim3 gr(8, 64);
    rowsum_kernel<<<gr, 256, HG3_SMEM_>>>();
    row_lse_final_kernel<<<C_ / 256, 256>>>();

    // per-(b,t) transition blocks
    blk_kernel<<<NP_, 256, HG2_SMEM_>>>(text, word2state);

    // emission via per-cluster GEMM + lookup
    emis_kernel<<<NC_, 256, HG2_SMEM_>>>(proj_b);
    obs_kernel<<<B_ * T_, 128>>>(text, word2state);

    // forward algorithm
    forward_kernel<<<B_, 512, FW_SMEM_>>>(text, word2state, out);
}

// round 6
// speedup vs baseline: 5.6207x; 1.0877x over previous
#include <cuda_runtime.h>
#include <cuda_bf16.h>
#include <math.h>
#include <stdint.h>

#define V_  10000
#define C_  8192
#define NC_ 64
#define SPW_ 128
#define H_  256
#define B_  16
#define T_  33
#define MAXW_ 1024
#define NP_  (B_ * (T_ - 1))     // 512 transition blocks

// ---------------- scratch (device globals; no allocation allowed) ----------------
__device__ __align__(16) float g_r_start[C_ * H_];
__device__ __align__(16) __nv_bfloat16 g_semb_bf[C_ * H_];
__device__ __align__(16) __nv_bfloat16 g_stemb_bf[C_ * H_];
__device__ __align__(16) __nv_bfloat16 g_ptemb_bf[C_ * H_];
__device__ __align__(16) __nv_bfloat16 g_next_bf[C_ * H_];
__device__ __align__(16) __nv_bfloat16 g_state_bf[C_ * H_];
__device__ __align__(16) __nv_bfloat16 g_rpre_bf[C_ * H_];
__device__ __align__(16) __nv_bfloat16 g_projw_bf[V_ * H_];
__device__ __align__(16) __nv_bfloat16 g_wbf[6 * H_ * H_];
__device__ __align__(16) float g_blk[(size_t)NP_ * SPW_ * SPW_];   // E' blocks, 32 MB
__device__ __align__(16) float g_elog[(size_t)NC_ * SPW_ * MAXW_];
__device__ __align__(16) float g_rowsum_part[4 * C_];
__device__ float g_rowinv[C_];
__device__ float g_start_s[C_];
__device__ float g_start_lse_v;
__device__ float g_else[C_];
__device__ float g_obs[B_ * T_ * SPW_];
__device__ int   g_cl_words[NC_ * MAXW_];
__device__ int   g_cl_cnt[NC_];
__device__ int   g_word_pos[V_];
__device__ int   g_word_cl[V_];

__device__ __forceinline__ uint32_t smem_u32(const void* p) {
    uint32_t a;
    asm("{ .reg .u64 t; cvta.to.shared.u64 t, %1; cvt.u32.u64 %0, t; }" : "=r"(a) : "l"(p));
    return a;
}

// ======================================================================================
// HMMA tile machinery: 128x128 output, K=256 SMEM-resident, 8 warps (2M x 4N)
// ======================================================================================
#define LDA_ 264
#define TILE_BYTES_ (128 * LDA_ * 2)
#define HG2_SMEM_ (2 * TILE_BYTES_)
#define HG3_SMEM_ (3 * TILE_BYTES_)

__device__ __forceinline__ void load_tile(__nv_bfloat16* dst, const __nv_bfloat16* src, int tid) {
    int row  = tid >> 1;
    int half = tid & 1;
    const uint4* g = reinterpret_cast<const uint4*>(src + (size_t)row * H_ + half * 128);
    uint4* s = reinterpret_cast<uint4*>(dst + row * LDA_ + half * 128);
#pragma unroll
    for (int i = 0; i < 16; i++) s[i] = g[i];
}

__device__ __forceinline__ void cp_tile(__nv_bfloat16* dst, const __nv_bfloat16* src, int tid) {
    int row  = tid >> 1;
    int half = tid & 1;
    const char* g = reinterpret_cast<const char*>(src + (size_t)row * H_ + half * 128);
    uint32_t s = smem_u32(dst + row * LDA_ + half * 128);
#pragma unroll
    for (int i = 0; i < 16; i++)
        asm volatile("cp.async.cg.shared.global [%0], [%1], 16;" :: "r"(s + i * 16), "l"(g + i * 16) : "memory");
}

__device__ __forceinline__ void mma_mainloop(const __nv_bfloat16* As, const __nv_bfloat16* Bs,
                                             int wm, int wn, int lane, float acc[4][4][4]) {
    uint32_t a_base = smem_u32(As) + (((wm * 64 + (lane & 15)) * LDA_ + (lane >> 4) * 8) << 1);
    uint32_t b_base = smem_u32(Bs) + (((wn * 32 + (lane & 7)) * LDA_ + ((lane >> 3) & 1) * 8) << 1);
#pragma unroll
    for (int k = 0; k < 16; k++) {
        uint32_t a[4][4], b[4][2];
#pragma unroll
        for (int mi = 0; mi < 4; mi++) {
            uint32_t addr = a_base + ((mi * 16 * LDA_ + k * 16) << 1);
            asm volatile("ldmatrix.sync.aligned.m8n8.x4.shared.b16 {%0,%1,%2,%3}, [%4];"
                         : "=r"(a[mi][0]), "=r"(a[mi][1]), "=r"(a[mi][2]), "=r"(a[mi][3])
                         : "r"(addr));
        }
#pragma unroll
        for (int nf = 0; nf < 4; nf++) {
            uint32_t addr = b_base + ((nf * 8 * LDA_ + k * 16) << 1);
            asm volatile("ldmatrix.sync.aligned.m8n8.x2.shared.b16 {%0,%1}, [%2];"
                         : "=r"(b[nf][0]), "=r"(b[nf][1])
                         : "r"(addr));
        }
#pragma unroll
        for (int mi = 0; mi < 4; mi++)
#pragma unroll
            for (int nf = 0; nf < 4; nf++) {
                asm volatile(
                    "mma.sync.aligned.m16n8k16.row.col.f32.bf16.bf16.f32 "
                    "{%0,%1,%2,%3}, {%4,%5,%6,%7}, {%8,%9}, {%0,%1,%2,%3};"
                    : "+f"(acc[mi][nf][0]), "+f"(acc[mi][nf][1]),
                      "+f"(acc[mi][nf][2]), "+f"(acc[mi][nf][3])
                    : "r"(a[mi][0]), "r"(a[mi][1]), "r"(a[mi][2]), "r"(a[mi][3]),
                      "r"(b[nf][0]), "r"(b[nf][1]));
            }
    }
}

#define ZERO_ACC(acc) do { \
    _Pragma("unroll") for (int mi = 0; mi < 4; mi++) \
    _Pragma("unroll") for (int nf = 0; nf < 4; nf++) \
    _Pragma("unroll") for (int r = 0; r < 4; r++) acc[mi][nf][r] = 0.f; } while (0)

// ---------------- rowsum strip kernel: 128 x 2048 per CTA, 16 B-tiles pipelined ---------
__global__ void __launch_bounds__(256, 1) rowsum_kernel() {
    extern __shared__ char smem[];
    __nv_bfloat16* As = reinterpret_cast<__nv_bfloat16*>(smem);
    __nv_bfloat16* B0 = reinterpret_cast<__nv_bfloat16*>(smem + TILE_BYTES_);
    __nv_bfloat16* B1 = reinterpret_cast<__nv_bfloat16*>(smem + 2 * TILE_BYTES_);
    __shared__ float rs_sm[4 * 128];

    int tid = threadIdx.x, warp = tid >> 5, lane = tid & 31;
    int wm = warp >> 2, wn = warp & 3;
    int m0 = blockIdx.y * 128;
    int n_base = blockIdx.x * 2048;

    load_tile(As, g_state_bf + (size_t)m0 * H_, tid);
    cp_tile(B0, g_next_bf + (size_t)n_base * H_, tid);
    asm volatile("cp.async.commit_group;" ::: "memory");
    cp_tile(B1, g_next_bf + (size_t)(n_base + 128) * H_, tid);
    asm volatile("cp.async.commit_group;" ::: "memory");

    int qr = lane >> 2, qc = lane & 3;
    float rsum[4][2];
#pragma unroll
    for (int mi = 0; mi < 4; mi++) { rsum[mi][0] = 0.f; rsum[mi][1] = 0.f; }

#pragma unroll
    for (int t = 0; t < 16; t++) {
        if (t < 15) asm volatile("cp.async.wait_group 1;" ::: "memory");
        else        asm volatile("cp.async.wait_group 0;" ::: "memory");
        __syncthreads();
        __nv_bfloat16* Bc = (t & 1) ? B1 : B0;
        float acc[4][4][4];
        ZERO_ACC(acc);
        mma_mainloop(As, Bc, wm, wn, lane, acc);
#pragma unroll
        for (int mi = 0; mi < 4; mi++) {
            float s0 = 0.f, s1 = 0.f;
#pragma unroll
            for (int nf = 0; nf < 4; nf++) {
                s0 += __expf(acc[mi][nf][0]) + __expf(acc[mi][nf][1]);
                s1 += __expf(acc[mi][nf][2]) + __expf(acc[mi][nf][3]);
            }
            rsum[mi][0] += s0;
            rsum[mi][1] += s1;
        }
        __syncthreads();
        if (t + 2 < 16) {
            cp_tile((t & 1) ? B1 : B0, g_next_bf + (size_t)(n_base + (t + 2) * 128) * H_, tid);
            asm volatile("cp.async.commit_group;" ::: "memory");
        }
    }

#pragma unroll
    for (int mi = 0; mi < 4; mi++) {
        float s0 = rsum[mi][0], s1 = rsum[mi][1];
        s0 += __shfl_xor_sync(0xffffffffu, s0, 1);
        s0 += __shfl_xor_sync(0xffffffffu, s0, 2);
        s1 += __shfl_xor_sync(0xffffffffu, s1, 1);
        s1 += __shfl_xor_sync(0xffffffffu, s1, 2);
        if (qc == 0) {
            int rloc = wm * 64 + mi * 16 + qr;
            rs_sm[wn * 128 + rloc]     = s0;
            rs_sm[wn * 128 + rloc + 8] = s1;
        }
    }
    __syncthreads();
    if (tid < 128) {
        float s = rs_sm[tid] + rs_sm[128 + tid] + rs_sm[256 + tid] + rs_sm[384 + tid];
        g_rowsum_part[(size_t)blockIdx.x * C_ + m0 + tid] = s;
    }
}

__global__ void rowinv_kernel() {
    int c = blockIdx.x * blockDim.x + threadIdx.x;
    if (c >= C_) return;
    float s = g_rowsum_part[c] + g_rowsum_part[C_ + c] + g_rowsum_part[2 * C_ + c] + g_rowsum_part[3 * C_ + c];
    g_rowinv[c] = 1.f / s;
}

// ---------------- blk kernel: normalized E' = exp(logit)/rowsum per (b,t) block ---------
__global__ void __launch_bounds__(256, 1) blk_kernel(const int* __restrict__ text,
                                                     const int* __restrict__ w2s) {
    extern __shared__ char smem[];
    __nv_bfloat16* As = reinterpret_cast<__nv_bfloat16*>(smem);
    __nv_bfloat16* Bs = reinterpret_cast<__nv_bfloat16*>(smem + TILE_BYTES_);

    int tid = threadIdx.x, warp = tid >> 5, lane = tid & 31;
    int wm = warp >> 2, wn = warp & 3;
    int p = blockIdx.x;
    int b = p >> 5, s = p & 31;
    int cp = w2s[(size_t)text[b * T_ + s]     * SPW_];
    int cn = w2s[(size_t)text[b * T_ + s + 1] * SPW_];

    load_tile(As, g_state_bf + (size_t)cp * H_, tid);
    load_tile(Bs, g_next_bf  + (size_t)cn * H_, tid);
    __syncthreads();

    float acc[4][4][4];
    ZERO_ACC(acc);
    mma_mainloop(As, Bs, wm, wn, lane, acc);

    int qr = lane >> 2, qc = lane & 3;
    float* out = g_blk + (size_t)p * (SPW_ * SPW_);
#pragma unroll
    for (int mi = 0; mi < 4; mi++) {
        int rloc0 = wm * 64 + mi * 16 + qr;
        float inv0 = g_rowinv[cp + rloc0];
        float inv1 = g_rowinv[cp + rloc0 + 8];
        float* row0 = out + rloc0 * SPW_ + wn * 32 + qc * 2;
        float* row1 = row0 + 8 * SPW_;
#pragma unroll
        for (int nf = 0; nf < 4; nf++) {
            *reinterpret_cast<float2*>(row0 + nf * 8) =
                make_float2(__expf(acc[mi][nf][0]) * inv0, __expf(acc[mi][nf][1]) * inv0);
            *reinterpret_cast<float2*>(row1 + nf * 8) =
                make_float2(__expf(acc[mi][nf][2]) * inv1, __expf(acc[mi][nf][3]) * inv1);
        }
    }
}

// ---------------- fused residual MLPs, all three in one launch --------------------------
struct MlpArgs {
    const __nv_bfloat16* A;
    const __nv_bfloat16* W1;
    const float* b1;
    const __nv_bfloat16* W2;
    const float* b2;
    const float* res;
    float* outF;
    __nv_bfloat16* outB;
};

__global__ void __launch_bounds__(256, 1) mlp3_kernel(MlpArgs a0, MlpArgs a1, MlpArgs a2) {
    extern __shared__ char smem[];
    __nv_bfloat16* bufA = reinterpret_cast<__nv_bfloat16*>(smem);
    __nv_bfloat16* bufB = reinterpret_cast<__nv_bfloat16*>(smem + TILE_BYTES_);
    __nv_bfloat16* bufH = reinterpret_cast<__nv_bfloat16*>(smem + 2 * TILE_BYTES_);

    MlpArgs a = (blockIdx.y == 0) ? a0 : (blockIdx.y == 1) ? a1 : a2;

    int tid = threadIdx.x, warp = tid >> 5, lane = tid & 31;
    int wm = warp >> 2, wn = warp & 3;
    int m0 = blockIdx.x * 128;
    int qr = lane >> 2, qc = lane & 3;

    load_tile(bufA, a.A + (size_t)m0 * H_, tid);

#pragma unroll
    for (int h = 0; h < 2; h++) {
        __syncthreads();
        load_tile(bufB, a.W1 + (size_t)(h * 128) * H_, tid);
        __syncthreads();
        float acc[4][4][4];
        ZERO_ACC(acc);
        mma_mainloop(bufA, bufB, wm, wn, lane, acc);
#pragma unroll
        for (int mi = 0; mi < 4; mi++) {
            int r0 = wm * 64 + mi * 16 + qr;
#pragma unroll
            for (int nf = 0; nf < 4; nf++) {
                int c = wn * 32 + nf * 8 + qc * 2;
                float bb0 = a.b1[h * 128 + c], bb1 = a.b1[h * 128 + c + 1];
                __nv_bfloat162 h0 = __floats2bfloat162_rn(fmaxf(acc[mi][nf][0] + bb0, 0.f),
                                                          fmaxf(acc[mi][nf][1] + bb1, 0.f));
                __nv_bfloat162 h1 = __floats2bfloat162_rn(fmaxf(acc[mi][nf][2] + bb0, 0.f),
                                                          fmaxf(acc[mi][nf][3] + bb1, 0.f));
                *reinterpret_cast<__nv_bfloat162*>(bufH + (size_t)r0 * LDA_ + h * 128 + c) = h0;
                *reinterpret_cast<__nv_bfloat162*>(bufH + (size_t)(r0 + 8) * LDA_ + h * 128 + c) = h1;
            }
        }
    }

#pragma unroll
    for (int h = 0; h < 2; h++) {
        __syncthreads();
        load_tile(bufB, a.W2 + (size_t)(h * 128) * H_, tid);
        __syncthreads();
        float acc[4][4][4];
        ZERO_ACC(acc);
        mma_mainloop(bufH, bufB, wm, wn, lane, acc);
#pragma unroll
        for (int mi = 0; mi < 4; mi++) {
            int r0 = m0 + wm * 64 + mi * 16 + qr;
            int r1 = r0 + 8;
#pragma unroll
            for (int nf = 0; nf < 4; nf++) {
                int c = h * 128 + wn * 32 + nf * 8 + qc * 2;
                float bb0 = a.b2[c], bb1 = a.b2[c + 1];
                float v00 = fmaxf(acc[mi][nf][0] + bb0, 0.f);
                float v01 = fmaxf(acc[mi][nf][1] + bb1, 0.f);
                float v10 = fmaxf(acc[mi][nf][2] + bb0, 0.f);
                float v11 = fmaxf(acc[mi][nf][3] + bb1, 0.f);
                float2 x0 = *reinterpret_cast<const float2*>(a.res + (size_t)r0 * H_ + c);
                float2 x1 = *reinterpret_cast<const float2*>(a.res + (size_t)r1 * H_ + c);
                v00 += x0.x; v01 += x0.y; v10 += x1.x; v11 += x1.y;
                if (a.outF) {
                    *reinterpret_cast<float2*>(a.outF + (size_t)r0 * H_ + c) = make_float2(v00, v01);
                    *reinterpret_cast<float2*>(a.outF + (size_t)r1 * H_ + c) = make_float2(v10, v11);
                }
                if (a.outB) {
                    *reinterpret_cast<__nv_bfloat162*>(a.outB + (size_t)r0 * H_ + c) = __floats2bfloat162_rn(v00, v01);
                    *reinterpret_cast<__nv_bfloat162*>(a.outB + (size_t)r1 * H_ + c) = __floats2bfloat162_rn(v10, v11);
                }
            }
        }
    }
}

// ---------------- one-shot conversions ---------------------------------------------------
__global__ void conv_all(const float* __restrict__ a, const float* __restrict__ b,
                         const float* __restrict__ c, const float* __restrict__ d,
                         const float* __restrict__ w0, const float* __restrict__ w1,
                         const float* __restrict__ w2, const float* __restrict__ w3,
                         const float* __restrict__ w4, const float* __restrict__ w5,
                         const float* __restrict__ pw) {
    int i = blockIdx.x * blockDim.x + threadIdx.x;
    if (i < C_ * H_) {
        g_semb_bf[i]  = __float2bfloat16_rn(a[i]);
        g_stemb_bf[i] = __float2bfloat16_rn(b[i]);
        g_ptemb_bf[i] = __float2bfloat16_rn(c[i]);
        g_next_bf[i]  = __float2bfloat16_rn(d[i]);
    }
    if (i < 6 * H_ * H_) {
        int wi = i / (H_ * H_), r = i % (H_ * H_);
        const float* ws[6] = {w0, w1, w2, w3, w4, w5};
        g_wbf[i] = __float2bfloat16_rn(ws[wi][r]);
    }
    if (i < V_ * H_) g_projw_bf[i] = __float2bfloat16_rn(pw[i]);
}

// ---------------- start head ----------------------------------------------------------
__global__ void start_head(const float* __restrict__ sow, const float* __restrict__ sob) {
    int gw   = (blockIdx.x * blockDim.x + threadIdx.x) >> 5;
    int lane = threadIdx.x & 31;
    if (gw >= C_) return;
    float acc = 0.f;
#pragma unroll
    for (int q = 0; q < 8; q++)
        acc += g_r_start[(size_t)gw * H_ + lane + 32 * q] * sow[lane + 32 * q];
#pragma unroll
    for (int o = 16; o > 0; o >>= 1) acc += __shfl_xor_sync(0xffffffffu, acc, o);
    if (lane == 0) g_start_s[gw] = acc + sob[0];
}

__global__ void start_lse_kernel() {
    int tid = threadIdx.x;
    float m = -INFINITY, s = 0.f;
    for (int c = tid; c < C_; c += 256) {
        float x  = g_start_s[c];
        float nm = fmaxf(m, x);
        s = s * __expf(m - nm) + __expf(x - nm);
        m = nm;
    }
    __shared__ float sm[256], ss[256];
    sm[tid] = m; ss[tid] = s;
    __syncthreads();
    for (int o = 128; o > 0; o >>= 1) {
        if (tid < o) {
            float m2 = sm[tid + o], s2 = ss[tid + o];
            float nm = fmaxf(sm[tid], m2);
            ss[tid] = ss[tid] * __expf(sm[tid] - nm) + s2 * __expf(m2 - nm);
            sm[tid] = nm;
        }
        __syncthreads();
    }
    if (tid == 0) g_start_lse_v = sm[0] + logf(ss[0]);
}

// ---------------- fast cluster lists ----------------------------------------------------
__global__ void word_cl_kernel(const int* __restrict__ w2s) {
    int w = blockIdx.x * blockDim.x + threadIdx.x;
    if (w < V_) g_word_cl[w] = w2s[(size_t)w * SPW_] >> 7;
}

#define WPT_ 40   // words per thread (256*40 >= 10000)
__global__ void build_lists3() {
    int k = blockIdx.x, tid = threadIdx.x;
    int lo = tid * WPT_;
    int hi = min(lo + WPT_, V_);
    int cnt = 0;
    for (int w = lo; w < hi; w++) cnt += (g_word_cl[w] == k);
    __shared__ int sc[256];
    sc[tid] = cnt;
    __syncthreads();
#pragma unroll
    for (int o = 1; o < 256; o <<= 1) {
        int v = (tid >= o) ? sc[tid - o] : 0;
        __syncthreads();
        sc[tid] += v;
        __syncthreads();
    }
    int p = sc[tid] - cnt;
    for (int w = lo; w < hi; w++) {
        if (g_word_cl[w] == k) {
            if (p < MAXW_) { g_cl_words[k * MAXW_ + p] = w; g_word_pos[w] = p; }
            p++;
        }
    }
    if (tid == 255) g_cl_cnt[k] = sc[255];
}

// ---------------- emission: per-cluster HMMA logits + row exp-sums ---------------------
__device__ __forceinline__ void gather_tile(__nv_bfloat16* dst, const int* __restrict__ words,
                                            int basei, int cnt, int tid) {
    int row  = tid >> 1;
    int half = tid & 1;
    uint4* s = reinterpret_cast<uint4*>(dst + row * LDA_ + half * 128);
    int idx = basei + row;
    if (idx < cnt) {
        const uint4* g = reinterpret_cast<const uint4*>(g_projw_bf + (size_t)words[idx] * H_ + half * 128);
#pragma unroll
        for (int i = 0; i < 16; i++) s[i] = g[i];
    } else {
        uint4 z = make_uint4(0, 0, 0, 0);
#pragma unroll
        for (int i = 0; i < 16; i++) s[i] = z;
    }
}

__global__ void __launch_bounds__(256, 1) emis_kernel(const float* __restrict__ proj_b) {
    extern __shared__ char smem[];
    __nv_bfloat16* As = reinterpret_cast<__nv_bfloat16*>(smem);
    __nv_bfloat16* Bs = reinterpret_cast<__nv_bfloat16*>(smem + TILE_BYTES_);
    __shared__ float rs_sm[4 * 128];

    int tid = threadIdx.x, warp = tid >> 5, lane = tid & 31;
    int wm = warp >> 2, wn = warp & 3;
    int k = blockIdx.x;
    int cnt = g_cl_cnt[k];
    const int* words = &g_cl_words[k * MAXW_];
    int qr = lane >> 2, qc = lane & 3;

    load_tile(As, g_rpre_bf + (size_t)(k * 128) * H_, tid);

    float rsum[4][2];
#pragma unroll
    for (int mi = 0; mi < 4; mi++) { rsum[mi][0] = 0.f; rsum[mi][1] = 0.f; }

    int nch = (cnt + 127) >> 7;
    for (int ch = 0; ch < nch; ch++) {
        __syncthreads();
        gather_tile(Bs, words, ch * 128, cnt, tid);
        __syncthreads();
        float acc[4][4][4];
        ZERO_ACC(acc);
        mma_mainloop(As, Bs, wm, wn, lane, acc);
#pragma unroll
        for (int mi = 0; mi < 4; mi++) {
            int r0 = wm * 64 + mi * 16 + qr;
            float* er0 = g_elog + ((size_t)(k * 128 + r0) * MAXW_);
            float* er1 = g_elog + ((size_t)(k * 128 + r0 + 8) * MAXW_);
#pragma unroll
            for (int nf = 0; nf < 4; nf++) {
                int n = ch * 128 + wn * 32 + nf * 8 + qc * 2;
                if (n < cnt) {
                    float bb = proj_b[words[n]];
                    float v0 = acc[mi][nf][0] + bb;
                    float v2 = acc[mi][nf][2] + bb;
                    er0[n] = v0; er1[n] = v2;
                    rsum[mi][0] += __expf(v0);
                    rsum[mi][1] += __expf(v2);
                }
                if (n + 1 < cnt) {
                    float bb = proj_b[words[n + 1]];
                    float v1 = acc[mi][nf][1] + bb;
                    float v3 = acc[mi][nf][3] + bb;
                    er0[n + 1] = v1; er1[n + 1] = v3;
                    rsum[mi][0] += __expf(v1);
                    rsum[mi][1] += __expf(v3);
                }
            }
        }
    }

#pragma unroll
    for (int mi = 0; mi < 4; mi++) {
        float s0 = rsum[mi][0], s1 = rsum[mi][1];
        s0 += __shfl_xor_sync(0xffffffffu, s0, 1);
        s0 += __shfl_xor_sync(0xffffffffu, s0, 2);
        s1 += __shfl_xor_sync(0xffffffffu, s1, 1);
        s1 += __shfl_xor_sync(0xffffffffu, s1, 2);
        if (qc == 0) {
            int rloc = wm * 64 + mi * 16 + qr;
            rs_sm[wn * 128 + rloc]     = s0;
            rs_sm[wn * 128 + rloc + 8] = s1;
        }
    }
    __syncthreads();
    if (tid < 128) {
        float s = rs_sm[tid] + rs_sm[128 + tid] + rs_sm[256 + tid] + rs_sm[384 + tid];
        g_else[k * 128 + tid] = logf(s);
    }
}

// ---------------- obs lookup ------------------------------------------------------------
__global__ void obs_kernel(const int* __restrict__ text, const int* __restrict__ w2s) {
    int bt = blockIdx.x;
    int s  = threadIdx.x;
    int v  = text[bt];
    int cb = w2s[(size_t)v * SPW_];
    int k  = cb >> 7;
    float lg = g_elog[((size_t)(k * 128 + s)) * MAXW_ + g_word_pos[v]];
    g_obs[bt * SPW_ + s] = lg - g_else[cb + s];
}

// ---------------- forward recursion: pure FMA inner loop over E' blocks ------------------
#define FW_PITCH_ 132
#define FW_BUF_   (128 * FW_PITCH_)
#define FW_SMEM_  (2 * FW_BUF_ * 4)

__device__ __forceinline__ void fwd_load512(float* buf, const float* __restrict__ src, int t) {
    uint32_t sb = smem_u32(buf);
#pragma unroll
    for (int k = 0; k < 8; k++) {
        int f = k * 512 + t;
        int e = f << 2;
        int i = e >> 7, col = e & 127;
        asm volatile("cp.async.cg.shared.global [%0], [%1], 16;"
                     :: "r"(sb + ((i * FW_PITCH_ + col) << 2)), "l"(src + e) : "memory");
    }
    asm volatile("cp.async.commit_group;" ::: "memory");
}

__global__ void __launch_bounds__(512, 1) forward_kernel(const int* __restrict__ text,
                                                         const int* __restrict__ w2s,
                                                         float* __restrict__ out) {
    extern __shared__ float fsm[];
    __shared__ float av[128], wv[128], red[128], psum[512];
    int b = blockIdx.x, t = threadIdx.x;
    int j = t & 127, g = t >> 7;
    float* buf0 = fsm;
    float* buf1 = fsm + FW_BUF_;
    const float* blkbase = g_blk + (size_t)b * (T_ - 1) * (SPW_ * SPW_);

    fwd_load512(buf0, blkbase, t);

    int cb0 = w2s[(size_t)text[b * T_] * SPW_];
    float aj = g_start_s[cb0 + j] - g_start_lse_v + g_obs[(b * T_) * SPW_ + j];

    for (int s = 0; s < T_ - 1; s++) {
        __syncthreads();
        if (g == 0) av[j] = aj;
        __syncthreads();
        if (t < 64) red[t] = fmaxf(av[t], av[t + 64]);
        __syncthreads();
        if (t < 32) {
            float v = fmaxf(red[t], red[t + 32]);
#pragma unroll
            for (int o = 16; o > 0; o >>= 1) v = fmaxf(v, __shfl_xor_sync(0xffffffffu, v, o));
            if (t == 0) red[0] = v;
        }
        __syncthreads();
        float mx = red[0];
        if (g == 0) wv[j] = __expf(av[j] - mx);
        asm volatile("cp.async.wait_group 0;" ::: "memory");
        __syncthreads();
        if (s + 1 < T_ - 1)
            fwd_load512((s & 1) ? buf0 : buf1, blkbase + (size_t)(s + 1) * (SPW_ * SPW_), t);

        const float* bc = (s & 1) ? buf1 : buf0;
        float sum = 0.f;
        int i0 = g * 32;
#pragma unroll 8
        for (int i = 0; i < 32; i++)
            sum = fmaf(bc[(i0 + i) * FW_PITCH_ + j], wv[i0 + i], sum);
        psum[t] = sum;
        __syncthreads();
        float tot = psum[j] + psum[j + 128] + psum[j + 256] + psum[j + 384];
        aj = mx + logf(tot) + g_obs[(b * T_ + s + 1) * SPW_ + j];
    }

    __syncthreads();
    if (g == 0) av[j] = aj;
    __syncthreads();
    if (t < 64) red[t] = fmaxf(av[t], av[t + 64]);
    __syncthreads();
    if (t < 32) {
        float v = fmaxf(red[t], red[t + 32]);
#pragma unroll
        for (int o = 16; o > 0; o >>= 1) v = fmaxf(v, __shfl_xor_sync(0xffffffffu, v, o));
        if (t == 0) red[0] = v;
    }
    __syncthreads();
    float m = red[0];
    if (t < 64) psum[t] = __expf(av[t] - m) + __expf(av[t + 64] - m);
    __syncthreads();
    if (t < 32) {
        float v = psum[t] + psum[t + 32];
#pragma unroll
        for (int o = 16; o > 0; o >>= 1) v += __shfl_xor_sync(0xffffffffu, v, o);
        if (t == 0) out[b] = m + logf(v);
    }
}

// ---------------- launch ----------------------------------------------------------------
extern "C" void kernel_launch(void* const* d_in, const int* in_sizes, int n_in,
                              void* d_out, int out_size) {
    const int*   text       = (const int*)d_in[0];
    const int*   word2state = (const int*)d_in[1];
    const float* start_emb  = (const float*)d_in[2];
    const float* sw1 = (const float*)d_in[3];
    const float* sb1 = (const float*)d_in[4];
    const float* sw2 = (const float*)d_in[5];
    const float* sb2 = (const float*)d_in[6];
    const float* sow = (const float*)d_in[7];
    const float* sob = (const float*)d_in[8];
    const float* state_emb = (const float*)d_in[9];
    const float* tw1 = (const float*)d_in[10];
    const float* tb1 = (const float*)d_in[11];
    const float* tw2 = (const float*)d_in[12];
    const float* tb2 = (const float*)d_in[13];
    const float* next_state_emb  = (const float*)d_in[14];
    const float* preterminal_emb = (const float*)d_in[15];
    const float* ew1 = (const float*)d_in[16];
    const float* eb1 = (const float*)d_in[17];
    const float* ew2 = (const float*)d_in[18];
    const float* eb2 = (const float*)d_in[19];
    const float* proj_w = (const float*)d_in[20];
    const float* proj_b = (const float*)d_in[21];
    float* out = (float*)d_out;

    __nv_bfloat16 *p_semb, *p_stemb, *p_ptemb, *p_state, *p_rpre, *p_w;
    float *p_rstart;
    cudaGetSymbolAddress((void**)&p_semb,   g_semb_bf);
    cudaGetSymbolAddress((void**)&p_stemb,  g_stemb_bf);
    cudaGetSymbolAddress((void**)&p_ptemb,  g_ptemb_bf);
    cudaGetSymbolAddress((void**)&p_state,  g_state_bf);
    cudaGetSymbolAddress((void**)&p_rpre,   g_rpre_bf);
    cudaGetSymbolAddress((void**)&p_w,      g_wbf);
    cudaGetSymbolAddress((void**)&p_rstart, g_r_start);

    cudaFuncSetAttribute(mlp3_kernel,    cudaFuncAttributeMaxDynamicSharedMemorySize, HG3_SMEM_);
    cudaFuncSetAttribute(rowsum_kernel,  cudaFuncAttributeMaxDynamicSharedMemorySize, HG3_SMEM_);
    cudaFuncSetAttribute(blk_kernel,     cudaFuncAttributeMaxDynamicSharedMemorySize, HG2_SMEM_);
    cudaFuncSetAttribute(emis_kernel,    cudaFuncAttributeMaxDynamicSharedMemorySize, HG2_SMEM_);
    cudaFuncSetAttribute(forward_kernel, cudaFuncAttributeMaxDynamicSharedMemorySize, FW_SMEM_);

    // conversions + cluster lists
    conv_all<<<(V_ * H_ + 255) / 256, 256>>>(start_emb, state_emb, preterminal_emb, next_state_emb,
                                             sw1, sw2, tw1, tw2, ew1, ew2, proj_w);
    word_cl_kernel<<<(V_ + 255) / 256, 256>>>(word2state);
    build_lists3<<<NC_, 256>>>();

    // fused residual MLPs, one launch
    MlpArgs a0 = {p_semb,  p_w + 0 * H_ * H_, sb1, p_w + 1 * H_ * H_, sb2, start_emb,       p_rstart, nullptr};
    MlpArgs a1 = {p_stemb, p_w + 2 * H_ * H_, tb1, p_w + 3 * H_ * H_, tb2, state_emb,       nullptr,  p_state};
    MlpArgs a2 = {p_ptemb, p_w + 4 * H_ * H_, eb1, p_w + 5 * H_ * H_, eb2, preterminal_emb, nullptr,  p_rpre};
    dim3 gm(C_ / 128, 3);
    mlp3_kernel<<<gm, 256, HG3_SMEM_>>>(a0, a1, a2);

    // start distribution
    start_head<<<C_ / 8, 256>>>(sow, sob);
    start_lse_kernel<<<1, 256>>>();

    // transition row sums -> inverses
    dim3 gr(4, 64);
    rowsum_kernel<<<gr, 256, HG3_SMEM_>>>();
    rowinv_kernel<<<C_ / 256, 256>>>();

    // normalized transition blocks E'
    blk_kernel<<<NP_, 256, HG2_SMEM_>>>(text, word2state);

    // emission via per-cluster GEMM + lookup
    emis_kernel<<<NC_, 256, HG2_SMEM_>>>(proj_b);
    obs_kernel<<<B_ * T_, 128>>>(text, word2state);

    // forward algorithm
    forward_kernel<<<B_, 512, FW_SMEM_>>>(text, word2state, out);
}

// round 7
// speedup vs baseline: 6.1599x; 1.0959x over previous
#include <cuda_runtime.h>
#include <cuda_bf16.h>
#include <math.h>
#include <stdint.h>

#define V_  10000
#define C_  8192
#define NC_ 64
#define SPW_ 128
#define H_  256
#define B_  16
#define T_  33
#define MAXW_ 1024
#define NP_  (B_ * (T_ - 1))
#define LOG2E_ 1.4426950408889634f

// ---------------- scratch ----------------
__device__ __align__(16) float g_r_start[C_ * H_];
__device__ __align__(16) __nv_bfloat16 g_semb_bf[C_ * H_];
__device__ __align__(16) __nv_bfloat16 g_stemb_bf[C_ * H_];
__device__ __align__(16) __nv_bfloat16 g_ptemb_bf[C_ * H_];
__device__ __align__(16) __nv_bfloat16 g_next_bf[C_ * H_];
__device__ __align__(16) __nv_bfloat16 g_state_bf[C_ * H_];   // pre-scaled by log2(e)
__device__ __align__(16) __nv_bfloat16 g_rpre_bf[C_ * H_];
__device__ __align__(16) __nv_bfloat16 g_hid_bf[3 * C_ * H_];
__device__ __align__(16) __nv_bfloat16 g_projw_bf[V_ * H_];
__device__ __align__(16) __nv_bfloat16 g_wbf[6 * H_ * H_];
__device__ __align__(16) float g_blk[(size_t)NP_ * SPW_ * SPW_];   // e^logit blocks
__device__ __align__(16) float g_elog[(size_t)NC_ * SPW_ * MAXW_];
__device__ __align__(16) float g_rowsum_part[4 * C_];
__device__ float g_rowinv[C_];
__device__ float g_start_s[C_];
__device__ float g_start_lse_v;
__device__ float g_else[C_];
__device__ float g_obs[B_ * T_ * SPW_];
__device__ int   g_cl_words[NC_ * MAXW_];
__device__ int   g_cl_cnt[NC_];
__device__ int   g_word_pos[V_];
__device__ int   g_word_cl[V_];

__device__ __forceinline__ uint32_t smem_u32(const void* p) {
    uint32_t a;
    asm("{ .reg .u64 t; cvta.to.shared.u64 t, %1; cvt.u32.u64 %0, t; }" : "=r"(a) : "l"(p));
    return a;
}
__device__ __forceinline__ float ex2f(float x) {
    float r;
    asm("ex2.approx.ftz.f32 %0, %1;" : "=f"(r) : "f"(x));
    return r;
}

// ======================================================================================
// HMMA tile machinery
// ======================================================================================
#define LDA_ 264
#define TILE_BYTES_ (128 * LDA_ * 2)
#define HG2_SMEM_ (2 * TILE_BYTES_)
#define HG3_SMEM_ (3 * TILE_BYTES_)

__device__ __forceinline__ void load_tile(__nv_bfloat16* dst, const __nv_bfloat16* src, int tid) {
    int row  = tid >> 1;
    int half = tid & 1;
    const uint4* g = reinterpret_cast<const uint4*>(src + (size_t)row * H_ + half * 128);
    uint4* s = reinterpret_cast<uint4*>(dst + row * LDA_ + half * 128);
#pragma unroll
    for (int i = 0; i < 16; i++) s[i] = g[i];
}

__device__ __forceinline__ void cp_tile(__nv_bfloat16* dst, const __nv_bfloat16* src, int tid) {
    int row  = tid >> 1;
    int half = tid & 1;
    const char* g = reinterpret_cast<const char*>(src + (size_t)row * H_ + half * 128);
    uint32_t s = smem_u32(dst + row * LDA_ + half * 128);
#pragma unroll
    for (int i = 0; i < 16; i++)
        asm volatile("cp.async.cg.shared.global [%0], [%1], 16;" :: "r"(s + i * 16), "l"(g + i * 16) : "memory");
}

__device__ __forceinline__ void mma_mainloop(const __nv_bfloat16* As, const __nv_bfloat16* Bs,
                                             int wm, int wn, int lane, float acc[4][4][4]) {
    uint32_t a_base = smem_u32(As) + (((wm * 64 + (lane & 15)) * LDA_ + (lane >> 4) * 8) << 1);
    uint32_t b_base = smem_u32(Bs) + (((wn * 32 + ((lane >> 4) * 8) + (lane & 7)) * LDA_ + ((lane >> 3) & 1) * 8) << 1);
#pragma unroll
    for (int k = 0; k < 16; k++) {
        uint32_t a[4][4], b[4][2];
#pragma unroll
        for (int mi = 0; mi < 4; mi++) {
            uint32_t addr = a_base + ((mi * 16 * LDA_ + k * 16) << 1);
            asm volatile("ldmatrix.sync.aligned.m8n8.x4.shared.b16 {%0,%1,%2,%3}, [%4];"
                         : "=r"(a[mi][0]), "=r"(a[mi][1]), "=r"(a[mi][2]), "=r"(a[mi][3])
                         : "r"(addr));
        }
#pragma unroll
        for (int np = 0; np < 2; np++) {
            uint32_t addr = b_base + ((np * 16 * LDA_ + k * 16) << 1);
            asm volatile("ldmatrix.sync.aligned.m8n8.x4.shared.b16 {%0,%1,%2,%3}, [%4];"
                         : "=r"(b[np * 2][0]), "=r"(b[np * 2][1]),
                           "=r"(b[np * 2 + 1][0]), "=r"(b[np * 2 + 1][1])
                         : "r"(addr));
        }
#pragma unroll
        for (int mi = 0; mi < 4; mi++)
#pragma unroll
            for (int nf = 0; nf < 4; nf++) {
                asm volatile(
                    "mma.sync.aligned.m16n8k16.row.col.f32.bf16.bf16.f32 "
                    "{%0,%1,%2,%3}, {%4,%5,%6,%7}, {%8,%9}, {%0,%1,%2,%3};"
                    : "+f"(acc[mi][nf][0]), "+f"(acc[mi][nf][1]),
                      "+f"(acc[mi][nf][2]), "+f"(acc[mi][nf][3])
                    : "r"(a[mi][0]), "r"(a[mi][1]), "r"(a[mi][2]), "r"(a[mi][3]),
                      "r"(b[nf][0]), "r"(b[nf][1]));
            }
    }
}

#define ZERO_ACC(acc) do { \
    _Pragma("unroll") for (int mi = 0; mi < 4; mi++) \
    _Pragma("unroll") for (int nf = 0; nf < 4; nf++) \
    _Pragma("unroll") for (int r = 0; r < 4; r++) acc[mi][nf][r] = 0.f; } while (0)

// ---------------- rowsum strip kernel: 128 x 2048 per CTA (logits in log2 domain) -------
__global__ void __launch_bounds__(256, 1) rowsum_kernel() {
    extern __shared__ char smem[];
    __nv_bfloat16* As = reinterpret_cast<__nv_bfloat16*>(smem);
    __nv_bfloat16* B0 = reinterpret_cast<__nv_bfloat16*>(smem + TILE_BYTES_);
    __nv_bfloat16* B1 = reinterpret_cast<__nv_bfloat16*>(smem + 2 * TILE_BYTES_);
    __shared__ float rs_sm[4 * 128];

    int tid = threadIdx.x, warp = tid >> 5, lane = tid & 31;
    int wm = warp >> 2, wn = warp & 3;
    int m0 = blockIdx.y * 128;
    int n_base = blockIdx.x * 2048;

    load_tile(As, g_state_bf + (size_t)m0 * H_, tid);
    cp_tile(B0, g_next_bf + (size_t)n_base * H_, tid);
    asm volatile("cp.async.commit_group;" ::: "memory");
    cp_tile(B1, g_next_bf + (size_t)(n_base + 128) * H_, tid);
    asm volatile("cp.async.commit_group;" ::: "memory");

    int qr = lane >> 2, qc = lane & 3;
    float rsum[4][2];
#pragma unroll
    for (int mi = 0; mi < 4; mi++) { rsum[mi][0] = 0.f; rsum[mi][1] = 0.f; }

#pragma unroll
    for (int t = 0; t < 16; t++) {
        if (t < 15) asm volatile("cp.async.wait_group 1;" ::: "memory");
        else        asm volatile("cp.async.wait_group 0;" ::: "memory");
        __syncthreads();
        __nv_bfloat16* Bc = (t & 1) ? B1 : B0;
        float acc[4][4][4];
        ZERO_ACC(acc);
        mma_mainloop(As, Bc, wm, wn, lane, acc);
#pragma unroll
        for (int mi = 0; mi < 4; mi++) {
            float s0 = 0.f, s1 = 0.f;
#pragma unroll
            for (int nf = 0; nf < 4; nf++) {
                s0 += ex2f(acc[mi][nf][0]) + ex2f(acc[mi][nf][1]);
                s1 += ex2f(acc[mi][nf][2]) + ex2f(acc[mi][nf][3]);
            }
            rsum[mi][0] += s0;
            rsum[mi][1] += s1;
        }
        __syncthreads();
        if (t + 2 < 16) {
            cp_tile((t & 1) ? B1 : B0, g_next_bf + (size_t)(n_base + (t + 2) * 128) * H_, tid);
            asm volatile("cp.async.commit_group;" ::: "memory");
        }
    }

#pragma unroll
    for (int mi = 0; mi < 4; mi++) {
        float s0 = rsum[mi][0], s1 = rsum[mi][1];
        s0 += __shfl_xor_sync(0xffffffffu, s0, 1);
        s0 += __shfl_xor_sync(0xffffffffu, s0, 2);
        s1 += __shfl_xor_sync(0xffffffffu, s1, 1);
        s1 += __shfl_xor_sync(0xffffffffu, s1, 2);
        if (qc == 0) {
            int rloc = wm * 64 + mi * 16 + qr;
            rs_sm[wn * 128 + rloc]     = s0;
            rs_sm[wn * 128 + rloc + 8] = s1;
        }
    }
    __syncthreads();
    if (tid < 128) {
        float s = rs_sm[tid] + rs_sm[128 + tid] + rs_sm[256 + tid] + rs_sm[384 + tid];
        g_rowsum_part[(size_t)blockIdx.x * C_ + m0 + tid] = s;
    }
}

__global__ void rowinv_kernel() {
    int c = blockIdx.x * blockDim.x + threadIdx.x;
    if (c >= C_) return;
    float s = g_rowsum_part[c] + g_rowsum_part[C_ + c] + g_rowsum_part[2 * C_ + c] + g_rowsum_part[3 * C_ + c];
    g_rowinv[c] = 1.f / s;
}

// ---------------- blk kernel: unnormalized P = e^logit per (b,t) block ------------------
__global__ void __launch_bounds__(256, 1) blk_kernel(const int* __restrict__ text,
                                                     const int* __restrict__ w2s) {
    extern __shared__ char smem[];
    __nv_bfloat16* As = reinterpret_cast<__nv_bfloat16*>(smem);
    __nv_bfloat16* Bs = reinterpret_cast<__nv_bfloat16*>(smem + TILE_BYTES_);

    int tid = threadIdx.x, warp = tid >> 5, lane = tid & 31;
    int wm = warp >> 2, wn = warp & 3;
    int p = blockIdx.x;
    int b = p >> 5, s = p & 31;
    int cp = w2s[(size_t)text[b * T_ + s]     * SPW_];
    int cn = w2s[(size_t)text[b * T_ + s + 1] * SPW_];

    load_tile(As, g_state_bf + (size_t)cp * H_, tid);
    load_tile(Bs, g_next_bf  + (size_t)cn * H_, tid);
    __syncthreads();

    float acc[4][4][4];
    ZERO_ACC(acc);
    mma_mainloop(As, Bs, wm, wn, lane, acc);

    int qr = lane >> 2, qc = lane & 3;
    float* out = g_blk + (size_t)p * (SPW_ * SPW_);
#pragma unroll
    for (int mi = 0; mi < 4; mi++) {
        int rloc0 = wm * 64 + mi * 16 + qr;
        float* row0 = out + rloc0 * SPW_ + wn * 32 + qc * 2;
        float* row1 = row0 + 8 * SPW_;
#pragma unroll
        for (int nf = 0; nf < 4; nf++) {
            *reinterpret_cast<float2*>(row0 + nf * 8) = make_float2(ex2f(acc[mi][nf][0]), ex2f(acc[mi][nf][1]));
            *reinterpret_cast<float2*>(row1 + nf * 8) = make_float2(ex2f(acc[mi][nf][2]), ex2f(acc[mi][nf][3]));
        }
    }
}

// ---------------- MLP layer kernel (3 nets per launch, pipelined W tiles) ----------------
struct L3Args {
    const __nv_bfloat16* A[3];
    const __nv_bfloat16* W[3];
    const float* bias[3];
    const float* res[3];        // null => layer-1 (relu only, bf16 out)
    float* outF[3];
    __nv_bfloat16* outB[3];
    float scale[3];
};

__global__ void __launch_bounds__(256, 1) mlp_layer_kernel(L3Args args) {
    extern __shared__ char smem[];
    __nv_bfloat16* bufA = reinterpret_cast<__nv_bfloat16*>(smem);
    __nv_bfloat16* B0   = reinterpret_cast<__nv_bfloat16*>(smem + TILE_BYTES_);
    __nv_bfloat16* B1   = reinterpret_cast<__nv_bfloat16*>(smem + 2 * TILE_BYTES_);

    int net = blockIdx.y;
    const __nv_bfloat16* A = args.A[net];
    const __nv_bfloat16* W = args.W[net];
    const float* bias = args.bias[net];
    const float* res  = args.res[net];
    float* outF = args.outF[net];
    __nv_bfloat16* outB = args.outB[net];
    float scale = args.scale[net];

    int tid = threadIdx.x, warp = tid >> 5, lane = tid & 31;
    int wm = warp >> 2, wn = warp & 3;
    int m0 = blockIdx.x * 128;
    int qr = lane >> 2, qc = lane & 3;

    cp_tile(bufA, A + (size_t)m0 * H_, tid);
    asm volatile("cp.async.commit_group;" ::: "memory");
    cp_tile(B0, W, tid);
    asm volatile("cp.async.commit_group;" ::: "memory");
    cp_tile(B1, W + (size_t)128 * H_, tid);
    asm volatile("cp.async.commit_group;" ::: "memory");

#pragma unroll
    for (int h = 0; h < 2; h++) {
        if (h == 0) asm volatile("cp.async.wait_group 1;" ::: "memory");
        else        asm volatile("cp.async.wait_group 0;" ::: "memory");
        __syncthreads();
        float acc[4][4][4];
        ZERO_ACC(acc);
        mma_mainloop(bufA, h ? B1 : B0, wm, wn, lane, acc);
#pragma unroll
        for (int mi = 0; mi < 4; mi++) {
            int r0 = m0 + wm * 64 + mi * 16 + qr;
            int r1 = r0 + 8;
#pragma unroll
            for (int nf = 0; nf < 4; nf++) {
                int c = h * 128 + wn * 32 + nf * 8 + qc * 2;
                float bb0 = bias[c], bb1 = bias[c + 1];
                float v00 = fmaxf(acc[mi][nf][0] + bb0, 0.f);
                float v01 = fmaxf(acc[mi][nf][1] + bb1, 0.f);
                float v10 = fmaxf(acc[mi][nf][2] + bb0, 0.f);
                float v11 = fmaxf(acc[mi][nf][3] + bb1, 0.f);
                if (res) {
                    float2 x0 = *reinterpret_cast<const float2*>(res + (size_t)r0 * H_ + c);
                    float2 x1 = *reinterpret_cast<const float2*>(res + (size_t)r1 * H_ + c);
                    v00 = (v00 + x0.x) * scale; v01 = (v01 + x0.y) * scale;
                    v10 = (v10 + x1.x) * scale; v11 = (v11 + x1.y) * scale;
                }
                if (outF) {
                    *reinterpret_cast<float2*>(outF + (size_t)r0 * H_ + c) = make_float2(v00, v01);
                    *reinterpret_cast<float2*>(outF + (size_t)r1 * H_ + c) = make_float2(v10, v11);
                }
                if (outB) {
                    *reinterpret_cast<__nv_bfloat162*>(outB + (size_t)r0 * H_ + c) = __floats2bfloat162_rn(v00, v01);
                    *reinterpret_cast<__nv_bfloat162*>(outB + (size_t)r1 * H_ + c) = __floats2bfloat162_rn(v10, v11);
                }
            }
        }
        __syncthreads();
    }
}

// ---------------- one-shot conversions (+ word_cl) ---------------------------------------
__global__ void conv_all(const float* __restrict__ a, const float* __restrict__ b,
                         const float* __restrict__ c, const float* __restrict__ d,
                         const float* __restrict__ w0, const float* __restrict__ w1,
                         const float* __restrict__ w2, const float* __restrict__ w3,
                         const float* __restrict__ w4, const float* __restrict__ w5,
                         const float* __restrict__ pw, const int* __restrict__ w2s) {
    int i = blockIdx.x * blockDim.x + threadIdx.x;
    if (i < C_ * H_) {
        g_semb_bf[i]  = __float2bfloat16_rn(a[i]);
        g_stemb_bf[i] = __float2bfloat16_rn(b[i]);
        g_ptemb_bf[i] = __float2bfloat16_rn(c[i]);
        g_next_bf[i]  = __float2bfloat16_rn(d[i]);
    }
    if (i < 6 * H_ * H_) {
        int wi = i / (H_ * H_), r = i % (H_ * H_);
        const float* ws[6] = {w0, w1, w2, w3, w4, w5};
        g_wbf[i] = __float2bfloat16_rn(ws[wi][r]);
    }
    if (i < V_ * H_) g_projw_bf[i] = __float2bfloat16_rn(pw[i]);
    if (i < V_) g_word_cl[i] = w2s[(size_t)i * SPW_] >> 7;
}

// ---------------- start head ----------------------------------------------------------
__global__ void start_head(const float* __restrict__ sow, const float* __restrict__ sob) {
    int gw   = (blockIdx.x * blockDim.x + threadIdx.x) >> 5;
    int lane = threadIdx.x & 31;
    if (gw >= C_) return;
    float acc = 0.f;
#pragma unroll
    for (int q = 0; q < 8; q++)
        acc += g_r_start[(size_t)gw * H_ + lane + 32 * q] * sow[lane + 32 * q];
#pragma unroll
    for (int o = 16; o > 0; o >>= 1) acc += __shfl_xor_sync(0xffffffffu, acc, o);
    if (lane == 0) g_start_s[gw] = acc + sob[0];
}

__global__ void start_lse_kernel() {
    int tid = threadIdx.x;
    float m = -INFINITY, s = 0.f;
    for (int c = tid; c < C_; c += 256) {
        float x  = g_start_s[c];
        float nm = fmaxf(m, x);
        s = s * __expf(m - nm) + __expf(x - nm);
        m = nm;
    }
    __shared__ float sm[256], ss[256];
    sm[tid] = m; ss[tid] = s;
    __syncthreads();
    for (int o = 128; o > 0; o >>= 1) {
        if (tid < o) {
            float m2 = sm[tid + o], s2 = ss[tid + o];
            float nm = fmaxf(sm[tid], m2);
            ss[tid] = ss[tid] * __expf(sm[tid] - nm) + s2 * __expf(m2 - nm);
            sm[tid] = nm;
        }
        __syncthreads();
    }
    if (tid == 0) g_start_lse_v = sm[0] + __logf(ss[0]);
}

// ---------------- fast cluster lists ----------------------------------------------------
#define WPT_ 40
__global__ void build_lists3() {
    int k = blockIdx.x, tid = threadIdx.x;
    int lo = tid * WPT_;
    int hi = min(lo + WPT_, V_);
    int cnt = 0;
    for (int w = lo; w < hi; w++) cnt += (g_word_cl[w] == k);
    __shared__ int sc[256];
    sc[tid] = cnt;
    __syncthreads();
#pragma unroll
    for (int o = 1; o < 256; o <<= 1) {
        int v = (tid >= o) ? sc[tid - o] : 0;
        __syncthreads();
        sc[tid] += v;
        __syncthreads();
    }
    int p = sc[tid] - cnt;
    for (int w = lo; w < hi; w++) {
        if (g_word_cl[w] == k) {
            if (p < MAXW_) { g_cl_words[k * MAXW_ + p] = w; g_word_pos[w] = p; }
            p++;
        }
    }
    if (tid == 255) g_cl_cnt[k] = sc[255];
}

// ---------------- emission: per-cluster HMMA logits + row exp-sums ---------------------
__device__ __forceinline__ void gather_tile(__nv_bfloat16* dst, const int* __restrict__ words,
                                            int basei, int cnt, int tid) {
    int row  = tid >> 1;
    int half = tid & 1;
    uint4* s = reinterpret_cast<uint4*>(dst + row * LDA_ + half * 128);
    int idx = basei + row;
    if (idx < cnt) {
        const uint4* g = reinterpret_cast<const uint4*>(g_projw_bf + (size_t)words[idx] * H_ + half * 128);
#pragma unroll
        for (int i = 0; i < 16; i++) s[i] = g[i];
    } else {
        uint4 z = make_uint4(0, 0, 0, 0);
#pragma unroll
        for (int i = 0; i < 16; i++) s[i] = z;
    }
}

__global__ void __launch_bounds__(256, 1) emis_kernel(const float* __restrict__ proj_b) {
    extern __shared__ char smem[];
    __nv_bfloat16* As = reinterpret_cast<__nv_bfloat16*>(smem);
    __nv_bfloat16* Bs = reinterpret_cast<__nv_bfloat16*>(smem + TILE_BYTES_);
    __shared__ float rs_sm[4 * 128];

    int tid = threadIdx.x, warp = tid >> 5, lane = tid & 31;
    int wm = warp >> 2, wn = warp & 3;
    int k = blockIdx.x;
    int cnt = g_cl_cnt[k];
    const int* words = &g_cl_words[k * MAXW_];
    int qr = lane >> 2, qc = lane & 3;

    load_tile(As, g_rpre_bf + (size_t)(k * 128) * H_, tid);

    float rsum[4][2];
#pragma unroll
    for (int mi = 0; mi < 4; mi++) { rsum[mi][0] = 0.f; rsum[mi][1] = 0.f; }

    int nch = (cnt + 127) >> 7;
    for (int ch = 0; ch < nch; ch++) {
        __syncthreads();
        gather_tile(Bs, words, ch * 128, cnt, tid);
        __syncthreads();
        float acc[4][4][4];
        ZERO_ACC(acc);
        mma_mainloop(As, Bs, wm, wn, lane, acc);
#pragma unroll
        for (int mi = 0; mi < 4; mi++) {
            int r0 = wm * 64 + mi * 16 + qr;
            float* er0 = g_elog + ((size_t)(k * 128 + r0) * MAXW_);
            float* er1 = g_elog + ((size_t)(k * 128 + r0 + 8) * MAXW_);
#pragma unroll
            for (int nf = 0; nf < 4; nf++) {
                int n = ch * 128 + wn * 32 + nf * 8 + qc * 2;
                if (n < cnt) {
                    float bb = proj_b[words[n]];
                    float v0 = acc[mi][nf][0] + bb;
                    float v2 = acc[mi][nf][2] + bb;
                    er0[n] = v0; er1[n] = v2;
                    rsum[mi][0] += __expf(v0);
                    rsum[mi][1] += __expf(v2);
                }
                if (n + 1 < cnt) {
                    float bb = proj_b[words[n + 1]];
                    float v1 = acc[mi][nf][1] + bb;
                    float v3 = acc[mi][nf][3] + bb;
                    er0[n + 1] = v1; er1[n + 1] = v3;
                    rsum[mi][0] += __expf(v1);
                    rsum[mi][1] += __expf(v3);
                }
            }
        }
    }

#pragma unroll
    for (int mi = 0; mi < 4; mi++) {
        float s0 = rsum[mi][0], s1 = rsum[mi][1];
        s0 += __shfl_xor_sync(0xffffffffu, s0, 1);
        s0 += __shfl_xor_sync(0xffffffffu, s0, 2);
        s1 += __shfl_xor_sync(0xffffffffu, s1, 1);
        s1 += __shfl_xor_sync(0xffffffffu, s1, 2);
        if (qc == 0) {
            int rloc = wm * 64 + mi * 16 + qr;
            rs_sm[wn * 128 + rloc]     = s0;
            rs_sm[wn * 128 + rloc + 8] = s1;
        }
    }
    __syncthreads();
    if (tid < 128) {
        float s = rs_sm[tid] + rs_sm[128 + tid] + rs_sm[256 + tid] + rs_sm[384 + tid];
        g_else[k * 128 + tid] = __logf(s);
    }
}

// ---------------- obs lookup ------------------------------------------------------------
__global__ void obs_kernel(const int* __restrict__ text, const int* __restrict__ w2s) {
    int bt = blockIdx.x;
    int s  = threadIdx.x;
    int v  = text[bt];
    int cb = w2s[(size_t)v * SPW_];
    int k  = cb >> 7;
    float lg = g_elog[((size_t)(k * 128 + s)) * MAXW_ + g_word_pos[v]];
    g_obs[bt * SPW_ + s] = lg - g_else[cb + s];
}

// ---------------- forward recursion: FMA inner loop over P blocks, inv in weights --------
#define FW_PITCH_ 132
#define FW_BUF_   (128 * FW_PITCH_)
#define FW_SMEM_  (2 * FW_BUF_ * 4)

__device__ __forceinline__ void fwd_load512(float* buf, const float* __restrict__ src, int t) {
    uint32_t sb = smem_u32(buf);
#pragma unroll
    for (int k = 0; k < 8; k++) {
        int f = k * 512 + t;
        int e = f << 2;
        int i = e >> 7, col = e & 127;
        asm volatile("cp.async.cg.shared.global [%0], [%1], 16;"
                     :: "r"(sb + ((i * FW_PITCH_ + col) << 2)), "l"(src + e) : "memory");
    }
    asm volatile("cp.async.commit_group;" ::: "memory");
}

__global__ void __launch_bounds__(512, 1) forward_kernel(const int* __restrict__ text,
                                                         const int* __restrict__ w2s,
                                                         float* __restrict__ out) {
    extern __shared__ float fsm[];
    __shared__ float av[128], wv[128], red[128], psum[512];
    int b = blockIdx.x, t = threadIdx.x;
    int j = t & 127, g = t >> 7;
    float* buf0 = fsm;
    float* buf1 = fsm + FW_BUF_;
    const float* blkbase = g_blk + (size_t)b * (T_ - 1) * (SPW_ * SPW_);

    fwd_load512(buf0, blkbase, t);

    int cbs = w2s[(size_t)text[b * T_] * SPW_];
    float aj = g_start_s[cbs + j] - g_start_lse_v + g_obs[(b * T_) * SPW_ + j];

    for (int s = 0; s < T_ - 1; s++) {
        __syncthreads();
        if (g == 0) av[j] = aj;
        __syncthreads();
        if (t < 64) red[t] = fmaxf(av[t], av[t + 64]);
        __syncthreads();
        if (t < 32) {
            float v = fmaxf(red[t], red[t + 32]);
#pragma unroll
            for (int o = 16; o > 0; o >>= 1) v = fmaxf(v, __shfl_xor_sync(0xffffffffu, v, o));
            if (t == 0) red[0] = v;
        }
        __syncthreads();
        float mx = red[0];
        if (g == 0) wv[j] = __expf(av[j] - mx) * g_rowinv[cbs + j];
        asm volatile("cp.async.wait_group 0;" ::: "memory");
        __syncthreads();
        if (s + 1 < T_ - 1)
            fwd_load512((s & 1) ? buf0 : buf1, blkbase + (size_t)(s + 1) * (SPW_ * SPW_), t);

        const float* bc = (s & 1) ? buf1 : buf0;
        float sum = 0.f;
        int i0 = g * 32;
#pragma unroll 8
        for (int i = 0; i < 32; i++)
            sum = fmaf(bc[(i0 + i) * FW_PITCH_ + j], wv[i0 + i], sum);
        psum[t] = sum;
        __syncthreads();
        float tot = psum[j] + psum[j + 128] + psum[j + 256] + psum[j + 384];
        aj = mx + __logf(tot) + g_obs[(b * T_ + s + 1) * SPW_ + j];
        cbs = w2s[(size_t)text[b * T_ + s + 1] * SPW_];
    }

    __syncthreads();
    if (g == 0) av[j] = aj;
    __syncthreads();
    if (t < 64) red[t] = fmaxf(av[t], av[t + 64]);
    __syncthreads();
    if (t < 32) {
        float v = fmaxf(red[t], red[t + 32]);
#pragma unroll
        for (int o = 16; o > 0; o >>= 1) v = fmaxf(v, __shfl_xor_sync(0xffffffffu, v, o));
        if (t == 0) red[0] = v;
    }
    __syncthreads();
    float m = red[0];
    if (t < 64) psum[t] = __expf(av[t] - m) + __expf(av[t + 64] - m);
    __syncthreads();
    if (t < 32) {
        float v = psum[t] + psum[t + 32];
#pragma unroll
        for (int o = 16; o > 0; o >>= 1) v += __shfl_xor_sync(0xffffffffu, v, o);
        if (t == 0) out[b] = m + __logf(v);
    }
}

// ---------------- launch ----------------------------------------------------------------
extern "C" void kernel_launch(void* const* d_in, const int* in_sizes, int n_in,
                              void* d_out, int out_size) {
    const int*   text       = (const int*)d_in[0];
    const int*   word2state = (const int*)d_in[1];
    const float* start_emb  = (const float*)d_in[2];
    const float* sw1 = (const float*)d_in[3];
    const float* sb1 = (const float*)d_in[4];
    const float* sw2 = (const float*)d_in[5];
    const float* sb2 = (const float*)d_in[6];
    const float* sow = (const float*)d_in[7];
    const float* sob = (const float*)d_in[8];
    const float* state_emb = (const float*)d_in[9];
    const float* tw1 = (const float*)d_in[10];
    const float* tb1 = (const float*)d_in[11];
    const float* tw2 = (const float*)d_in[12];
    const float* tb2 = (const float*)d_in[13];
    const float* next_state_emb  = (const float*)d_in[14];
    const float* preterminal_emb = (const float*)d_in[15];
    const float* ew1 = (const float*)d_in[16];
    const float* eb1 = (const float*)d_in[17];
    const float* ew2 = (const float*)d_in[18];
    const float* eb2 = (const float*)d_in[19];
    const float* proj_w = (const float*)d_in[20];
    const float* proj_b = (const float*)d_in[21];
    float* out = (float*)d_out;

    __nv_bfloat16 *p_semb, *p_stemb, *p_ptemb, *p_state, *p_rpre, *p_w, *p_hid;
    float *p_rstart;
    cudaGetSymbolAddress((void**)&p_semb,   g_semb_bf);
    cudaGetSymbolAddress((void**)&p_stemb,  g_stemb_bf);
    cudaGetSymbolAddress((void**)&p_ptemb,  g_ptemb_bf);
    cudaGetSymbolAddress((void**)&p_state,  g_state_bf);
    cudaGetSymbolAddress((void**)&p_rpre,   g_rpre_bf);
    cudaGetSymbolAddress((void**)&p_w,      g_wbf);
    cudaGetSymbolAddress((void**)&p_hid,    g_hid_bf);
    cudaGetSymbolAddress((void**)&p_rstart, g_r_start);

    cudaFuncSetAttribute(mlp_layer_kernel, cudaFuncAttributeMaxDynamicSharedMemorySize, HG3_SMEM_);
    cudaFuncSetAttribute(rowsum_kernel,    cudaFuncAttributeMaxDynamicSharedMemorySize, HG3_SMEM_);
    cudaFuncSetAttribute(blk_kernel,       cudaFuncAttributeMaxDynamicSharedMemorySize, HG2_SMEM_);
    cudaFuncSetAttribute(emis_kernel,      cudaFuncAttributeMaxDynamicSharedMemorySize, HG2_SMEM_);
    cudaFuncSetAttribute(forward_kernel,   cudaFuncAttributeMaxDynamicSharedMemorySize, FW_SMEM_);

    conv_all<<<(V_ * H_ + 255) / 256, 256>>>(start_emb, state_emb, preterminal_emb, next_state_emb,
                                             sw1, sw2, tw1, tw2, ew1, ew2, proj_w, word2state);
    build_lists3<<<NC_, 256>>>();

    // MLP layer 1 for all 3 nets
    L3Args l1;
    l1.A[0] = p_semb;  l1.A[1] = p_stemb; l1.A[2] = p_ptemb;
    l1.W[0] = p_w;     l1.W[1] = p_w + 2 * H_ * H_; l1.W[2] = p_w + 4 * H_ * H_;
    l1.bias[0] = sb1;  l1.bias[1] = tb1;  l1.bias[2] = eb1;
    l1.res[0] = nullptr; l1.res[1] = nullptr; l1.res[2] = nullptr;
    l1.outF[0] = nullptr; l1.outF[1] = nullptr; l1.outF[2] = nullptr;
    l1.outB[0] = p_hid; l1.outB[1] = p_hid + C_ * H_; l1.outB[2] = p_hid + 2 * C_ * H_;
    l1.scale[0] = 1.f; l1.scale[1] = 1.f; l1.scale[2] = 1.f;
    dim3 gm(C_ / 128, 3);
    mlp_layer_kernel<<<gm, 256, HG3_SMEM_>>>(l1);

    // MLP layer 2 (+ residual); state net pre-scaled by log2(e)
    L3Args l2;
    l2.A[0] = p_hid; l2.A[1] = p_hid + C_ * H_; l2.A[2] = p_hid + 2 * C_ * H_;
    l2.W[0] = p_w + 1 * H_ * H_; l2.W[1] = p_w + 3 * H_ * H_; l2.W[2] = p_w + 5 * H_ * H_;
    l2.bias[0] = sb2; l2.bias[1] = tb2; l2.bias[2] = eb2;
    l2.res[0] = start_emb; l2.res[1] = state_emb; l2.res[2] = preterminal_emb;
    l2.outF[0] = p_rstart; l2.outF[1] = nullptr; l2.outF[2] = nullptr;
    l2.outB[0] = nullptr; l2.outB[1] = p_state; l2.outB[2] = p_rpre;
    l2.scale[0] = 1.f; l2.scale[1] = LOG2E_; l2.scale[2] = 1.f;
    mlp_layer_kernel<<<gm, 256, HG3_SMEM_>>>(l2);

    start_head<<<C_ / 8, 256>>>(sow, sob);
    start_lse_kernel<<<1, 256>>>();

    dim3 gr(4, 64);
    rowsum_kernel<<<gr, 256, HG3_SMEM_>>>();
    rowinv_kernel<<<C_ / 256, 256>>>();

    blk_kernel<<<NP_, 256, HG2_SMEM_>>>(text, word2state);

    emis_kernel<<<NC_, 256, HG2_SMEM_>>>(proj_b);
    obs_kernel<<<B_ * T_, 128>>>(text, word2state);

    forward_kernel<<<B_, 512, FW_SMEM_>>>(text, word2state, out);
}

// round 8
// speedup vs baseline: 6.6933x; 1.0866x over previous
#include <cuda_runtime.h>
#include <cuda_bf16.h>
#include <math.h>
#include <stdint.h>

#define V_  10000
#define C_  8192
#define NC_ 64
#define SPW_ 128
#define H_  256
#define B_  16
#define T_  33
#define MAXW_ 1024
#define NP_  (B_ * (T_ - 1))
#define LOG2E_ 1.4426950408889634f
#define SLOT_NONE_ 0x7fffffff

// ---------------- scratch ----------------
__device__ __align__(16) float g_r_start[C_ * H_];
__device__ __align__(16) __nv_bfloat16 g_semb_bf[C_ * H_];
__device__ __align__(16) __nv_bfloat16 g_stemb_bf[C_ * H_];
__device__ __align__(16) __nv_bfloat16 g_ptemb_bf[C_ * H_];
__device__ __align__(16) __nv_bfloat16 g_next_bf[C_ * H_];
__device__ __align__(16) __nv_bfloat16 g_state_bf[C_ * H_];   // pre-scaled by log2(e)
__device__ __align__(16) __nv_bfloat16 g_rpre_bf[C_ * H_];
__device__ __align__(16) __nv_bfloat16 g_hid_bf[3 * C_ * H_];
__device__ __align__(16) __nv_bfloat16 g_projw_bf[V_ * H_];
__device__ __align__(16) __nv_bfloat16 g_wbf[6 * H_ * H_];
__device__ __align__(16) float g_blk[(size_t)NP_ * SPW_ * SPW_];
__device__ __align__(16) float g_elog[(size_t)NC_ * SPW_ * MAXW_];
__device__ __align__(16) float g_rowsum_part[4 * C_];
__device__ float g_rowinv[C_];
__device__ float g_start_s[C_];
__device__ float g_start_lse_v;
__device__ float g_else[C_];
__device__ float g_obs[B_ * T_ * SPW_];
__device__ int   g_cl_words[NC_ * MAXW_];
__device__ int   g_cl_cnt[NC_];
__device__ int   g_word_pos[V_];
__device__ int   g_word_cl[V_];
__device__ int   g_pair_slot[NC_ * NC_];

__device__ __forceinline__ uint32_t smem_u32(const void* p) {
    uint32_t a;
    asm("{ .reg .u64 t; cvta.to.shared.u64 t, %1; cvt.u32.u64 %0, t; }" : "=r"(a) : "l"(p));
    return a;
}
__device__ __forceinline__ float ex2f(float x) {
    float r;
    asm("ex2.approx.ftz.f32 %0, %1;" : "=f"(r) : "f"(x));
    return r;
}

// ======================================================================================
// HMMA tile machinery: 512 threads, 16 warps (4M x 4N), warp tile 32x32
// ======================================================================================
#define LDA_ 264
#define TILE_BYTES_ (128 * LDA_ * 2)
#define HG2_SMEM_ (2 * TILE_BYTES_)
#define HG3_SMEM_ (3 * TILE_BYTES_)

// 512-thread tile loaders: thread = (row = tid>>2, quarter = tid&3), 8 uint4 each
__device__ __forceinline__ void load_tile(__nv_bfloat16* dst, const __nv_bfloat16* src, int tid) {
    int row = tid >> 2;
    int q   = tid & 3;
    const uint4* g = reinterpret_cast<const uint4*>(src + (size_t)row * H_ + q * 64);
    uint4* s = reinterpret_cast<uint4*>(dst + row * LDA_ + q * 64);
#pragma unroll
    for (int i = 0; i < 8; i++) s[i] = g[i];
}

__device__ __forceinline__ void cp_tile(__nv_bfloat16* dst, const __nv_bfloat16* src, int tid) {
    int row = tid >> 2;
    int q   = tid & 3;
    const char* g = reinterpret_cast<const char*>(src + (size_t)row * H_ + q * 64);
    uint32_t s = smem_u32(dst + row * LDA_ + q * 64);
#pragma unroll
    for (int i = 0; i < 8; i++)
        asm volatile("cp.async.cg.shared.global [%0], [%1], 16;" :: "r"(s + i * 16), "l"(g + i * 16) : "memory");
}

// acc[2][4][4]: warp tile 32(M) x 32(N)
__device__ __forceinline__ void mma_mainloop(const __nv_bfloat16* As, const __nv_bfloat16* Bs,
                                             int wm, int wn, int lane, float acc[2][4][4]) {
    uint32_t a_base = smem_u32(As) + (((wm * 32 + (lane & 15)) * LDA_ + (lane >> 4) * 8) << 1);
    uint32_t b_base = smem_u32(Bs) + (((wn * 32 + ((lane >> 4) * 8) + (lane & 7)) * LDA_ + ((lane >> 3) & 1) * 8) << 1);
#pragma unroll
    for (int k = 0; k < 16; k++) {
        uint32_t a[2][4], b[4][2];
#pragma unroll
        for (int mi = 0; mi < 2; mi++) {
            uint32_t addr = a_base + ((mi * 16 * LDA_ + k * 16) << 1);
            asm volatile("ldmatrix.sync.aligned.m8n8.x4.shared.b16 {%0,%1,%2,%3}, [%4];"
                         : "=r"(a[mi][0]), "=r"(a[mi][1]), "=r"(a[mi][2]), "=r"(a[mi][3])
                         : "r"(addr));
        }
#pragma unroll
        for (int np = 0; np < 2; np++) {
            uint32_t addr = b_base + ((np * 16 * LDA_ + k * 16) << 1);
            asm volatile("ldmatrix.sync.aligned.m8n8.x4.shared.b16 {%0,%1,%2,%3}, [%4];"
                         : "=r"(b[np * 2][0]), "=r"(b[np * 2][1]),
                           "=r"(b[np * 2 + 1][0]), "=r"(b[np * 2 + 1][1])
                         : "r"(addr));
        }
#pragma unroll
        for (int mi = 0; mi < 2; mi++)
#pragma unroll
            for (int nf = 0; nf < 4; nf++) {
                asm volatile(
                    "mma.sync.aligned.m16n8k16.row.col.f32.bf16.bf16.f32 "
                    "{%0,%1,%2,%3}, {%4,%5,%6,%7}, {%8,%9}, {%0,%1,%2,%3};"
                    : "+f"(acc[mi][nf][0]), "+f"(acc[mi][nf][1]),
                      "+f"(acc[mi][nf][2]), "+f"(acc[mi][nf][3])
                    : "r"(a[mi][0]), "r"(a[mi][1]), "r"(a[mi][2]), "r"(a[mi][3]),
                      "r"(b[nf][0]), "r"(b[nf][1]));
            }
    }
}

#define ZERO_ACC(acc) do { \
    _Pragma("unroll") for (int mi = 0; mi < 2; mi++) \
    _Pragma("unroll") for (int nf = 0; nf < 4; nf++) \
    _Pragma("unroll") for (int r = 0; r < 4; r++) acc[mi][nf][r] = 0.f; } while (0)

// ---------------- pair-slot table (deterministic) ----------------------------------------
__global__ void pair_init_kernel() {
    int i = blockIdx.x * blockDim.x + threadIdx.x;
    if (i < NC_ * NC_) g_pair_slot[i] = SLOT_NONE_;
}
__global__ void pair_min_kernel(const int* __restrict__ text) {
    int p = threadIdx.x;           // 0..511
    int b = p >> 5, s = p & 31;
    int kp = g_word_cl[text[b * T_ + s]];
    int kn = g_word_cl[text[b * T_ + s + 1]];
    atomicMin(&g_pair_slot[kp * NC_ + kn], p);
}

// ---------------- rowsum strip kernel: 128 x 2048 per CTA, fused blk store --------------
__global__ void __launch_bounds__(512, 1) rowsum_kernel() {
    extern __shared__ char smem[];
    __nv_bfloat16* As = reinterpret_cast<__nv_bfloat16*>(smem);
    __nv_bfloat16* B0 = reinterpret_cast<__nv_bfloat16*>(smem + TILE_BYTES_);
    __nv_bfloat16* B1 = reinterpret_cast<__nv_bfloat16*>(smem + 2 * TILE_BYTES_);
    __shared__ float rs_sm[4 * 128];

    int tid = threadIdx.x, warp = tid >> 5, lane = tid & 31;
    int wm = warp >> 2, wn = warp & 3;
    int mc = blockIdx.y;
    int m0 = mc * 128;
    int n_base = blockIdx.x * 2048;
    int nc0 = blockIdx.x * 16;
    int qr = lane >> 2, qc = lane & 3;

    load_tile(As, g_state_bf + (size_t)m0 * H_, tid);
    cp_tile(B0, g_next_bf + (size_t)n_base * H_, tid);
    asm volatile("cp.async.commit_group;" ::: "memory");
    cp_tile(B1, g_next_bf + (size_t)(n_base + 128) * H_, tid);
    asm volatile("cp.async.commit_group;" ::: "memory");

    float rsum[2][2];
    rsum[0][0] = rsum[0][1] = rsum[1][0] = rsum[1][1] = 0.f;

#pragma unroll
    for (int t = 0; t < 16; t++) {
        if (t < 15) asm volatile("cp.async.wait_group 1;" ::: "memory");
        else        asm volatile("cp.async.wait_group 0;" ::: "memory");
        __syncthreads();
        __nv_bfloat16* Bc = (t & 1) ? B1 : B0;
        float acc[2][4][4];
        ZERO_ACC(acc);
        mma_mainloop(As, Bc, wm, wn, lane, acc);

        int slot = g_pair_slot[mc * NC_ + nc0 + t];
        if (slot != SLOT_NONE_) {
            float* out = g_blk + (size_t)slot * (SPW_ * SPW_);
#pragma unroll
            for (int mi = 0; mi < 2; mi++) {
                int r0 = wm * 32 + mi * 16 + qr;
                float* row0 = out + r0 * SPW_ + wn * 32 + qc * 2;
                float* row1 = row0 + 8 * SPW_;
                float s0 = 0.f, s1 = 0.f;
#pragma unroll
                for (int nf = 0; nf < 4; nf++) {
                    float e0 = ex2f(acc[mi][nf][0]);
                    float e1 = ex2f(acc[mi][nf][1]);
                    float e2 = ex2f(acc[mi][nf][2]);
                    float e3 = ex2f(acc[mi][nf][3]);
                    s0 += e0 + e1; s1 += e2 + e3;
                    *reinterpret_cast<float2*>(row0 + nf * 8) = make_float2(e0, e1);
                    *reinterpret_cast<float2*>(row1 + nf * 8) = make_float2(e2, e3);
                }
                rsum[mi][0] += s0; rsum[mi][1] += s1;
            }
        } else {
#pragma unroll
            for (int mi = 0; mi < 2; mi++) {
                float s0 = 0.f, s1 = 0.f;
#pragma unroll
                for (int nf = 0; nf < 4; nf++) {
                    s0 += ex2f(acc[mi][nf][0]) + ex2f(acc[mi][nf][1]);
                    s1 += ex2f(acc[mi][nf][2]) + ex2f(acc[mi][nf][3]);
                }
                rsum[mi][0] += s0; rsum[mi][1] += s1;
            }
        }
        __syncthreads();
        if (t + 2 < 16) {
            cp_tile((t & 1) ? B1 : B0, g_next_bf + (size_t)(n_base + (t + 2) * 128) * H_, tid);
            asm volatile("cp.async.commit_group;" ::: "memory");
        }
    }

#pragma unroll
    for (int mi = 0; mi < 2; mi++) {
        float s0 = rsum[mi][0], s1 = rsum[mi][1];
        s0 += __shfl_xor_sync(0xffffffffu, s0, 1);
        s0 += __shfl_xor_sync(0xffffffffu, s0, 2);
        s1 += __shfl_xor_sync(0xffffffffu, s1, 1);
        s1 += __shfl_xor_sync(0xffffffffu, s1, 2);
        if (qc == 0) {
            int rloc = wm * 32 + mi * 16 + qr;
            rs_sm[wn * 128 + rloc]     = s0;
            rs_sm[wn * 128 + rloc + 8] = s1;
        }
    }
    __syncthreads();
    if (tid < 128) {
        float s = rs_sm[tid] + rs_sm[128 + tid] + rs_sm[256 + tid] + rs_sm[384 + tid];
        g_rowsum_part[(size_t)blockIdx.x * C_ + m0 + tid] = s;
    }
}

__global__ void rowinv_kernel() {
    int c = blockIdx.x * blockDim.x + threadIdx.x;
    if (c >= C_) return;
    float s = g_rowsum_part[c] + g_rowsum_part[C_ + c] + g_rowsum_part[2 * C_ + c] + g_rowsum_part[3 * C_ + c];
    g_rowinv[c] = 1.f / s;
}

// ---------------- MLP layer kernel (3 nets per launch, pipelined W tiles) ----------------
struct L3Args {
    const __nv_bfloat16* A[3];
    const __nv_bfloat16* W[3];
    const float* bias[3];
    const float* res[3];
    float* outF[3];
    __nv_bfloat16* outB[3];
    float scale[3];
};

__global__ void __launch_bounds__(512, 1) mlp_layer_kernel(L3Args args) {
    extern __shared__ char smem[];
    __nv_bfloat16* bufA = reinterpret_cast<__nv_bfloat16*>(smem);
    __nv_bfloat16* B0   = reinterpret_cast<__nv_bfloat16*>(smem + TILE_BYTES_);
    __nv_bfloat16* B1   = reinterpret_cast<__nv_bfloat16*>(smem + 2 * TILE_BYTES_);

    int net = blockIdx.y;
    const __nv_bfloat16* A = args.A[net];
    const __nv_bfloat16* W = args.W[net];
    const float* bias = args.bias[net];
    const float* res  = args.res[net];
    float* outF = args.outF[net];
    __nv_bfloat16* outB = args.outB[net];
    float scale = args.scale[net];

    int tid = threadIdx.x, warp = tid >> 5, lane = tid & 31;
    int wm = warp >> 2, wn = warp & 3;
    int m0 = blockIdx.x * 128;
    int qr = lane >> 2, qc = lane & 3;

    cp_tile(bufA, A + (size_t)m0 * H_, tid);
    asm volatile("cp.async.commit_group;" ::: "memory");
    cp_tile(B0, W, tid);
    asm volatile("cp.async.commit_group;" ::: "memory");
    cp_tile(B1, W + (size_t)128 * H_, tid);
    asm volatile("cp.async.commit_group;" ::: "memory");

#pragma unroll
    for (int h = 0; h < 2; h++) {
        if (h == 0) asm volatile("cp.async.wait_group 1;" ::: "memory");
        else        asm volatile("cp.async.wait_group 0;" ::: "memory");
        __syncthreads();
        float acc[2][4][4];
        ZERO_ACC(acc);
        mma_mainloop(bufA, h ? B1 : B0, wm, wn, lane, acc);
#pragma unroll
        for (int mi = 0; mi < 2; mi++) {
            int r0 = m0 + wm * 32 + mi * 16 + qr;
            int r1 = r0 + 8;
#pragma unroll
            for (int nf = 0; nf < 4; nf++) {
                int c = h * 128 + wn * 32 + nf * 8 + qc * 2;
                float bb0 = bias[c], bb1 = bias[c + 1];
                float v00 = fmaxf(acc[mi][nf][0] + bb0, 0.f);
                float v01 = fmaxf(acc[mi][nf][1] + bb1, 0.f);
                float v10 = fmaxf(acc[mi][nf][2] + bb0, 0.f);
                float v11 = fmaxf(acc[mi][nf][3] + bb1, 0.f);
                if (res) {
                    float2 x0 = *reinterpret_cast<const float2*>(res + (size_t)r0 * H_ + c);
                    float2 x1 = *reinterpret_cast<const float2*>(res + (size_t)r1 * H_ + c);
                    v00 = (v00 + x0.x) * scale; v01 = (v01 + x0.y) * scale;
                    v10 = (v10 + x1.x) * scale; v11 = (v11 + x1.y) * scale;
                }
                if (outF) {
                    *reinterpret_cast<float2*>(outF + (size_t)r0 * H_ + c) = make_float2(v00, v01);
                    *reinterpret_cast<float2*>(outF + (size_t)r1 * H_ + c) = make_float2(v10, v11);
                }
                if (outB) {
                    *reinterpret_cast<__nv_bfloat162*>(outB + (size_t)r0 * H_ + c) = __floats2bfloat162_rn(v00, v01);
                    *reinterpret_cast<__nv_bfloat162*>(outB + (size_t)r1 * H_ + c) = __floats2bfloat162_rn(v10, v11);
                }
            }
        }
        __syncthreads();
    }
}

// ---------------- one-shot conversions (float4 vectorized) -------------------------------
__global__ void conv_all(const float4* __restrict__ a, const float4* __restrict__ b,
                         const float4* __restrict__ c, const float4* __restrict__ d,
                         const float4* __restrict__ w, const float4* __restrict__ pw,
                         const int* __restrict__ w2s) {
    int i4 = blockIdx.x * blockDim.x + threadIdx.x;
    int i = i4 * 4;
#define CVT4(dst, srcv) do { \
        float4 v = srcv; \
        *reinterpret_cast<__nv_bfloat162*>(dst + i)     = __floats2bfloat162_rn(v.x, v.y); \
        *reinterpret_cast<__nv_bfloat162*>(dst + i + 2) = __floats2bfloat162_rn(v.z, v.w); } while (0)
    if (i < C_ * H_) {
        CVT4(g_semb_bf,  a[i4]);
        CVT4(g_stemb_bf, b[i4]);
        CVT4(g_ptemb_bf, c[i4]);
        CVT4(g_next_bf,  d[i4]);
    }
    if (i < 6 * H_ * H_) CVT4(g_wbf, w[i4]);
    if (i < V_ * H_) CVT4(g_projw_bf, pw[i4]);
    if (i4 < V_) g_word_cl[i4] = w2s[(size_t)i4 * SPW_] >> 7;
#undef CVT4
}

// ---------------- start head ----------------------------------------------------------
__global__ void start_head(const float* __restrict__ sow, const float* __restrict__ sob) {
    int gw   = (blockIdx.x * blockDim.x + threadIdx.x) >> 5;
    int lane = threadIdx.x & 31;
    if (gw >= C_) return;
    float acc = 0.f;
#pragma unroll
    for (int q = 0; q < 8; q++)
        acc += g_r_start[(size_t)gw * H_ + lane + 32 * q] * sow[lane + 32 * q];
#pragma unroll
    for (int o = 16; o > 0; o >>= 1) acc += __shfl_xor_sync(0xffffffffu, acc, o);
    if (lane == 0) g_start_s[gw] = acc + sob[0];
}

__global__ void start_lse_kernel() {
    int tid = threadIdx.x;
    float m = -INFINITY, s = 0.f;
    for (int c = tid; c < C_; c += 256) {
        float x  = g_start_s[c];
        float nm = fmaxf(m, x);
        s = s * __expf(m - nm) + __expf(x - nm);
        m = nm;
    }
    __shared__ float sm[256], ss[256];
    sm[tid] = m; ss[tid] = s;
    __syncthreads();
    for (int o = 128; o > 0; o >>= 1) {
        if (tid < o) {
            float m2 = sm[tid + o], s2 = ss[tid + o];
            float nm = fmaxf(sm[tid], m2);
            ss[tid] = ss[tid] * __expf(sm[tid] - nm) + s2 * __expf(m2 - nm);
            sm[tid] = nm;
        }
        __syncthreads();
    }
    if (tid == 0) g_start_lse_v = sm[0] + __logf(ss[0]);
}

// ---------------- fast cluster lists ----------------------------------------------------
#define WPT_ 40
__global__ void build_lists3() {
    int k = blockIdx.x, tid = threadIdx.x;
    int lo = tid * WPT_;
    int hi = min(lo + WPT_, V_);
    int cnt = 0;
    for (int w = lo; w < hi; w++) cnt += (g_word_cl[w] == k);
    __shared__ int sc[256];
    sc[tid] = cnt;
    __syncthreads();
#pragma unroll
    for (int o = 1; o < 256; o <<= 1) {
        int v = (tid >= o) ? sc[tid - o] : 0;
        __syncthreads();
        sc[tid] += v;
        __syncthreads();
    }
    int p = sc[tid] - cnt;
    for (int w = lo; w < hi; w++) {
        if (g_word_cl[w] == k) {
            if (p < MAXW_) { g_cl_words[k * MAXW_ + p] = w; g_word_pos[w] = p; }
            p++;
        }
    }
    if (tid == 255) g_cl_cnt[k] = sc[255];
}

// ---------------- emission: per-cluster HMMA logits + row exp-sums ---------------------
__device__ __forceinline__ void gather_tile(__nv_bfloat16* dst, const int* __restrict__ words,
                                            int basei, int cnt, int tid) {
    int row = tid >> 2;
    int q   = tid & 3;
    uint4* s = reinterpret_cast<uint4*>(dst + row * LDA_ + q * 64);
    int idx = basei + row;
    if (idx < cnt) {
        const uint4* g = reinterpret_cast<const uint4*>(g_projw_bf + (size_t)words[idx] * H_ + q * 64);
#pragma unroll
        for (int i = 0; i < 8; i++) s[i] = g[i];
    } else {
        uint4 z = make_uint4(0, 0, 0, 0);
#pragma unroll
        for (int i = 0; i < 8; i++) s[i] = z;
    }
}

__global__ void __launch_bounds__(512, 1) emis_kernel(const float* __restrict__ proj_b) {
    extern __shared__ char smem[];
    __nv_bfloat16* As = reinterpret_cast<__nv_bfloat16*>(smem);
    __nv_bfloat16* Bs = reinterpret_cast<__nv_bfloat16*>(smem + TILE_BYTES_);
    __shared__ float rs_sm[4 * 128];

    int tid = threadIdx.x, warp = tid >> 5, lane = tid & 31;
    int wm = warp >> 2, wn = warp & 3;
    int k = blockIdx.x;
    int cnt = g_cl_cnt[k];
    const int* words = &g_cl_words[k * MAXW_];
    int qr = lane >> 2, qc = lane & 3;

    load_tile(As, g_rpre_bf + (size_t)(k * 128) * H_, tid);

    float rsum[2][2];
    rsum[0][0] = rsum[0][1] = rsum[1][0] = rsum[1][1] = 0.f;

    int nch = (cnt + 127) >> 7;
    for (int ch = 0; ch < nch; ch++) {
        __syncthreads();
        gather_tile(Bs, words, ch * 128, cnt, tid);
        __syncthreads();
        float acc[2][4][4];
        ZERO_ACC(acc);
        mma_mainloop(As, Bs, wm, wn, lane, acc);
#pragma unroll
        for (int mi = 0; mi < 2; mi++) {
            int r0 = wm * 32 + mi * 16 + qr;
            float* er0 = g_elog + ((size_t)(k * 128 + r0) * MAXW_);
            float* er1 = g_elog + ((size_t)(k * 128 + r0 + 8) * MAXW_);
#pragma unroll
            for (int nf = 0; nf < 4; nf++) {
                int n = ch * 128 + wn * 32 + nf * 8 + qc * 2;
                if (n < cnt) {
                    float bb = proj_b[words[n]];
                    float v0 = acc[mi][nf][0] + bb;
                    float v2 = acc[mi][nf][2] + bb;
                    er0[n] = v0; er1[n] = v2;
                    rsum[mi][0] += __expf(v0);
                    rsum[mi][1] += __expf(v2);
                }
                if (n + 1 < cnt) {
                    float bb = proj_b[words[n + 1]];
                    float v1 = acc[mi][nf][1] + bb;
                    float v3 = acc[mi][nf][3] + bb;
                    er0[n + 1] = v1; er1[n + 1] = v3;
                    rsum[mi][0] += __expf(v1);
                    rsum[mi][1] += __expf(v3);
                }
            }
        }
    }

#pragma unroll
    for (int mi = 0; mi < 2; mi++) {
        float s0 = rsum[mi][0], s1 = rsum[mi][1];
        s0 += __shfl_xor_sync(0xffffffffu, s0, 1);
        s0 += __shfl_xor_sync(0xffffffffu, s0, 2);
        s1 += __shfl_xor_sync(0xffffffffu, s1, 1);
        s1 += __shfl_xor_sync(0xffffffffu, s1, 2);
        if (qc == 0) {
            int rloc = wm * 32 + mi * 16 + qr;
            rs_sm[wn * 128 + rloc]     = s0;
            rs_sm[wn * 128 + rloc + 8] = s1;
        }
    }
    __syncthreads();
    if (tid < 128) {
        float s = rs_sm[tid] + rs_sm[128 + tid] + rs_sm[256 + tid] + rs_sm[384 + tid];
        g_else[k * 128 + tid] = __logf(s);
    }
}

// ---------------- obs lookup ------------------------------------------------------------
__global__ void obs_kernel(const int* __restrict__ text) {
    int bt = blockIdx.x;
    int s  = threadIdx.x;
    int v  = text[bt];
    int k  = g_word_cl[v];
    float lg = g_elog[((size_t)(k * 128 + s)) * MAXW_ + g_word_pos[v]];
    g_obs[bt * SPW_ + s] = lg - g_else[k * 128 + s];
}

// ---------------- forward recursion ------------------------------------------------------
#define FW_PITCH_ 132
#define FW_BUF_   (128 * FW_PITCH_)
#define FW_SMEM_  (2 * FW_BUF_ * 4)

__device__ __forceinline__ void fwd_load512(float* buf, const float* __restrict__ src, int t) {
    uint32_t sb = smem_u32(buf);
#pragma unroll
    for (int k = 0; k < 8; k++) {
        int f = k * 512 + t;
        int e = f << 2;
        int i = e >> 7, col = e & 127;
        asm volatile("cp.async.cg.shared.global [%0], [%1], 16;"
                     :: "r"(sb + ((i * FW_PITCH_ + col) << 2)), "l"(src + e) : "memory");
    }
    asm volatile("cp.async.commit_group;" ::: "memory");
}

__global__ void __launch_bounds__(512, 1) forward_kernel(const int* __restrict__ text,
                                                         float* __restrict__ out) {
    extern __shared__ float fsm[];
    __shared__ float av[128], wv[128], red[128], psum[512];
    int b = blockIdx.x, t = threadIdx.x;
    int j = t & 127, g = t >> 7;
    float* buf0 = fsm;
    float* buf1 = fsm + FW_BUF_;

    int kcur  = g_word_cl[text[b * T_]];
    int knext = g_word_cl[text[b * T_ + 1]];
    fwd_load512(buf0, g_blk + (size_t)g_pair_slot[kcur * NC_ + knext] * (SPW_ * SPW_), t);

    float aj = g_start_s[kcur * 128 + j] - g_start_lse_v + g_obs[(b * T_) * SPW_ + j];

    for (int s = 0; s < T_ - 1; s++) {
        __syncthreads();
        if (g == 0) av[j] = aj;
        __syncthreads();
        if (t < 64) red[t] = fmaxf(av[t], av[t + 64]);
        __syncthreads();
        if (t < 32) {
            float v = fmaxf(red[t], red[t + 32]);
#pragma unroll
            for (int o = 16; o > 0; o >>= 1) v = fmaxf(v, __shfl_xor_sync(0xffffffffu, v, o));
            if (t == 0) red[0] = v;
        }
        __syncthreads();
        float mx = red[0];
        if (g == 0) wv[j] = __expf(av[j] - mx) * g_rowinv[kcur * 128 + j];
        asm volatile("cp.async.wait_group 0;" ::: "memory");
        __syncthreads();
        int knext2 = 0;
        if (s + 1 < T_ - 1) {
            knext2 = g_word_cl[text[b * T_ + s + 2]];
            fwd_load512((s & 1) ? buf0 : buf1,
                        g_blk + (size_t)g_pair_slot[knext * NC_ + knext2] * (SPW_ * SPW_), t);
        }

        const float* bc = (s & 1) ? buf1 : buf0;
        float sum = 0.f;
        int i0 = g * 32;
#pragma unroll 8
        for (int i = 0; i < 32; i++)
            sum = fmaf(bc[(i0 + i) * FW_PITCH_ + j], wv[i0 + i], sum);
        psum[t] = sum;
        __syncthreads();
        float tot = psum[j] + psum[j + 128] + psum[j + 256] + psum[j + 384];
        aj = mx + __logf(tot) + g_obs[(b * T_ + s + 1) * SPW_ + j];
        kcur = knext; knext = knext2;
    }

    __syncthreads();
    if (g == 0) av[j] = aj;
    __syncthreads();
    if (t < 64) red[t] = fmaxf(av[t], av[t + 64]);
    __syncthreads();
    if (t < 32) {
        float v = fmaxf(red[t], red[t + 32]);
#pragma unroll
        for (int o = 16; o > 0; o >>= 1) v = fmaxf(v, __shfl_xor_sync(0xffffffffu, v, o));
        if (t == 0) red[0] = v;
    }
    __syncthreads();
    float m = red[0];
    if (t < 64) psum[t] = __expf(av[t] - m) + __expf(av[t + 64] - m);
    __syncthreads();
    if (t < 32) {
        float v = psum[t] + psum[t + 32];
#pragma unroll
        for (int o = 16; o > 0; o >>= 1) v += __shfl_xor_sync(0xffffffffu, v, o);
        if (t == 0) out[b] = m + __logf(v);
    }
}

// ---------------- launch ----------------------------------------------------------------
extern "C" void kernel_launch(void* const* d_in, const int* in_sizes, int n_in,
                              void* d_out, int out_size) {
    const int*   text       = (const int*)d_in[0];
    const int*   word2state = (const int*)d_in[1];
    const float* start_emb  = (const float*)d_in[2];
    const float* sw1 = (const float*)d_in[3];
    const float* sb1 = (const float*)d_in[4];
    const float* sw2 = (const float*)d_in[5];
    const float* sb2 = (const float*)d_in[6];
    const float* sow = (const float*)d_in[7];
    const float* sob = (const float*)d_in[8];
    const float* state_emb = (const float*)d_in[9];
    const float* tw1 = (const float*)d_in[10];
    const float* tb1 = (const float*)d_in[11];
    const float* tw2 = (const float*)d_in[12];
    const float* tb2 = (const float*)d_in[13];
    const float* next_state_emb  = (const float*)d_in[14];
    const float* preterminal_emb = (const float*)d_in[15];
    const float* ew1 = (const float*)d_in[16];
    const float* eb1 = (const float*)d_in[17];
    const float* ew2 = (const float*)d_in[18];
    const float* eb2 = (const float*)d_in[19];
    const float* proj_w = (const float*)d_in[20];
    const float* proj_b = (const float*)d_in[21];
    float* out = (float*)d_out;

    // NOTE: conv_all assumes sw1..ew2 are 6 contiguous H*H arrays? They are separate
    // pointers; pass weights individually via a small staging kernel approach instead.
    __nv_bfloat16 *p_semb, *p_stemb, *p_ptemb, *p_state, *p_rpre, *p_w, *p_hid;
    float *p_rstart;
    cudaGetSymbolAddress((void**)&p_semb,   g_semb_bf);
    cudaGetSymbolAddress((void**)&p_stemb,  g_stemb_bf);
    cudaGetSymbolAddress((void**)&p_ptemb,  g_ptemb_bf);
    cudaGetSymbolAddress((void**)&p_state,  g_state_bf);
    cudaGetSymbolAddress((void**)&p_rpre,   g_rpre_bf);
    cudaGetSymbolAddress((void**)&p_w,      g_wbf);
    cudaGetSymbolAddress((void**)&p_hid,    g_hid_bf);
    cudaGetSymbolAddress((void**)&p_rstart, g_r_start);

    cudaFuncSetAttribute(mlp_layer_kernel, cudaFuncAttributeMaxDynamicSharedMemorySize, HG3_SMEM_);
    cudaFuncSetAttribute(rowsum_kernel,    cudaFuncAttributeMaxDynamicSharedMemorySize, HG3_SMEM_);
    cudaFuncSetAttribute(emis_kernel,      cudaFuncAttributeMaxDynamicSharedMemorySize, HG2_SMEM_);
    cudaFuncSetAttribute(forward_kernel,   cudaFuncAttributeMaxDynamicSharedMemorySize, FW_SMEM_);

    // stage the 6 weight matrices contiguously in bf16 via per-matrix kernels is wasteful;
    // instead convert each weight with its own offset using a tiny dedicated kernel:
    // (single conv kernel handles embeddings + proj_w + word_cl; weights done inline here)
    struct WPair { const float* src; int off; };
    // weights conversion fused into conv_all would need contiguity; do 1 extra kernel:
    // simple approach: one kernel converting all 6 via pointer array in params.
    {
        // vectorized conversions for embeddings / proj_w / word_cl
        conv_all<<<(V_ * H_ / 4 + 255) / 256, 256>>>(
            (const float4*)start_emb, (const float4*)state_emb,
            (const float4*)preterminal_emb, (const float4*)next_state_emb,
            (const float4*)sw1 /*placeholder, weights handled below*/,
            (const float4*)proj_w, word2state);
    }
    // convert the 6 weight matrices (each 64K elements) in one small kernel:
    {
        auto cw = [](const float* src, __nv_bfloat16* dst) {};
        // use a lambda-free approach: six tiny launches are cheap (~1-2 us total)
    }
    // fallback: dedicated kernel for weights
    {
        static const int dummy = 0; (void)dummy;
    }
    // six small conversions (grid 64 each, vectorized)
    {
        struct ConvW { const float4* s; int o; };
        // implemented via conv_w kernel below
    }
    extern __global__ void conv_w6(const float4*, const float4*, const float4*,
                                   const float4*, const float4*, const float4*);
    conv_w6<<<(6 * H_ * H_ / 4 + 255) / 256, 256>>>(
        (const float4*)sw1, (const float4*)sw2, (const float4*)tw1,
        (const float4*)tw2, (const float4*)ew1, (const float4*)ew2);

    build_lists3<<<NC_, 256>>>();
    pair_init_kernel<<<(NC_ * NC_ + 255) / 256, 256>>>();
    pair_min_kernel<<<1, NP_>>>(text);

    L3Args l1;
    l1.A[0] = p_semb;  l1.A[1] = p_stemb; l1.A[2] = p_ptemb;
    l1.W[0] = p_w;     l1.W[1] = p_w + 2 * H_ * H_; l1.W[2] = p_w + 4 * H_ * H_;
    l1.bias[0] = sb1;  l1.bias[1] = tb1;  l1.bias[2] = eb1;
    l1.res[0] = nullptr; l1.res[1] = nullptr; l1.res[2] = nullptr;
    l1.outF[0] = nullptr; l1.outF[1] = nullptr; l1.outF[2] = nullptr;
    l1.outB[0] = p_hid; l1.outB[1] = p_hid + C_ * H_; l1.outB[2] = p_hid + 2 * C_ * H_;
    l1.scale[0] = 1.f; l1.scale[1] = 1.f; l1.scale[2] = 1.f;
    dim3 gm(C_ / 128, 3);
    mlp_layer_kernel<<<gm, 512, HG3_SMEM_>>>(l1);

    L3Args l2;
    l2.A[0] = p_hid; l2.A[1] = p_hid + C_ * H_; l2.A[2] = p_hid + 2 * C_ * H_;
    l2.W[0] = p_w + 1 * H_ * H_; l2.W[1] = p_w + 3 * H_ * H_; l2.W[2] = p_w + 5 * H_ * H_;
    l2.bias[0] = sb2; l2.bias[1] = tb2; l2.bias[2] = eb2;
    l2.res[0] = start_emb; l2.res[1] = state_emb; l2.res[2] = preterminal_emb;
    l2.outF[0] = p_rstart; l2.outF[1] = nullptr; l2.outF[2] = nullptr;
    l2.outB[0] = nullptr; l2.outB[1] = p_state; l2.outB[2] = p_rpre;
    l2.scale[0] = 1.f; l2.scale[1] = LOG2E_; l2.scale[2] = 1.f;
    mlp_layer_kernel<<<gm, 512, HG3_SMEM_>>>(l2);

    start_head<<<C_ / 8, 256>>>(sow, sob);
    start_lse_kernel<<<1, 256>>>();

    dim3 gr(4, 64);
    rowsum_kernel<<<gr, 512, HG3_SMEM_>>>();
    rowinv_kernel<<<C_ / 256, 256>>>();

    emis_kernel<<<NC_, 512, HG2_SMEM_>>>(proj_b);
    obs_kernel<<<B_ * T_, 128>>>(text);

    forward_kernel<<<B_, 512, FW_SMEM_>>>(text, out);
}

// weights conversion kernel (6 x H*H), float4 vectorized
__global__ void conv_w6(const float4* __restrict__ w0, const float4* __restrict__ w1,
                        const float4* __restrict__ w2, const float4* __restrict__ w3,
                        const float4* __restrict__ w4, const float4* __restrict__ w5) {
    int i4 = blockIdx.x * blockDim.x + threadIdx.x;
    int per = H_ * H_ / 4;   // 16384 float4 per matrix
    if (i4 >= 6 * per) return;
    int wi = i4 / per, r4 = i4 % per;
    const float4* srcs[6] = {w0, w1, w2, w3, w4, w5};
    float4 v = srcs[wi][r4];
    int o = wi * H_ * H_ + r4 * 4;
    *reinterpret_cast<__nv_bfloat162*>(g_wbf + o)     = __floats2bfloat162_rn(v.x, v.y);
    *reinterpret_cast<__nv_bfloat162*>(g_wbf + o + 2) = __floats2bfloat162_rn(v.z, v.w);
}